// round 7
// baseline (speedup 1.0000x reference)
#include <cuda_runtime.h>
#include <cuda_bf16.h>
#include <cstdint>
#include <math.h>

#define NB   64
#define NT   128
#define BT   8192
#define H    1024
#define DIN  2048
#define G4   4096
#define NH1  256
#define NANS 1000
#define NCTA 128u

// ---------------- device scratch ----------------
__device__ float g_X1[(size_t)BT * G4];          // [t][b][4H] (includes +b1)
__device__ float g_c1[NB * H];
__device__ float g_c2[NB * H];
__device__ unsigned g_bar;
// h in bf16 A-fragment layout: [kc(64)][mt(4)][lane(32)][reg(4)] u32
__device__ __align__(16) uint32_t g_h1p[2][32768];
__device__ __align__(16) uint32_t g_h2p[2][32768];
// step weights, B-fragment layout: [bx(128)][kc][g(4)][lane(32)] uint2
__device__ __align__(16) uint32_t g_W1p[128 * 64 * 4 * 32 * 2];     // 8 MB
__device__ __align__(16) uint32_t g_W2p[128 * 128 * 4 * 32 * 2];    // 16 MB
// xproj operands
__device__ __align__(16) uint32_t g_Ax[(size_t)128 * 128 * 4 * 32 * 4];  // 32 MB
__device__ __align__(16) uint32_t g_Wx[(size_t)64 * 128 * 8 * 32 * 2];   // 16 MB
// head: lstm_out bf16 A-frag [mb(128)][kc(64)][mt(4)][lane(32)][reg(4)]
__device__ __align__(16) uint32_t g_LOp[(size_t)128 * 64 * 4 * 32 * 4];  // 16 MB
// hid bf16 A-frag [mb(128)][kc(16)][mt][lane][reg]
__device__ __align__(16) uint32_t g_HIDp[(size_t)128 * 16 * 4 * 32 * 4]; // 4 MB
__device__ __align__(16) uint32_t g_Wp1p[4 * 64 * 8 * 32 * 2];
__device__ __align__(16) uint32_t g_Wp2p[16 * 16 * 8 * 32 * 2];

__device__ __forceinline__ float sigmoidf_(float x) { return 1.f / (1.f + expf(-x)); }
__device__ __forceinline__ uint32_t pk(float x, float y) {
    __nv_bfloat162 v = __floats2bfloat162_rn(x, y);
    return *reinterpret_cast<uint32_t*>(&v);
}
__device__ __forceinline__ void mmabf(float c[4], uint4 a, uint2 b) {
    asm volatile(
        "mma.sync.aligned.m16n8k16.row.col.f32.bf16.bf16.f32 "
        "{%0,%1,%2,%3},{%4,%5,%6,%7},{%8,%9},{%0,%1,%2,%3};"
        : "+f"(c[0]), "+f"(c[1]), "+f"(c[2]), "+f"(c[3])
        : "r"(a.x), "r"(a.y), "r"(a.z), "r"(a.w), "r"(b.x), "r"(b.y));
}
__device__ __forceinline__ float2 ld2cg(const float* p) {
    float2 v;
    asm volatile("ld.global.cg.v2.f32 {%0,%1}, [%2];" : "=f"(v.x), "=f"(v.y) : "l"(p));
    return v;
}
__device__ __forceinline__ void cp16(void* smem, const void* g) {
    uint32_t s = (uint32_t)__cvta_generic_to_shared(smem);
    asm volatile("cp.async.cg.shared.global [%0], [%1], 16;" :: "r"(s), "l"(g));
}
__device__ __forceinline__ void cp_commit() { asm volatile("cp.async.commit_group;"); }
__device__ __forceinline__ void cp_wait2()  { asm volatile("cp.async.wait_group 2;"); }
__device__ __forceinline__ void cp_wait0()  { asm volatile("cp.async.wait_group 0;"); }

__device__ __forceinline__ void gbar(unsigned target) {
    __syncthreads();
    if (threadIdx.x == 0) {
        __threadfence();
        atomicAdd(&g_bar, 1u);
        while (*(volatile unsigned*)&g_bar < target) { }
        __threadfence();
    }
    __syncthreads();
}

// ---------------- init ----------------
__global__ void k_init_state() {
    int i = blockIdx.x * blockDim.x + threadIdx.x;
    if (i == 0) g_bar = 0u;
    if (i < NB * H) { g_c1[i] = 0.f; g_c2[i] = 0.f; }
    if (i < 32768)  { g_h1p[0][i] = 0u; g_h2p[0][i] = 0u; }
}

// ---------------- pack step weights -> B fragments ---------------------------
__global__ void k_pack_w(const float* __restrict__ Wa, const float* __restrict__ Wb,
                         int nkc, uint2* __restrict__ out)
{
    int total = 128 * nkc * 4 * 32;
    for (int idx = blockIdx.x * blockDim.x + threadIdx.x; idx < total;
         idx += gridDim.x * blockDim.x) {
        int lane = idx & 31;
        int t1 = idx >> 5;
        int g  = t1 & 3;
        int t2 = t1 >> 2;
        int kc = t2 % nkc;
        int bx = t2 / nkc;
        int rr = lane >> 2, cc = lane & 3;
        int row = g * H + bx * 8 + rr;
        const float* W = Wa; int k0 = kc * 16 + cc * 2;
        if (kc >= 64) { W = Wb; k0 -= 1024; }
        const float* p = W + (size_t)row * H + k0;
        uint2 v; v.x = pk(p[0], p[1]); v.y = pk(p[8], p[9]);
        out[idx] = v;
    }
}

// ---------------- pack xproj A ------------------------------------------------
__global__ void k_pack_a(const float* __restrict__ d1, const float* __restrict__ d2)
{
    uint4* out = (uint4*)g_Ax;
    int total = 128 * 128 * 4 * 32;
    for (int idx = blockIdx.x * blockDim.x + threadIdx.x; idx < total;
         idx += gridDim.x * blockDim.x) {
        int lane = idx & 31;
        int t1 = idx >> 5;
        int mt = t1 & 3; t1 >>= 2;
        int kc = t1 & 127;
        int mb = t1 >> 7;
        int rr = lane >> 2, cc = lane & 3;
        int r0 = mb * 64 + mt * 16 + rr, r1 = r0 + 8;
        int k0 = kc * 16 + cc * 2;
        const float *s0, *s1;
        if (k0 < 1024) { s0 = d1 + (size_t)r0 * 1024 + k0;        s1 = d1 + (size_t)r1 * 1024 + k0; }
        else           { s0 = d2 + (size_t)r0 * 1024 + k0 - 1024; s1 = d2 + (size_t)r1 * 1024 + k0 - 1024; }
        uint4 v;
        v.x = pk(s0[0], s0[1]);
        v.y = pk(s1[0], s1[1]);
        v.z = pk(s0[8], s0[9]);
        v.w = pk(s1[8], s1[9]);
        out[idx] = v;
    }
}

// ---------------- pack xproj W_ih1 --------------------------------------------
__global__ void k_pack_wx(const float* __restrict__ W)
{
    uint2* out = (uint2*)g_Wx;
    int total = 64 * 128 * 8 * 32;
    for (int idx = blockIdx.x * blockDim.x + threadIdx.x; idx < total;
         idx += gridDim.x * blockDim.x) {
        int lane = idx & 31;
        int t1 = idx >> 5;
        int c = t1 & 7; t1 >>= 3;
        int kc = t1 & 127;
        int nb = t1 >> 7;
        int rr = lane >> 2, cc = lane & 3;
        int n = nb * 64 + c * 8 + rr;
        int k0 = kc * 16 + cc * 2;
        const float* p = W + (size_t)n * DIN + k0;
        uint2 v; v.x = pk(p[0], p[1]); v.y = pk(p[8], p[9]);
        out[idx] = v;
    }
}

// ---------------- pack Wp1 / Wp2 ------------------------------------------------
__global__ void k_pack_wp1(const float* __restrict__ W)
{
    uint2* out = (uint2*)g_Wp1p;
    int total = 4 * 64 * 8 * 32;
    for (int idx = blockIdx.x * blockDim.x + threadIdx.x; idx < total;
         idx += gridDim.x * blockDim.x) {
        int lane = idx & 31;
        int t1 = idx >> 5;
        int c = t1 & 7; t1 >>= 3;
        int kc = t1 & 63;
        int nb = t1 >> 6;
        int rr = lane >> 2, cc = lane & 3;
        int n  = nb * 64 + c * 8 + rr;
        int k0 = kc * 16 + cc * 2;
        uint2 v;
        v.x = pk(W[(size_t)k0 * NH1 + n],       W[(size_t)(k0 + 1) * NH1 + n]);
        v.y = pk(W[(size_t)(k0 + 8) * NH1 + n], W[(size_t)(k0 + 9) * NH1 + n]);
        out[idx] = v;
    }
}

__global__ void k_pack_wp2(const float* __restrict__ W)
{
    uint2* out = (uint2*)g_Wp2p;
    int total = 16 * 16 * 8 * 32;
    for (int idx = blockIdx.x * blockDim.x + threadIdx.x; idx < total;
         idx += gridDim.x * blockDim.x) {
        int lane = idx & 31;
        int t1 = idx >> 5;
        int c = t1 & 7; t1 >>= 3;
        int kc = t1 & 15;
        int nb = t1 >> 4;
        int rr = lane >> 2, cc = lane & 3;
        int n  = nb * 64 + c * 8 + rr;
        int k0 = kc * 16 + cc * 2;
        float a0 = 0.f, a1 = 0.f, b0 = 0.f, b1 = 0.f;
        if (n < NANS) {
            a0 = W[(size_t)k0 * NANS + n];       a1 = W[(size_t)(k0 + 1) * NANS + n];
            b0 = W[(size_t)(k0 + 8) * NANS + n]; b1 = W[(size_t)(k0 + 9) * NANS + n];
        }
        uint2 v; v.x = pk(a0, a1); v.y = pk(b0, b1);
        out[idx] = v;
    }
}

// =================== xproj: bf16 mma, pre-packed fragments ==================
__global__ __launch_bounds__(256) void k_xprojb(const float* __restrict__ bias)
{
    extern __shared__ uint4 sm[];
    const int tid = threadIdx.x, wid = tid >> 5, lane = tid & 31;
    const int mt = wid & 3, s = wid >> 2;
    const int rr = lane >> 2, cc = lane & 3;
    const int nb = blockIdx.x, mb = blockIdx.y;
    float acc[4][4] = {};
    const uint4* A4 = (const uint4*)g_Ax + (size_t)mb * 128 * 128;
    const uint4* B4 = (const uint4*)g_Wx + (size_t)nb * 128 * 128;

    auto loadst = [&](int it) {
        if (it < 32) {
            uint4* dst = sm + (it & 3) * 1024;
            const uint4* a = A4 + (size_t)it * 512;
            const uint4* b = B4 + (size_t)it * 512;
            cp16(&dst[tid],             &a[tid]);
            cp16(&dst[tid + 256],       &a[tid + 256]);
            cp16(&dst[512 + tid],       &b[tid]);
            cp16(&dst[512 + tid + 256], &b[tid + 256]);
        }
        cp_commit();
    };
    loadst(0); loadst(1); loadst(2);
    for (int it = 0; it < 32; it++) {
        cp_wait2(); __syncthreads();
        loadst(it + 3);
        const uint4* SA = sm + (it & 3) * 1024;
        const uint2* SB = (const uint2*)(SA + 512);
#pragma unroll
        for (int kcl = 0; kcl < 4; kcl++) {
            uint4 a = SA[(kcl * 4 + mt) * 32 + lane];
#pragma unroll
            for (int jn = 0; jn < 4; jn++) {
                uint2 b = SB[(kcl * 8 + s * 4 + jn) * 32 + lane];
                mmabf(acc[jn], a, b);
            }
        }
    }
#pragma unroll
    for (int jn = 0; jn < 4; jn++) {
        int col = nb * 64 + (s * 4 + jn) * 8 + cc * 2;
        float b0 = bias[col], b1 = bias[col + 1];
#pragma unroll
        for (int hh = 0; hh < 2; hh++) {
            int m = mb * 64 + mt * 16 + rr + hh * 8;
            int tt = m & 127, bb = m >> 7;
            float* o = g_X1 + ((size_t)tt * NB + bb) * G4 + col;
            o[0] = acc[jn][hh * 2 + 0] + b0;
            o[1] = acc[jn][hh * 2 + 1] + b1;
        }
    }
}

// =================== persistent recurrence kernel ===========================
// A fragments direct from L2 via depth-8 register ring; contiguous kc per warp;
// epilogue operands (X1, c1, c2) prefetched at GEMM start (DRAM latency hidden
// under the GEMM). Weights smem-resident. Gs reduction combines the 2 K-halves.
// smem (uint4 units): Gs [0,576) ; W1 [576,4672) ; W2 [4672,12864)
__global__ __launch_bounds__(256) void k_recur(const float* __restrict__ b2)
{
    extern __shared__ uint4 sm[];
    const int tid = threadIdx.x, wid = tid >> 5, lane = tid & 31;
    const int mt = wid & 3, s = wid >> 2;
    const int rr = lane >> 2, cc = lane & 3;
    const int bx = blockIdx.x;
    float* Gs   = (float*)sm;
    const uint2* Wsm1 = (const uint2*)(sm + 576);
    const uint2* Wsm2 = (const uint2*)(sm + 4672);
    const int j = bx * 8 + cc * 2;

    // weights -> smem (one time)
    {
        const uint4* w1 = (const uint4*)g_W1p + (size_t)bx * 4096;
        for (int i = tid; i < 4096; i += 256) cp16(&sm[576 + i], &w1[i]);
        const uint4* w2 = (const uint4*)g_W2p + (size_t)bx * 8192;
        for (int i = tid; i < 8192; i += 256) cp16(&sm[4672 + i], &w2[i]);
        cp_commit(); cp_wait0(); __syncthreads();
    }

    float2 b2i = make_float2(b2[j],         b2[j + 1]);
    float2 b2f = make_float2(b2[H + j],     b2[H + j + 1]);
    float2 b2g = make_float2(b2[2 * H + j], b2[2 * H + j + 1]);
    float2 b2o = make_float2(b2[3 * H + j], b2[3 * H + j + 1]);

    // epilogue row indices for this thread (s==1 does epilogue)
    const int em0 = mt * 16 + rr, em1 = em0 + 8;
    float2 h1res[2];

    for (int t = 0; t < NT; t++) {
        // ================= L1: gates = h1_prev @ W1^T + X1[t] ================
        {
            const uint4* A4 = (const uint4*)(g_h1p[t & 1]);
            const uint4* Aw = A4 + ((s * 32) * 4 + mt) * 32 + lane;   // stride 128/ kc
            float acc[4][4] = {};
            uint4 ring[8];
#pragma unroll
            for (int p = 0; p < 8; p++) ring[p] = __ldcg(Aw + p * 128);
            // prefetch epilogue operands into registers (hidden under GEMM)
            float2 px0[4], px1[4], pc0, pc1;
            if (s == 1) {
                const float* Xt = g_X1 + (size_t)t * NB * G4;
                const float* xr0 = Xt + (size_t)em0 * G4 + j;
                const float* xr1 = Xt + (size_t)em1 * G4 + j;
#pragma unroll
                for (int g = 0; g < 4; g++) {
                    px0[g] = ld2cg(xr0 + g * H);
                    px1[g] = ld2cg(xr1 + g * H);
                }
                pc0 = ld2cg(&g_c1[em0 * H + j]);
                pc1 = ld2cg(&g_c1[em1 * H + j]);
            }
#pragma unroll
            for (int q = 0; q < 32; q++) {
                uint4 a = ring[q & 7];
                if (q + 8 < 32) ring[q & 7] = __ldcg(Aw + (q + 8) * 128);
                const int kc = s * 32 + q;
#pragma unroll
                for (int g = 0; g < 4; g++)
                    mmabf(acc[g], a, Wsm1[(kc * 4 + g) * 32 + lane]);
            }
            __syncthreads();                       // Gs free (prev step done)
            if (s == 0) {
#pragma unroll
                for (int g = 0; g < 4; g++) {
                    Gs[em0 * 36 + g * 8 + cc * 2]     = acc[g][0];
                    Gs[em0 * 36 + g * 8 + cc * 2 + 1] = acc[g][1];
                    Gs[em1 * 36 + g * 8 + cc * 2]     = acc[g][2];
                    Gs[em1 * 36 + g * 8 + cc * 2 + 1] = acc[g][3];
                }
            }
            __syncthreads();
            if (s == 1) {
                float2 pxs[2][4] = { {px0[0], px0[1], px0[2], px0[3]},
                                     {px1[0], px1[1], px1[2], px1[3]} };
                float2 pcs[2] = { pc0, pc1 };
#pragma unroll
                for (int hh = 0; hh < 2; hh++) {
                    int m = hh ? em1 : em0;
                    float gi0 = acc[0][hh*2]   + Gs[m*36 +      cc*2]     + pxs[hh][0].x;
                    float gi1 = acc[0][hh*2+1] + Gs[m*36 +      cc*2 + 1] + pxs[hh][0].y;
                    float gf0 = acc[1][hh*2]   + Gs[m*36 +  8 + cc*2]     + pxs[hh][1].x;
                    float gf1 = acc[1][hh*2+1] + Gs[m*36 +  8 + cc*2 + 1] + pxs[hh][1].y;
                    float gg0 = acc[2][hh*2]   + Gs[m*36 + 16 + cc*2]     + pxs[hh][2].x;
                    float gg1 = acc[2][hh*2+1] + Gs[m*36 + 16 + cc*2 + 1] + pxs[hh][2].y;
                    float go0 = acc[3][hh*2]   + Gs[m*36 + 24 + cc*2]     + pxs[hh][3].x;
                    float go1 = acc[3][hh*2+1] + Gs[m*36 + 24 + cc*2 + 1] + pxs[hh][3].y;
                    float cn0 = sigmoidf_(gf0) * pcs[hh].x + sigmoidf_(gi0) * tanhf(gg0);
                    float cn1 = sigmoidf_(gf1) * pcs[hh].y + sigmoidf_(gi1) * tanhf(gg1);
                    *(float2*)&g_c1[m * H + j] = make_float2(cn0, cn1);
                    float h0 = sigmoidf_(go0) * tanhf(cn0);
                    float h1 = sigmoidf_(go1) * tanhf(cn1);
                    h1res[hh] = make_float2(h0, h1);
                    g_h1p[(t + 1) & 1][((((bx >> 1) * 4 + mt) * 32 + lane) * 4)
                                       + hh + 2 * (bx & 1)] = pk(h0, h1);
                }
            }
        }
        gbar((unsigned)(t + 1) * NCTA);            // all h1_t visible
        // ======= L2: gates = h1_t@Wih2^T + h2_prev@Whh2^T + b2, residual =====
        {
            const uint4* A4a = (const uint4*)(g_h1p[(t + 1) & 1]);
            const uint4* A4b = (const uint4*)(g_h2p[t & 1]);
            const uint4* Awa = A4a + ((s * 32) * 4 + mt) * 32 + lane;
            const uint4* Awb = A4b + ((s * 32) * 4 + mt) * 32 + lane;
            float acc[4][4] = {};
            uint4 ring[8];
            // prefetch c2 (hidden under GEMM)
            float2 pc0, pc1;
            if (s == 1) {
                pc0 = ld2cg(&g_c2[em0 * H + j]);
                pc1 = ld2cg(&g_c2[em1 * H + j]);
            }
            // ---- half 1: h1_t @ Wih2 (kc = s*32+q) ----
#pragma unroll
            for (int p = 0; p < 8; p++) ring[p] = __ldcg(Awa + p * 128);
#pragma unroll
            for (int q = 0; q < 32; q++) {
                uint4 a = ring[q & 7];
                ring[q & 7] = (q + 8 < 32) ? __ldcg(Awa + (q + 8) * 128)
                                           : __ldcg(Awb + (q - 24) * 128);
                const int kc = s * 32 + q;
#pragma unroll
                for (int g = 0; g < 4; g++)
                    mmabf(acc[g], a, Wsm2[(kc * 4 + g) * 32 + lane]);
            }
            // ---- half 2: h2_prev @ Whh2 (kc = 64 + s*32 + q) ----
#pragma unroll
            for (int q = 0; q < 32; q++) {
                uint4 a = ring[q & 7];
                if (q + 8 < 32) ring[q & 7] = __ldcg(Awb + (q + 8) * 128);
                const int kc = 64 + s * 32 + q;
#pragma unroll
                for (int g = 0; g < 4; g++)
                    mmabf(acc[g], a, Wsm2[(kc * 4 + g) * 32 + lane]);
            }
            __syncthreads();
            if (s == 0) {
#pragma unroll
                for (int g = 0; g < 4; g++) {
                    Gs[em0 * 36 + g * 8 + cc * 2]     = acc[g][0];
                    Gs[em0 * 36 + g * 8 + cc * 2 + 1] = acc[g][1];
                    Gs[em1 * 36 + g * 8 + cc * 2]     = acc[g][2];
                    Gs[em1 * 36 + g * 8 + cc * 2 + 1] = acc[g][3];
                }
            }
            __syncthreads();
            if (s == 1) {
                float2 pcs[2] = { pc0, pc1 };
#pragma unroll
                for (int hh = 0; hh < 2; hh++) {
                    int m = hh ? em1 : em0;
                    float gi0 = acc[0][hh*2]   + Gs[m*36 +      cc*2]     + b2i.x;
                    float gi1 = acc[0][hh*2+1] + Gs[m*36 +      cc*2 + 1] + b2i.y;
                    float gf0 = acc[1][hh*2]   + Gs[m*36 +  8 + cc*2]     + b2f.x;
                    float gf1 = acc[1][hh*2+1] + Gs[m*36 +  8 + cc*2 + 1] + b2f.y;
                    float gg0 = acc[2][hh*2]   + Gs[m*36 + 16 + cc*2]     + b2g.x;
                    float gg1 = acc[2][hh*2+1] + Gs[m*36 + 16 + cc*2 + 1] + b2g.y;
                    float go0 = acc[3][hh*2]   + Gs[m*36 + 24 + cc*2]     + b2o.x;
                    float go1 = acc[3][hh*2+1] + Gs[m*36 + 24 + cc*2 + 1] + b2o.y;
                    float cn0 = sigmoidf_(gf0) * pcs[hh].x + sigmoidf_(gi0) * tanhf(gg0);
                    float cn1 = sigmoidf_(gf1) * pcs[hh].y + sigmoidf_(gi1) * tanhf(gg1);
                    *(float2*)&g_c2[m * H + j] = make_float2(cn0, cn1);
                    float h0 = sigmoidf_(go0) * tanhf(cn0);
                    float h1 = sigmoidf_(go1) * tanhf(cn1);
                    g_h2p[(t + 1) & 1][((((bx >> 1) * 4 + mt) * 32 + lane) * 4)
                                       + hh + 2 * (bx & 1)] = pk(h0, h1);
                    int mbL   = m * 2 + (t >> 6);
                    int kcL   = bx >> 1;
                    int mtL   = (t >> 4) & 3;
                    int laneL = (t & 7) * 4 + cc;
                    int regL  = ((t >> 3) & 1) + 2 * (bx & 1);
                    g_LOp[((((size_t)mbL * 64 + kcL) * 4 + mtL) * 32 + laneL) * 4 + regL]
                        = pk(h0 + h1res[hh].x, h1 + h1res[hh].y);
                }
            }
        }
    }
}

// =================== head GEMM 1: hid = relu(LO @ Wp1 + bp1) =================
__global__ __launch_bounds__(256) void k_mlp1b(const float* __restrict__ bp1)
{
    extern __shared__ uint4 sm[];
    const int tid = threadIdx.x, wid = tid >> 5, lane = tid & 31;
    const int mt = wid & 3, s = wid >> 2;
    const int rr = lane >> 2, cc = lane & 3;
    const int nb = blockIdx.x, mb = blockIdx.y;
    float acc[4][4] = {};
    const uint4* A4 = (const uint4*)g_LOp + (size_t)mb * 64 * 128;
    const uint4* B4 = (const uint4*)g_Wp1p + (size_t)nb * 64 * 128;

    auto loadst = [&](int it) {
        if (it < 16) {
            uint4* dst = sm + (it & 3) * 1024;
            const uint4* a = A4 + (size_t)it * 512;
            const uint4* b = B4 + (size_t)it * 512;
            cp16(&dst[tid],             &a[tid]);
            cp16(&dst[tid + 256],       &a[tid + 256]);
            cp16(&dst[512 + tid],       &b[tid]);
            cp16(&dst[512 + tid + 256], &b[tid + 256]);
        }
        cp_commit();
    };
    loadst(0); loadst(1); loadst(2);
    for (int it = 0; it < 16; it++) {
        cp_wait2(); __syncthreads();
        loadst(it + 3);
        const uint4* SA = sm + (it & 3) * 1024;
        const uint2* SB = (const uint2*)(SA + 512);
#pragma unroll
        for (int kcl = 0; kcl < 4; kcl++) {
            uint4 a = SA[(kcl * 4 + mt) * 32 + lane];
#pragma unroll
            for (int jn = 0; jn < 4; jn++) {
                uint2 b = SB[(kcl * 8 + s * 4 + jn) * 32 + lane];
                mmabf(acc[jn], a, b);
            }
        }
    }
#pragma unroll
    for (int jn = 0; jn < 4; jn++) {
        int c8  = s * 4 + jn;
        int col = nb * 64 + c8 * 8 + cc * 2;
        float b0 = bp1[col], b1 = bp1[col + 1];
        int kcH = nb * 4 + (c8 >> 1);
        int regH_base = 2 * (c8 & 1);
#pragma unroll
        for (int hh = 0; hh < 2; hh++) {
            float v0 = fmaxf(acc[jn][hh * 2 + 0] + b0, 0.f);
            float v1 = fmaxf(acc[jn][hh * 2 + 1] + b1, 0.f);
            g_HIDp[((((size_t)mb * 16 + kcH) * 4 + mt) * 32 + (rr * 4 + cc)) * 4
                   + hh + regH_base] = pk(v0, v1);
        }
    }
}

// =================== head GEMM 2: logits = hid @ Wp2 + bp2 ===================
__global__ __launch_bounds__(256) void k_logitsb(const float* __restrict__ bp2,
                                                 float* __restrict__ out)
{
    extern __shared__ uint4 sm[];
    const int tid = threadIdx.x, wid = tid >> 5, lane = tid & 31;
    const int mt = wid & 3, s = wid >> 2;
    const int rr = lane >> 2, cc = lane & 3;
    const int nb = blockIdx.x, mb = blockIdx.y;
    float acc[4][4] = {};
    const uint4* A4 = (const uint4*)g_HIDp + (size_t)mb * 16 * 128;
    const uint4* B4 = (const uint4*)g_Wp2p + (size_t)nb * 16 * 128;

    auto loadst = [&](int it) {
        if (it < 4) {
            uint4* dst = sm + (it & 3) * 1024;
            const uint4* a = A4 + (size_t)it * 512;
            const uint4* b = B4 + (size_t)it * 512;
            cp16(&dst[tid],             &a[tid]);
            cp16(&dst[tid + 256],       &a[tid + 256]);
            cp16(&dst[512 + tid],       &b[tid]);
            cp16(&dst[512 + tid + 256], &b[tid + 256]);
        }
        cp_commit();
    };
    loadst(0); loadst(1); loadst(2);
    for (int it = 0; it < 4; it++) {
        cp_wait2(); __syncthreads();
        loadst(it + 3);
        const uint4* SA = sm + (it & 3) * 1024;
        const uint2* SB = (const uint2*)(SA + 512);
#pragma unroll
        for (int kcl = 0; kcl < 4; kcl++) {
            uint4 a = SA[(kcl * 4 + mt) * 32 + lane];
#pragma unroll
            for (int jn = 0; jn < 4; jn++) {
                uint2 b = SB[(kcl * 8 + s * 4 + jn) * 32 + lane];
                mmabf(acc[jn], a, b);
            }
        }
    }
#pragma unroll
    for (int jn = 0; jn < 4; jn++) {
        int n = nb * 64 + (s * 4 + jn) * 8 + cc * 2;
        if (n < NANS) {
            float b0 = bp2[n], b1 = bp2[n + 1];
#pragma unroll
            for (int hh = 0; hh < 2; hh++) {
                int m = mb * 64 + mt * 16 + rr + hh * 8;
                float* o = out + (size_t)m * NANS + n;
                o[0] = acc[jn][hh * 2 + 0] + b0;
                o[1] = acc[jn][hh * 2 + 1] + b1;
            }
        }
    }
}

// ---------------- softmax ------------------------------------------------------
__global__ __launch_bounds__(256) void k_softmax(float* __restrict__ out)
{
    __shared__ float red[256];
    const int tid = threadIdx.x;
    float* p = out + (size_t)blockIdx.x * NANS;
    float v[4];
    float mx = -1e30f;
#pragma unroll
    for (int i = 0; i < 4; i++) {
        int n = tid + i * 256;
        v[i] = (n < NANS) ? p[n] : -1e30f;
        mx = fmaxf(mx, v[i]);
    }
    red[tid] = mx; __syncthreads();
    for (int s = 128; s > 0; s >>= 1) {
        if (tid < s) red[tid] = fmaxf(red[tid], red[tid + s]);
        __syncthreads();
    }
    mx = red[0]; __syncthreads();
    float sum = 0.f;
#pragma unroll
    for (int i = 0; i < 4; i++) {
        int n = tid + i * 256;
        if (n < NANS) { v[i] = expf(v[i] - mx); sum += v[i]; }
    }
    red[tid] = sum; __syncthreads();
    for (int s = 128; s > 0; s >>= 1) {
        if (tid < s) red[tid] += red[tid + s];
        __syncthreads();
    }
    float inv = 1.f / red[0];
#pragma unroll
    for (int i = 0; i < 4; i++) {
        int n = tid + i * 256;
        if (n < NANS) p[n] = v[i] * inv;
    }
}

// ---------------- launch ------------------------------------------------------
extern "C" void kernel_launch(void* const* d_in, const int* in_sizes, int n_in,
                              void* d_out, int out_size)
{
    const float* data1 = (const float*)d_in[0];
    const float* data2 = (const float*)d_in[1];
    const float* W_ih1 = (const float*)d_in[2];
    const float* W_hh1 = (const float*)d_in[3];
    const float* b1    = (const float*)d_in[4];
    const float* W_ih2 = (const float*)d_in[5];
    const float* W_hh2 = (const float*)d_in[6];
    const float* b2    = (const float*)d_in[7];
    const float* Wp1   = (const float*)d_in[8];
    const float* bp1   = (const float*)d_in[9];
    const float* Wp2   = (const float*)d_in[10];
    const float* bp2   = (const float*)d_in[11];
    float* out = (float*)d_out;

    static bool attr_done = false;
    if (!attr_done) {
        cudaFuncSetAttribute(k_xprojb,  cudaFuncAttributeMaxDynamicSharedMemorySize, 65536);
        cudaFuncSetAttribute(k_mlp1b,   cudaFuncAttributeMaxDynamicSharedMemorySize, 65536);
        cudaFuncSetAttribute(k_logitsb, cudaFuncAttributeMaxDynamicSharedMemorySize, 65536);
        cudaFuncSetAttribute(k_recur,   cudaFuncAttributeMaxDynamicSharedMemorySize, 229376);
        attr_done = true;
    }

    uint2* W1p; cudaGetSymbolAddress((void**)&W1p, g_W1p);
    uint2* W2p; cudaGetSymbolAddress((void**)&W2p, g_W2p);

    k_init_state<<<256, 256>>>();
    k_pack_w<<<1024, 256>>>(W_hh1, nullptr, 64, W1p);
    k_pack_w<<<2048, 256>>>(W_ih2, W_hh2, 128, W2p);
    k_pack_a<<<4096, 256>>>(data1, data2);
    k_pack_wx<<<4096, 256>>>(W_ih1);
    k_pack_wp1<<<256, 256>>>(Wp1);
    k_pack_wp2<<<256, 256>>>(Wp2);
    k_xprojb<<<dim3(64, 128), 256, 65536>>>(b1);
    k_recur<<<128, 256, 205824>>>(b2);
    k_mlp1b<<<dim3(4, 128), 256, 65536>>>(bp1);
    k_logitsb<<<dim3(16, 128), 256, 65536>>>(bp2, out);
    k_softmax<<<BT, 256>>>(out);
}

// round 8
// speedup vs baseline: 1.2523x; 1.2523x over previous
#include <cuda_runtime.h>
#include <cuda_bf16.h>
#include <cstdint>
#include <math.h>

#define NB   64
#define NT   128
#define BT   8192
#define H    1024
#define DIN  2048
#define G4   4096
#define NH1  256
#define NANS 1000
#define NCTA 128u

// ---------------- device scratch ----------------
__device__ float g_X1[(size_t)BT * G4];          // [t][b][4H] (includes +b1)
__device__ unsigned g_bar;
// h in bf16 A-fragment layout: [kc(64)][mt(4)][lane(32)][reg(4)] u32
__device__ __align__(16) uint32_t g_h1p[2][32768];
__device__ __align__(16) uint32_t g_h2p[2][32768];
// step weights, B-fragment layout: [bx(128)][kc][g(4)][lane(32)] uint2
__device__ __align__(16) uint32_t g_W1p[128 * 64 * 4 * 32 * 2];     // 8 MB
__device__ __align__(16) uint32_t g_W2p[128 * 128 * 4 * 32 * 2];    // 16 MB
// xproj operands
__device__ __align__(16) uint32_t g_Ax[(size_t)128 * 128 * 4 * 32 * 4];  // 32 MB
__device__ __align__(16) uint32_t g_Wx[(size_t)64 * 128 * 8 * 32 * 2];   // 16 MB
// head: lstm_out bf16 A-frag [mb(128)][kc(64)][mt(4)][lane(32)][reg(4)]
__device__ __align__(16) uint32_t g_LOp[(size_t)128 * 64 * 4 * 32 * 4];  // 16 MB
// hid bf16 A-frag [mb(128)][kc(16)][mt][lane][reg]
__device__ __align__(16) uint32_t g_HIDp[(size_t)128 * 16 * 4 * 32 * 4]; // 4 MB
__device__ __align__(16) uint32_t g_Wp1p[4 * 64 * 8 * 32 * 2];
__device__ __align__(16) uint32_t g_Wp2p[16 * 16 * 8 * 32 * 2];

__device__ __forceinline__ float sigmoidf_(float x) { return 1.f / (1.f + expf(-x)); }
__device__ __forceinline__ uint32_t pk(float x, float y) {
    __nv_bfloat162 v = __floats2bfloat162_rn(x, y);
    return *reinterpret_cast<uint32_t*>(&v);
}
__device__ __forceinline__ void mmabf(float c[4], uint4 a, uint2 b) {
    asm volatile(
        "mma.sync.aligned.m16n8k16.row.col.f32.bf16.bf16.f32 "
        "{%0,%1,%2,%3},{%4,%5,%6,%7},{%8,%9},{%0,%1,%2,%3};"
        : "+f"(c[0]), "+f"(c[1]), "+f"(c[2]), "+f"(c[3])
        : "r"(a.x), "r"(a.y), "r"(a.z), "r"(a.w), "r"(b.x), "r"(b.y));
}
__device__ __forceinline__ void cp16(void* smem, const void* g) {
    uint32_t s = (uint32_t)__cvta_generic_to_shared(smem);
    asm volatile("cp.async.cg.shared.global [%0], [%1], 16;" :: "r"(s), "l"(g));
}
__device__ __forceinline__ void cp_commit() { asm volatile("cp.async.commit_group;"); }
__device__ __forceinline__ void cp_wait2()  { asm volatile("cp.async.wait_group 2;"); }
__device__ __forceinline__ void cp_wait0()  { asm volatile("cp.async.wait_group 0;"); }

__device__ __forceinline__ void gbar(unsigned target) {
    __syncthreads();
    if (threadIdx.x == 0) {
        __threadfence();
        atomicAdd(&g_bar, 1u);
        while (*(volatile unsigned*)&g_bar < target) { }
        __threadfence();
    }
    __syncthreads();
}

// ---------------- init ----------------
__global__ void k_init_state() {
    int i = blockIdx.x * blockDim.x + threadIdx.x;
    if (i == 0) g_bar = 0u;
    if (i < 32768) { g_h1p[0][i] = 0u; g_h2p[0][i] = 0u; }
}

// ---------------- unified pack kernel (job = blockIdx.y) ---------------------
__global__ void k_pack_all(
    const float* __restrict__ W_hh1, const float* __restrict__ W_ih2,
    const float* __restrict__ W_hh2, const float* __restrict__ d1,
    const float* __restrict__ d2,   const float* __restrict__ W_ih1,
    const float* __restrict__ Wp1,  const float* __restrict__ Wp2)
{
    const int job = blockIdx.y;
    const int gid = blockIdx.x * blockDim.x + threadIdx.x;
    const int stride = gridDim.x * blockDim.x;

    if (job == 0) {                       // W1p from W_hh1 (nkc=64)
        uint2* out = (uint2*)g_W1p;
        for (int idx = gid; idx < 128 * 64 * 4 * 32; idx += stride) {
            int lane = idx & 31;
            int t1 = idx >> 5;  int g = t1 & 3;
            int t2 = t1 >> 2;   int kc = t2 & 63; int bx = t2 >> 6;
            int rr = lane >> 2, cc = lane & 3;
            const float* p = W_hh1 + (size_t)(g * H + bx * 8 + rr) * H + kc * 16 + cc * 2;
            uint2 v; v.x = pk(p[0], p[1]); v.y = pk(p[8], p[9]);
            out[idx] = v;
        }
    } else if (job == 1) {                // W2p from W_ih2 | W_hh2 (nkc=128)
        uint2* out = (uint2*)g_W2p;
        for (int idx = gid; idx < 128 * 128 * 4 * 32; idx += stride) {
            int lane = idx & 31;
            int t1 = idx >> 5;  int g = t1 & 3;
            int t2 = t1 >> 2;   int kc = t2 & 127; int bx = t2 >> 7;
            int rr = lane >> 2, cc = lane & 3;
            int row = g * H + bx * 8 + rr;
            const float* W = W_ih2; int k0 = kc * 16 + cc * 2;
            if (kc >= 64) { W = W_hh2; k0 -= 1024; }
            const float* p = W + (size_t)row * H + k0;
            uint2 v; v.x = pk(p[0], p[1]); v.y = pk(p[8], p[9]);
            out[idx] = v;
        }
    } else if (job == 2) {                // Ax from d1|d2
        uint4* out = (uint4*)g_Ax;
        for (int idx = gid; idx < 128 * 128 * 4 * 32; idx += stride) {
            int lane = idx & 31;
            int t1 = idx >> 5;
            int mt = t1 & 3; t1 >>= 2;
            int kc = t1 & 127;
            int mb = t1 >> 7;
            int rr = lane >> 2, cc = lane & 3;
            int r0 = mb * 64 + mt * 16 + rr, r1 = r0 + 8;
            int k0 = kc * 16 + cc * 2;
            const float *s0, *s1;
            if (k0 < 1024) { s0 = d1 + (size_t)r0 * 1024 + k0;        s1 = d1 + (size_t)r1 * 1024 + k0; }
            else           { s0 = d2 + (size_t)r0 * 1024 + k0 - 1024; s1 = d2 + (size_t)r1 * 1024 + k0 - 1024; }
            uint4 v;
            v.x = pk(s0[0], s0[1]);
            v.y = pk(s1[0], s1[1]);
            v.z = pk(s0[8], s0[9]);
            v.w = pk(s1[8], s1[9]);
            out[idx] = v;
        }
    } else if (job == 3) {                // Wx from W_ih1
        uint2* out = (uint2*)g_Wx;
        for (int idx = gid; idx < 64 * 128 * 8 * 32; idx += stride) {
            int lane = idx & 31;
            int t1 = idx >> 5;
            int c = t1 & 7; t1 >>= 3;
            int kc = t1 & 127;
            int nb = t1 >> 7;
            int rr = lane >> 2, cc = lane & 3;
            const float* p = W_ih1 + (size_t)(nb * 64 + c * 8 + rr) * DIN + kc * 16 + cc * 2;
            uint2 v; v.x = pk(p[0], p[1]); v.y = pk(p[8], p[9]);
            out[idx] = v;
        }
    } else if (job == 4) {                // Wp1p
        uint2* out = (uint2*)g_Wp1p;
        for (int idx = gid; idx < 4 * 64 * 8 * 32; idx += stride) {
            int lane = idx & 31;
            int t1 = idx >> 5;
            int c = t1 & 7; t1 >>= 3;
            int kc = t1 & 63;
            int nb = t1 >> 6;
            int rr = lane >> 2, cc = lane & 3;
            int n  = nb * 64 + c * 8 + rr;
            int k0 = kc * 16 + cc * 2;
            uint2 v;
            v.x = pk(Wp1[(size_t)k0 * NH1 + n],       Wp1[(size_t)(k0 + 1) * NH1 + n]);
            v.y = pk(Wp1[(size_t)(k0 + 8) * NH1 + n], Wp1[(size_t)(k0 + 9) * NH1 + n]);
            out[idx] = v;
        }
    } else {                              // Wp2p (N padded 1000->1024)
        uint2* out = (uint2*)g_Wp2p;
        for (int idx = gid; idx < 16 * 16 * 8 * 32; idx += stride) {
            int lane = idx & 31;
            int t1 = idx >> 5;
            int c = t1 & 7; t1 >>= 3;
            int kc = t1 & 15;
            int nb = t1 >> 4;
            int rr = lane >> 2, cc = lane & 3;
            int n  = nb * 64 + c * 8 + rr;
            int k0 = kc * 16 + cc * 2;
            float a0 = 0.f, a1 = 0.f, b0 = 0.f, b1 = 0.f;
            if (n < NANS) {
                a0 = Wp2[(size_t)k0 * NANS + n];       a1 = Wp2[(size_t)(k0 + 1) * NANS + n];
                b0 = Wp2[(size_t)(k0 + 8) * NANS + n]; b1 = Wp2[(size_t)(k0 + 9) * NANS + n];
            }
            uint2 v; v.x = pk(a0, a1); v.y = pk(b0, b1);
            out[idx] = v;
        }
    }
}

// =================== xproj: bf16 mma, pre-packed fragments ==================
__global__ __launch_bounds__(256) void k_xprojb(const float* __restrict__ bias)
{
    extern __shared__ uint4 sm[];
    const int tid = threadIdx.x, wid = tid >> 5, lane = tid & 31;
    const int mt = wid & 3, s = wid >> 2;
    const int rr = lane >> 2, cc = lane & 3;
    const int nb = blockIdx.x, mb = blockIdx.y;
    float acc[4][4] = {};
    const uint4* A4 = (const uint4*)g_Ax + (size_t)mb * 128 * 128;
    const uint4* B4 = (const uint4*)g_Wx + (size_t)nb * 128 * 128;

    auto loadst = [&](int it) {
        if (it < 32) {
            uint4* dst = sm + (it & 3) * 1024;
            const uint4* a = A4 + (size_t)it * 512;
            const uint4* b = B4 + (size_t)it * 512;
            cp16(&dst[tid],             &a[tid]);
            cp16(&dst[tid + 256],       &a[tid + 256]);
            cp16(&dst[512 + tid],       &b[tid]);
            cp16(&dst[512 + tid + 256], &b[tid + 256]);
        }
        cp_commit();
    };
    loadst(0); loadst(1); loadst(2);
    for (int it = 0; it < 32; it++) {
        cp_wait2(); __syncthreads();
        loadst(it + 3);
        const uint4* SA = sm + (it & 3) * 1024;
        const uint2* SB = (const uint2*)(SA + 512);
#pragma unroll
        for (int kcl = 0; kcl < 4; kcl++) {
            uint4 a = SA[(kcl * 4 + mt) * 32 + lane];
#pragma unroll
            for (int jn = 0; jn < 4; jn++) {
                uint2 b = SB[(kcl * 8 + s * 4 + jn) * 32 + lane];
                mmabf(acc[jn], a, b);
            }
        }
    }
#pragma unroll
    for (int jn = 0; jn < 4; jn++) {
        int col = nb * 64 + (s * 4 + jn) * 8 + cc * 2;
        float b0 = bias[col], b1 = bias[col + 1];
#pragma unroll
        for (int hh = 0; hh < 2; hh++) {
            int m = mb * 64 + mt * 16 + rr + hh * 8;
            int tt = m & 127, bb = m >> 7;
            float* o = g_X1 + ((size_t)tt * NB + bb) * G4 + col;
            o[0] = acc[jn][hh * 2 + 0] + b0;
            o[1] = acc[jn][hh * 2 + 1] + b1;
        }
    }
}

// =================== persistent recurrence kernel ===========================
// R6 GEMM core (depth-2 ring, strided kc split). New: c1/c2 carried in
// REGISTERS (static per-thread cell ownership); X1 epilogue slab staged via
// cp.async (no register cost).
// smem (uint4 units): Gs [0,576) ; W1 [576,4672) ; W2 [4672,12864) ;
//                     XS [12864, 13440)  (64 rows x 36 floats)
__global__ __launch_bounds__(256) void k_recur(const float* __restrict__ b2)
{
    extern __shared__ uint4 sm[];
    const int tid = threadIdx.x, wid = tid >> 5, lane = tid & 31;
    const int mt = wid & 3, s = wid >> 2;
    const int rr = lane >> 2, cc = lane & 3;
    const int bx = blockIdx.x;
    float* Gs   = (float*)sm;
    const uint2* Wsm1 = (const uint2*)(sm + 576);
    const uint2* Wsm2 = (const uint2*)(sm + 4672);
    float* XSf  = (float*)(sm + 12864);     // [64][36]
    const int j = bx * 8 + cc * 2;
    const int j0 = bx * 8;

    // weights -> smem (one time)
    {
        const uint4* w1 = (const uint4*)g_W1p + (size_t)bx * 4096;
        for (int i = tid; i < 4096; i += 256) cp16(&sm[576 + i], &w1[i]);
        const uint4* w2 = (const uint4*)g_W2p + (size_t)bx * 8192;
        for (int i = tid; i < 8192; i += 256) cp16(&sm[4672 + i], &w2[i]);
        cp_commit(); cp_wait0(); __syncthreads();
    }

    float2 b2i = make_float2(b2[j],         b2[j + 1]);
    float2 b2f = make_float2(b2[H + j],     b2[H + j + 1]);
    float2 b2g = make_float2(b2[2 * H + j], b2[2 * H + j + 1]);
    float2 b2o = make_float2(b2[3 * H + j], b2[3 * H + j + 1]);

    const int em0 = mt * 16 + rr, em1 = em0 + 8;
    float2 h1res[2];
    float2 c1v[2] = { make_float2(0.f, 0.f), make_float2(0.f, 0.f) };
    float2 c2v[2] = { make_float2(0.f, 0.f), make_float2(0.f, 0.f) };

    for (int t = 0; t < NT; t++) {
        // ================= L1: gates = h1_prev @ W1^T + X1[t] ================
        {
            const uint4* A4 = (const uint4*)(g_h1p[t & 1]);
            float acc[4][4] = {};
            uint4 abuf[2][2];
            auto lda = [&](int q, uint4* d) {
                d[0] = __ldcg(A4 + ((q * 4 + s    ) * 4 + mt) * 32 + lane);
                d[1] = __ldcg(A4 + ((q * 4 + s + 2) * 4 + mt) * 32 + lane);
            };
            lda(0, abuf[0]); lda(1, abuf[1]);
            // stage X1 slab for the epilogue via cp.async (no register cost)
            {
                const float* Xt = g_X1 + (size_t)t * NB * G4;
#pragma unroll
                for (int e = 0; e < 2; e++) {
                    int i = tid + e * 256;          // 0..511
                    int m = i >> 3, seg = i & 7;
                    int g = seg >> 1, half = seg & 1;
                    cp16(&XSf[m * 36 + g * 8 + half * 4],
                         Xt + (size_t)m * G4 + g * H + j0 + half * 4);
                }
                cp_commit();
            }
#pragma unroll
            for (int q = 0; q < 16; q++) {
                uint4 c0 = abuf[q & 1][0], c1 = abuf[q & 1][1];
                if (q + 2 < 16) lda(q + 2, abuf[q & 1]);
                const int kc0 = q * 4 + s, kc1 = kc0 + 2;
#pragma unroll
                for (int g = 0; g < 4; g++)
                    mmabf(acc[g], c0, Wsm1[(kc0 * 4 + g) * 32 + lane]);
#pragma unroll
                for (int g = 0; g < 4; g++)
                    mmabf(acc[g], c1, Wsm1[(kc1 * 4 + g) * 32 + lane]);
            }
            cp_wait0();
            __syncthreads();                       // Gs free + XS ready
            if (s == 0) {
#pragma unroll
                for (int g = 0; g < 4; g++) {
                    Gs[em0 * 36 + g * 8 + cc * 2]     = acc[g][0];
                    Gs[em0 * 36 + g * 8 + cc * 2 + 1] = acc[g][1];
                    Gs[em1 * 36 + g * 8 + cc * 2]     = acc[g][2];
                    Gs[em1 * 36 + g * 8 + cc * 2 + 1] = acc[g][3];
                }
            }
            __syncthreads();
            if (s == 1) {
#pragma unroll
                for (int hh = 0; hh < 2; hh++) {
                    int m = hh ? em1 : em0;
                    const float* xm = &XSf[m * 36];
                    float gi0 = acc[0][hh*2]   + Gs[m*36 +      cc*2]     + xm[     cc*2];
                    float gi1 = acc[0][hh*2+1] + Gs[m*36 +      cc*2 + 1] + xm[     cc*2 + 1];
                    float gf0 = acc[1][hh*2]   + Gs[m*36 +  8 + cc*2]     + xm[ 8 + cc*2];
                    float gf1 = acc[1][hh*2+1] + Gs[m*36 +  8 + cc*2 + 1] + xm[ 8 + cc*2 + 1];
                    float gg0 = acc[2][hh*2]   + Gs[m*36 + 16 + cc*2]     + xm[16 + cc*2];
                    float gg1 = acc[2][hh*2+1] + Gs[m*36 + 16 + cc*2 + 1] + xm[16 + cc*2 + 1];
                    float go0 = acc[3][hh*2]   + Gs[m*36 + 24 + cc*2]     + xm[24 + cc*2];
                    float go1 = acc[3][hh*2+1] + Gs[m*36 + 24 + cc*2 + 1] + xm[24 + cc*2 + 1];
                    float cn0 = sigmoidf_(gf0) * c1v[hh].x + sigmoidf_(gi0) * tanhf(gg0);
                    float cn1 = sigmoidf_(gf1) * c1v[hh].y + sigmoidf_(gi1) * tanhf(gg1);
                    c1v[hh] = make_float2(cn0, cn1);
                    float h0 = sigmoidf_(go0) * tanhf(cn0);
                    float h1 = sigmoidf_(go1) * tanhf(cn1);
                    h1res[hh] = make_float2(h0, h1);
                    g_h1p[(t + 1) & 1][((((bx >> 1) * 4 + mt) * 32 + lane) * 4)
                                       + hh + 2 * (bx & 1)] = pk(h0, h1);
                }
            }
        }
        gbar((unsigned)(t + 1) * NCTA);            // all h1_t visible
        // ======= L2: gates = h1_t@Wih2^T + h2_prev@Whh2^T + b2, residual =====
        {
            const uint4* A4a = (const uint4*)(g_h1p[(t + 1) & 1]);
            const uint4* A4b = (const uint4*)(g_h2p[t & 1]);
            float acc[4][4] = {};
            uint4 abuf[2][2];
            auto lda2 = [&](int q, uint4* d) {
                const int k0 = q * 4 + s, k1 = k0 + 2;
                const uint4* p0 = (k0 < 64) ? (A4a + (k0 * 4 + mt) * 32 + lane)
                                            : (A4b + ((k0 - 64) * 4 + mt) * 32 + lane);
                const uint4* p1 = (k1 < 64) ? (A4a + (k1 * 4 + mt) * 32 + lane)
                                            : (A4b + ((k1 - 64) * 4 + mt) * 32 + lane);
                d[0] = __ldcg(p0); d[1] = __ldcg(p1);
            };
            lda2(0, abuf[0]); lda2(1, abuf[1]);
#pragma unroll
            for (int q = 0; q < 32; q++) {
                uint4 c0 = abuf[q & 1][0], c1 = abuf[q & 1][1];
                if (q + 2 < 32) lda2(q + 2, abuf[q & 1]);
                const int kc0 = q * 4 + s, kc1 = kc0 + 2;
#pragma unroll
                for (int g = 0; g < 4; g++)
                    mmabf(acc[g], c0, Wsm2[(kc0 * 4 + g) * 32 + lane]);
#pragma unroll
                for (int g = 0; g < 4; g++)
                    mmabf(acc[g], c1, Wsm2[(kc1 * 4 + g) * 32 + lane]);
            }
            __syncthreads();
            if (s == 0) {
#pragma unroll
                for (int g = 0; g < 4; g++) {
                    Gs[em0 * 36 + g * 8 + cc * 2]     = acc[g][0];
                    Gs[em0 * 36 + g * 8 + cc * 2 + 1] = acc[g][1];
                    Gs[em1 * 36 + g * 8 + cc * 2]     = acc[g][2];
                    Gs[em1 * 36 + g * 8 + cc * 2 + 1] = acc[g][3];
                }
            }
            __syncthreads();
            if (s == 1) {
#pragma unroll
                for (int hh = 0; hh < 2; hh++) {
                    int m = hh ? em1 : em0;
                    float gi0 = acc[0][hh*2]   + Gs[m*36 +      cc*2]     + b2i.x;
                    float gi1 = acc[0][hh*2+1] + Gs[m*36 +      cc*2 + 1] + b2i.y;
                    float gf0 = acc[1][hh*2]   + Gs[m*36 +  8 + cc*2]     + b2f.x;
                    float gf1 = acc[1][hh*2+1] + Gs[m*36 +  8 + cc*2 + 1] + b2f.y;
                    float gg0 = acc[2][hh*2]   + Gs[m*36 + 16 + cc*2]     + b2g.x;
                    float gg1 = acc[2][hh*2+1] + Gs[m*36 + 16 + cc*2 + 1] + b2g.y;
                    float go0 = acc[3][hh*2]   + Gs[m*36 + 24 + cc*2]     + b2o.x;
                    float go1 = acc[3][hh*2+1] + Gs[m*36 + 24 + cc*2 + 1] + b2o.y;
                    float cn0 = sigmoidf_(gf0) * c2v[hh].x + sigmoidf_(gi0) * tanhf(gg0);
                    float cn1 = sigmoidf_(gf1) * c2v[hh].y + sigmoidf_(gi1) * tanhf(gg1);
                    c2v[hh] = make_float2(cn0, cn1);
                    float h0 = sigmoidf_(go0) * tanhf(cn0);
                    float h1 = sigmoidf_(go1) * tanhf(cn1);
                    g_h2p[(t + 1) & 1][((((bx >> 1) * 4 + mt) * 32 + lane) * 4)
                                       + hh + 2 * (bx & 1)] = pk(h0, h1);
                    int mbL   = m * 2 + (t >> 6);
                    int kcL   = bx >> 1;
                    int mtL   = (t >> 4) & 3;
                    int laneL = (t & 7) * 4 + cc;
                    int regL  = ((t >> 3) & 1) + 2 * (bx & 1);
                    g_LOp[((((size_t)mbL * 64 + kcL) * 4 + mtL) * 32 + laneL) * 4 + regL]
                        = pk(h0 + h1res[hh].x, h1 + h1res[hh].y);
                }
            }
        }
    }
}

// =================== head GEMM 1: hid = relu(LO @ Wp1 + bp1) =================
__global__ __launch_bounds__(256) void k_mlp1b(const float* __restrict__ bp1)
{
    extern __shared__ uint4 sm[];
    const int tid = threadIdx.x, wid = tid >> 5, lane = tid & 31;
    const int mt = wid & 3, s = wid >> 2;
    const int rr = lane >> 2, cc = lane & 3;
    const int nb = blockIdx.x, mb = blockIdx.y;
    float acc[4][4] = {};
    const uint4* A4 = (const uint4*)g_LOp + (size_t)mb * 64 * 128;
    const uint4* B4 = (const uint4*)g_Wp1p + (size_t)nb * 64 * 128;

    auto loadst = [&](int it) {
        if (it < 16) {
            uint4* dst = sm + (it & 3) * 1024;
            const uint4* a = A4 + (size_t)it * 512;
            const uint4* b = B4 + (size_t)it * 512;
            cp16(&dst[tid],             &a[tid]);
            cp16(&dst[tid + 256],       &a[tid + 256]);
            cp16(&dst[512 + tid],       &b[tid]);
            cp16(&dst[512 + tid + 256], &b[tid + 256]);
        }
        cp_commit();
    };
    loadst(0); loadst(1); loadst(2);
    for (int it = 0; it < 16; it++) {
        cp_wait2(); __syncthreads();
        loadst(it + 3);
        const uint4* SA = sm + (it & 3) * 1024;
        const uint2* SB = (const uint2*)(SA + 512);
#pragma unroll
        for (int kcl = 0; kcl < 4; kcl++) {
            uint4 a = SA[(kcl * 4 + mt) * 32 + lane];
#pragma unroll
            for (int jn = 0; jn < 4; jn++) {
                uint2 b = SB[(kcl * 8 + s * 4 + jn) * 32 + lane];
                mmabf(acc[jn], a, b);
            }
        }
    }
#pragma unroll
    for (int jn = 0; jn < 4; jn++) {
        int c8  = s * 4 + jn;
        int col = nb * 64 + c8 * 8 + cc * 2;
        float b0 = bp1[col], b1 = bp1[col + 1];
        int kcH = nb * 4 + (c8 >> 1);
        int regH_base = 2 * (c8 & 1);
#pragma unroll
        for (int hh = 0; hh < 2; hh++) {
            float v0 = fmaxf(acc[jn][hh * 2 + 0] + b0, 0.f);
            float v1 = fmaxf(acc[jn][hh * 2 + 1] + b1, 0.f);
            g_HIDp[((((size_t)mb * 16 + kcH) * 4 + mt) * 32 + (rr * 4 + cc)) * 4
                   + hh + regH_base] = pk(v0, v1);
        }
    }
}

// =================== head GEMM 2: logits = hid @ Wp2 + bp2 ===================
__global__ __launch_bounds__(256) void k_logitsb(const float* __restrict__ bp2,
                                                 float* __restrict__ out)
{
    extern __shared__ uint4 sm[];
    const int tid = threadIdx.x, wid = tid >> 5, lane = tid & 31;
    const int mt = wid & 3, s = wid >> 2;
    const int rr = lane >> 2, cc = lane & 3;
    const int nb = blockIdx.x, mb = blockIdx.y;
    float acc[4][4] = {};
    const uint4* A4 = (const uint4*)g_HIDp + (size_t)mb * 16 * 128;
    const uint4* B4 = (const uint4*)g_Wp2p + (size_t)nb * 16 * 128;

    auto loadst = [&](int it) {
        if (it < 4) {
            uint4* dst = sm + (it & 3) * 1024;
            const uint4* a = A4 + (size_t)it * 512;
            const uint4* b = B4 + (size_t)it * 512;
            cp16(&dst[tid],             &a[tid]);
            cp16(&dst[tid + 256],       &a[tid + 256]);
            cp16(&dst[512 + tid],       &b[tid]);
            cp16(&dst[512 + tid + 256], &b[tid + 256]);
        }
        cp_commit();
    };
    loadst(0); loadst(1); loadst(2);
    for (int it = 0; it < 4; it++) {
        cp_wait2(); __syncthreads();
        loadst(it + 3);
        const uint4* SA = sm + (it & 3) * 1024;
        const uint2* SB = (const uint2*)(SA + 512);
#pragma unroll
        for (int kcl = 0; kcl < 4; kcl++) {
            uint4 a = SA[(kcl * 4 + mt) * 32 + lane];
#pragma unroll
            for (int jn = 0; jn < 4; jn++) {
                uint2 b = SB[(kcl * 8 + s * 4 + jn) * 32 + lane];
                mmabf(acc[jn], a, b);
            }
        }
    }
#pragma unroll
    for (int jn = 0; jn < 4; jn++) {
        int n = nb * 64 + (s * 4 + jn) * 8 + cc * 2;
        if (n < NANS) {
            float b0 = bp2[n], b1 = bp2[n + 1];
#pragma unroll
            for (int hh = 0; hh < 2; hh++) {
                int m = mb * 64 + mt * 16 + rr + hh * 8;
                float* o = out + (size_t)m * NANS + n;
                o[0] = acc[jn][hh * 2 + 0] + b0;
                o[1] = acc[jn][hh * 2 + 1] + b1;
            }
        }
    }
}

// ---------------- softmax ------------------------------------------------------
__global__ __launch_bounds__(256) void k_softmax(float* __restrict__ out)
{
    __shared__ float red[256];
    const int tid = threadIdx.x;
    float* p = out + (size_t)blockIdx.x * NANS;
    float v[4];
    float mx = -1e30f;
#pragma unroll
    for (int i = 0; i < 4; i++) {
        int n = tid + i * 256;
        v[i] = (n < NANS) ? p[n] : -1e30f;
        mx = fmaxf(mx, v[i]);
    }
    red[tid] = mx; __syncthreads();
    for (int s = 128; s > 0; s >>= 1) {
        if (tid < s) red[tid] = fmaxf(red[tid], red[tid + s]);
        __syncthreads();
    }
    mx = red[0]; __syncthreads();
    float sum = 0.f;
#pragma unroll
    for (int i = 0; i < 4; i++) {
        int n = tid + i * 256;
        if (n < NANS) { v[i] = expf(v[i] - mx); sum += v[i]; }
    }
    red[tid] = sum; __syncthreads();
    for (int s = 128; s > 0; s >>= 1) {
        if (tid < s) red[tid] += red[tid + s];
        __syncthreads();
    }
    float inv = 1.f / red[0];
#pragma unroll
    for (int i = 0; i < 4; i++) {
        int n = tid + i * 256;
        if (n < NANS) p[n] = v[i] * inv;
    }
}

// ---------------- launch ------------------------------------------------------
extern "C" void kernel_launch(void* const* d_in, const int* in_sizes, int n_in,
                              void* d_out, int out_size)
{
    const float* data1 = (const float*)d_in[0];
    const float* data2 = (const float*)d_in[1];
    const float* W_ih1 = (const float*)d_in[2];
    const float* W_hh1 = (const float*)d_in[3];
    const float* b1    = (const float*)d_in[4];
    const float* W_ih2 = (const float*)d_in[5];
    const float* W_hh2 = (const float*)d_in[6];
    const float* b2    = (const float*)d_in[7];
    const float* Wp1   = (const float*)d_in[8];
    const float* bp1   = (const float*)d_in[9];
    const float* Wp2   = (const float*)d_in[10];
    const float* bp2   = (const float*)d_in[11];
    float* out = (float*)d_out;

    static bool attr_done = false;
    if (!attr_done) {
        cudaFuncSetAttribute(k_xprojb,  cudaFuncAttributeMaxDynamicSharedMemorySize, 65536);
        cudaFuncSetAttribute(k_mlp1b,   cudaFuncAttributeMaxDynamicSharedMemorySize, 65536);
        cudaFuncSetAttribute(k_logitsb, cudaFuncAttributeMaxDynamicSharedMemorySize, 65536);
        cudaFuncSetAttribute(k_recur,   cudaFuncAttributeMaxDynamicSharedMemorySize, 215040);
        attr_done = true;
    }

    k_init_state<<<128, 256>>>();
    k_pack_all<<<dim3(1024, 6), 256>>>(W_hh1, W_ih2, W_hh2, data1, data2,
                                       W_ih1, Wp1, Wp2);
    k_xprojb<<<dim3(64, 128), 256, 65536>>>(b1);
    k_recur<<<128, 256, 215040>>>(b2);
    k_mlp1b<<<dim3(4, 128), 256, 65536>>>(bp1);
    k_logitsb<<<dim3(16, 128), 256, 65536>>>(bp2, out);
    k_softmax<<<BT, 256>>>(out);
}

// round 9
// speedup vs baseline: 1.3937x; 1.1129x over previous
#include <cuda_runtime.h>
#include <cuda_bf16.h>
#include <cstdint>
#include <math.h>

#define NB   64
#define NT   128
#define BT   8192
#define H    1024
#define DIN  2048
#define G4   4096
#define NH1  256
#define NANS 1000
#define NCTA 128u

// ---------------- device scratch ----------------
__device__ float g_X1[(size_t)BT * G4];          // [t][b][4H] (includes +b1)
__device__ unsigned g_bar;
// h in bf16 A-fragment layout: [kc(64)][mt(4)][lane(32)][reg(4)] u32
__device__ __align__(16) uint32_t g_h1p[2][32768];
__device__ __align__(16) uint32_t g_h2p[2][32768];
// step weights, B-fragment layout: [bx(128)][kc][g(4)][lane(32)] uint2
__device__ __align__(16) uint32_t g_W1p[128 * 64 * 4 * 32 * 2];     // 8 MB
__device__ __align__(16) uint32_t g_W2p[128 * 128 * 4 * 32 * 2];    // 16 MB
// xproj operands
__device__ __align__(16) uint32_t g_Ax[(size_t)128 * 128 * 4 * 32 * 4];  // 32 MB
__device__ __align__(16) uint32_t g_Wx[(size_t)64 * 128 * 8 * 32 * 2];   // 16 MB
// head: lstm_out bf16 A-frag [mb(128)][kc(64)][mt(4)][lane(32)][reg(4)]
__device__ __align__(16) uint32_t g_LOp[(size_t)128 * 64 * 4 * 32 * 4];  // 16 MB
// hid bf16 A-frag [mb(128)][kc(16)][mt][lane][reg]
__device__ __align__(16) uint32_t g_HIDp[(size_t)128 * 16 * 4 * 32 * 4]; // 4 MB
__device__ __align__(16) uint32_t g_Wp1p[4 * 64 * 8 * 32 * 2];
__device__ __align__(16) uint32_t g_Wp2p[16 * 16 * 8 * 32 * 2];

// fast activations: __expf is branch-free MUFU.EX2; division via MUFU.RCP
__device__ __forceinline__ float fsig(float x) {
    return __fdividef(1.f, 1.f + __expf(-x));
}
__device__ __forceinline__ float ftanh_(float x) {
    return fmaf(2.f, fsig(2.f * x), -1.f);
}
__device__ __forceinline__ uint32_t pk(float x, float y) {
    __nv_bfloat162 v = __floats2bfloat162_rn(x, y);
    return *reinterpret_cast<uint32_t*>(&v);
}
__device__ __forceinline__ void mmabf(float c[4], uint4 a, uint2 b) {
    asm volatile(
        "mma.sync.aligned.m16n8k16.row.col.f32.bf16.bf16.f32 "
        "{%0,%1,%2,%3},{%4,%5,%6,%7},{%8,%9},{%0,%1,%2,%3};"
        : "+f"(c[0]), "+f"(c[1]), "+f"(c[2]), "+f"(c[3])
        : "r"(a.x), "r"(a.y), "r"(a.z), "r"(a.w), "r"(b.x), "r"(b.y));
}
__device__ __forceinline__ void cp16(void* smem, const void* g) {
    uint32_t s = (uint32_t)__cvta_generic_to_shared(smem);
    asm volatile("cp.async.cg.shared.global [%0], [%1], 16;" :: "r"(s), "l"(g));
}
__device__ __forceinline__ void cp_commit() { asm volatile("cp.async.commit_group;"); }
__device__ __forceinline__ void cp_wait2()  { asm volatile("cp.async.wait_group 2;"); }
__device__ __forceinline__ void cp_wait0()  { asm volatile("cp.async.wait_group 0;"); }

// global barrier: release-arrive + acquire-poll (no full MEMBAR.GPU)
__device__ __forceinline__ void gbar(unsigned target) {
    __syncthreads();
    if (threadIdx.x == 0) {
        unsigned* bp = &g_bar;
        asm volatile("red.release.gpu.global.add.u32 [%0], %1;"
                     :: "l"(bp), "r"(1u) : "memory");
        unsigned v;
        do {
            asm volatile("ld.acquire.gpu.global.u32 %0, [%1];"
                         : "=r"(v) : "l"(bp) : "memory");
        } while (v < target);
    }
    __syncthreads();
}

// ---------------- init ----------------
__global__ void k_init_state() {
    int i = blockIdx.x * blockDim.x + threadIdx.x;
    if (i == 0) g_bar = 0u;
    if (i < 32768) { g_h1p[0][i] = 0u; g_h2p[0][i] = 0u; }
}

// ---------------- unified pack kernel (job = blockIdx.y) ---------------------
__global__ void k_pack_all(
    const float* __restrict__ W_hh1, const float* __restrict__ W_ih2,
    const float* __restrict__ W_hh2, const float* __restrict__ d1,
    const float* __restrict__ d2,   const float* __restrict__ W_ih1,
    const float* __restrict__ Wp1,  const float* __restrict__ Wp2)
{
    const int job = blockIdx.y;
    const int gid = blockIdx.x * blockDim.x + threadIdx.x;
    const int stride = gridDim.x * blockDim.x;

    if (job == 0) {
        uint2* out = (uint2*)g_W1p;
        for (int idx = gid; idx < 128 * 64 * 4 * 32; idx += stride) {
            int lane = idx & 31;
            int t1 = idx >> 5;  int g = t1 & 3;
            int t2 = t1 >> 2;   int kc = t2 & 63; int bx = t2 >> 6;
            int rr = lane >> 2, cc = lane & 3;
            const float* p = W_hh1 + (size_t)(g * H + bx * 8 + rr) * H + kc * 16 + cc * 2;
            uint2 v; v.x = pk(p[0], p[1]); v.y = pk(p[8], p[9]);
            out[idx] = v;
        }
    } else if (job == 1) {
        uint2* out = (uint2*)g_W2p;
        for (int idx = gid; idx < 128 * 128 * 4 * 32; idx += stride) {
            int lane = idx & 31;
            int t1 = idx >> 5;  int g = t1 & 3;
            int t2 = t1 >> 2;   int kc = t2 & 127; int bx = t2 >> 7;
            int rr = lane >> 2, cc = lane & 3;
            int row = g * H + bx * 8 + rr;
            const float* W = W_ih2; int k0 = kc * 16 + cc * 2;
            if (kc >= 64) { W = W_hh2; k0 -= 1024; }
            const float* p = W + (size_t)row * H + k0;
            uint2 v; v.x = pk(p[0], p[1]); v.y = pk(p[8], p[9]);
            out[idx] = v;
        }
    } else if (job == 2) {
        uint4* out = (uint4*)g_Ax;
        for (int idx = gid; idx < 128 * 128 * 4 * 32; idx += stride) {
            int lane = idx & 31;
            int t1 = idx >> 5;
            int mt = t1 & 3; t1 >>= 2;
            int kc = t1 & 127;
            int mb = t1 >> 7;
            int rr = lane >> 2, cc = lane & 3;
            int r0 = mb * 64 + mt * 16 + rr, r1 = r0 + 8;
            int k0 = kc * 16 + cc * 2;
            const float *s0, *s1;
            if (k0 < 1024) { s0 = d1 + (size_t)r0 * 1024 + k0;        s1 = d1 + (size_t)r1 * 1024 + k0; }
            else           { s0 = d2 + (size_t)r0 * 1024 + k0 - 1024; s1 = d2 + (size_t)r1 * 1024 + k0 - 1024; }
            uint4 v;
            v.x = pk(s0[0], s0[1]);
            v.y = pk(s1[0], s1[1]);
            v.z = pk(s0[8], s0[9]);
            v.w = pk(s1[8], s1[9]);
            out[idx] = v;
        }
    } else if (job == 3) {
        uint2* out = (uint2*)g_Wx;
        for (int idx = gid; idx < 64 * 128 * 8 * 32; idx += stride) {
            int lane = idx & 31;
            int t1 = idx >> 5;
            int c = t1 & 7; t1 >>= 3;
            int kc = t1 & 127;
            int nb = t1 >> 7;
            int rr = lane >> 2, cc = lane & 3;
            const float* p = W_ih1 + (size_t)(nb * 64 + c * 8 + rr) * DIN + kc * 16 + cc * 2;
            uint2 v; v.x = pk(p[0], p[1]); v.y = pk(p[8], p[9]);
            out[idx] = v;
        }
    } else if (job == 4) {
        uint2* out = (uint2*)g_Wp1p;
        for (int idx = gid; idx < 4 * 64 * 8 * 32; idx += stride) {
            int lane = idx & 31;
            int t1 = idx >> 5;
            int c = t1 & 7; t1 >>= 3;
            int kc = t1 & 63;
            int nb = t1 >> 6;
            int rr = lane >> 2, cc = lane & 3;
            int n  = nb * 64 + c * 8 + rr;
            int k0 = kc * 16 + cc * 2;
            uint2 v;
            v.x = pk(Wp1[(size_t)k0 * NH1 + n],       Wp1[(size_t)(k0 + 1) * NH1 + n]);
            v.y = pk(Wp1[(size_t)(k0 + 8) * NH1 + n], Wp1[(size_t)(k0 + 9) * NH1 + n]);
            out[idx] = v;
        }
    } else {
        uint2* out = (uint2*)g_Wp2p;
        for (int idx = gid; idx < 16 * 16 * 8 * 32; idx += stride) {
            int lane = idx & 31;
            int t1 = idx >> 5;
            int c = t1 & 7; t1 >>= 3;
            int kc = t1 & 15;
            int nb = t1 >> 4;
            int rr = lane >> 2, cc = lane & 3;
            int n  = nb * 64 + c * 8 + rr;
            int k0 = kc * 16 + cc * 2;
            float a0 = 0.f, a1 = 0.f, b0 = 0.f, b1 = 0.f;
            if (n < NANS) {
                a0 = Wp2[(size_t)k0 * NANS + n];       a1 = Wp2[(size_t)(k0 + 1) * NANS + n];
                b0 = Wp2[(size_t)(k0 + 8) * NANS + n]; b1 = Wp2[(size_t)(k0 + 9) * NANS + n];
            }
            uint2 v; v.x = pk(a0, a1); v.y = pk(b0, b1);
            out[idx] = v;
        }
    }
}

// =================== xproj: bf16 mma, pre-packed fragments ==================
__global__ __launch_bounds__(256) void k_xprojb(const float* __restrict__ bias)
{
    extern __shared__ uint4 sm[];
    const int tid = threadIdx.x, wid = tid >> 5, lane = tid & 31;
    const int mt = wid & 3, s = wid >> 2;
    const int rr = lane >> 2, cc = lane & 3;
    const int nb = blockIdx.x, mb = blockIdx.y;
    float acc[4][4] = {};
    const uint4* A4 = (const uint4*)g_Ax + (size_t)mb * 128 * 128;
    const uint4* B4 = (const uint4*)g_Wx + (size_t)nb * 128 * 128;

    auto loadst = [&](int it) {
        if (it < 32) {
            uint4* dst = sm + (it & 3) * 1024;
            const uint4* a = A4 + (size_t)it * 512;
            const uint4* b = B4 + (size_t)it * 512;
            cp16(&dst[tid],             &a[tid]);
            cp16(&dst[tid + 256],       &a[tid + 256]);
            cp16(&dst[512 + tid],       &b[tid]);
            cp16(&dst[512 + tid + 256], &b[tid + 256]);
        }
        cp_commit();
    };
    loadst(0); loadst(1); loadst(2);
    for (int it = 0; it < 32; it++) {
        cp_wait2(); __syncthreads();
        loadst(it + 3);
        const uint4* SA = sm + (it & 3) * 1024;
        const uint2* SB = (const uint2*)(SA + 512);
#pragma unroll
        for (int kcl = 0; kcl < 4; kcl++) {
            uint4 a = SA[(kcl * 4 + mt) * 32 + lane];
#pragma unroll
            for (int jn = 0; jn < 4; jn++) {
                uint2 b = SB[(kcl * 8 + s * 4 + jn) * 32 + lane];
                mmabf(acc[jn], a, b);
            }
        }
    }
#pragma unroll
    for (int jn = 0; jn < 4; jn++) {
        int col = nb * 64 + (s * 4 + jn) * 8 + cc * 2;
        float b0 = bias[col], b1 = bias[col + 1];
#pragma unroll
        for (int hh = 0; hh < 2; hh++) {
            int m = mb * 64 + mt * 16 + rr + hh * 8;
            int tt = m & 127, bb = m >> 7;
            float* o = g_X1 + ((size_t)tt * NB + bb) * G4 + col;
            o[0] = acc[jn][hh * 2 + 0] + b0;
            o[1] = acc[jn][hh * 2 + 1] + b1;
        }
    }
}

// =================== persistent recurrence kernel ===========================
// Contiguous-kc warp split, depth-4 A ring (reg-neutral), cross-step prefetch
// of next L1's first A-frags in the L2 GEMM tail, c-state in registers, X1 via
// cp.async, fast activations, release/acquire global barrier.
// smem (uint4 units): Gs [0,576) ; W1 [576,4672) ; W2 [4672,12864) ;
//                     XS [12864,13440)
__global__ __launch_bounds__(256) void k_recur(const float* __restrict__ b2)
{
    extern __shared__ uint4 sm[];
    const int tid = threadIdx.x, wid = tid >> 5, lane = tid & 31;
    const int mt = wid & 3, s = wid >> 2;
    const int rr = lane >> 2, cc = lane & 3;
    const int bx = blockIdx.x;
    float* Gs   = (float*)sm;
    const uint2* Wsm1 = (const uint2*)(sm + 576);
    const uint2* Wsm2 = (const uint2*)(sm + 4672);
    float* XSf  = (float*)(sm + 12864);     // [64][36]
    const int j = bx * 8 + cc * 2;
    const int j0 = bx * 8;
    const int fragoff = mt * 32 + lane;     // within-kc fragment offset (uint4)

    // weights -> smem (one time)
    {
        const uint4* w1 = (const uint4*)g_W1p + (size_t)bx * 4096;
        for (int i = tid; i < 4096; i += 256) cp16(&sm[576 + i], &w1[i]);
        const uint4* w2 = (const uint4*)g_W2p + (size_t)bx * 8192;
        for (int i = tid; i < 8192; i += 256) cp16(&sm[4672 + i], &w2[i]);
        cp_commit(); cp_wait0(); __syncthreads();
    }

    float2 b2i = make_float2(b2[j],         b2[j + 1]);
    float2 b2f = make_float2(b2[H + j],     b2[H + j + 1]);
    float2 b2g = make_float2(b2[2 * H + j], b2[2 * H + j + 1]);
    float2 b2o = make_float2(b2[3 * H + j], b2[3 * H + j + 1]);

    const int em0 = mt * 16 + rr, em1 = em0 + 8;
    float2 h1res[2];
    float2 c1v[2] = { make_float2(0.f, 0.f), make_float2(0.f, 0.f) };
    float2 c2v[2] = { make_float2(0.f, 0.f), make_float2(0.f, 0.f) };

    // prefill ring for L1(t=0): kc = s*32 + p
    uint4 ring[4];
    {
        const uint4* Aw = (const uint4*)(g_h1p[0]) + (s * 32) * 128 + fragoff;
#pragma unroll
        for (int p = 0; p < 4; p++) ring[p] = __ldcg(Aw + p * 128);
    }

    for (int t = 0; t < NT; t++) {
        // ================= L1: gates = h1_prev @ W1^T + X1[t] ================
        {
            const uint4* Aw = (const uint4*)(g_h1p[t & 1]) + (s * 32) * 128 + fragoff;
            float acc[4][4] = {};
            // stage X1 slab for the epilogue via cp.async
            {
                const float* Xt = g_X1 + (size_t)t * NB * G4;
#pragma unroll
                for (int e = 0; e < 2; e++) {
                    int i = tid + e * 256;
                    int m = i >> 3, seg = i & 7;
                    int g = seg >> 1, half = seg & 1;
                    cp16(&XSf[m * 36 + g * 8 + half * 4],
                         Xt + (size_t)m * G4 + g * H + j0 + half * 4);
                }
                cp_commit();
            }
#pragma unroll 8
            for (int q = 0; q < 32; q++) {
                uint4 a = ring[q & 3];
                if (q + 4 < 32) ring[q & 3] = __ldcg(Aw + (q + 4) * 128);
                const int kc = s * 32 + q;
#pragma unroll
                for (int g = 0; g < 4; g++)
                    mmabf(acc[g], a, Wsm1[(kc * 4 + g) * 32 + lane]);
            }
            cp_wait0();
            __syncthreads();                       // Gs free + XS ready
            if (s == 0) {
#pragma unroll
                for (int g = 0; g < 4; g++) {
                    Gs[em0 * 36 + g * 8 + cc * 2]     = acc[g][0];
                    Gs[em0 * 36 + g * 8 + cc * 2 + 1] = acc[g][1];
                    Gs[em1 * 36 + g * 8 + cc * 2]     = acc[g][2];
                    Gs[em1 * 36 + g * 8 + cc * 2 + 1] = acc[g][3];
                }
            }
            __syncthreads();
            if (s == 1) {
#pragma unroll
                for (int hh = 0; hh < 2; hh++) {
                    int m = hh ? em1 : em0;
                    const float* xm = &XSf[m * 36];
                    float gi0 = acc[0][hh*2]   + Gs[m*36 +      cc*2]     + xm[     cc*2];
                    float gi1 = acc[0][hh*2+1] + Gs[m*36 +      cc*2 + 1] + xm[     cc*2 + 1];
                    float gf0 = acc[1][hh*2]   + Gs[m*36 +  8 + cc*2]     + xm[ 8 + cc*2];
                    float gf1 = acc[1][hh*2+1] + Gs[m*36 +  8 + cc*2 + 1] + xm[ 8 + cc*2 + 1];
                    float gg0 = acc[2][hh*2]   + Gs[m*36 + 16 + cc*2]     + xm[16 + cc*2];
                    float gg1 = acc[2][hh*2+1] + Gs[m*36 + 16 + cc*2 + 1] + xm[16 + cc*2 + 1];
                    float go0 = acc[3][hh*2]   + Gs[m*36 + 24 + cc*2]     + xm[24 + cc*2];
                    float go1 = acc[3][hh*2+1] + Gs[m*36 + 24 + cc*2 + 1] + xm[24 + cc*2 + 1];
                    float cn0 = fsig(gf0) * c1v[hh].x + fsig(gi0) * ftanh_(gg0);
                    float cn1 = fsig(gf1) * c1v[hh].y + fsig(gi1) * ftanh_(gg1);
                    c1v[hh] = make_float2(cn0, cn1);
                    float h0 = fsig(go0) * ftanh_(cn0);
                    float h1 = fsig(go1) * ftanh_(cn1);
                    h1res[hh] = make_float2(h0, h1);
                    g_h1p[(t + 1) & 1][((((bx >> 1) * 4 + mt) * 32 + lane) * 4)
                                       + hh + 2 * (bx & 1)] = pk(h0, h1);
                }
            }
        }
        gbar((unsigned)(t + 1) * NCTA);            // all h1_t visible
        // ======= L2: gates = h1_t@Wih2^T + h2_prev@Whh2^T + b2, residual =====
        {
            // s=0 warps consume h1_t (kc 0..63), s=1 warps consume h2_prev (kc 64..127)
            const uint4* Aw2 = (const uint4*)(s == 0 ? g_h1p[(t + 1) & 1]
                                                     : g_h2p[t & 1]) + fragoff;
            // next step L1 A pointer (h1p[(t+1)&1] is now globally synced)
            const uint4* AwN = (const uint4*)(g_h1p[(t + 1) & 1])
                               + (s * 32) * 128 + fragoff;
            float acc[4][4] = {};
#pragma unroll
            for (int p = 0; p < 4; p++) ring[p] = __ldcg(Aw2 + p * 128);
#pragma unroll 8
            for (int q = 0; q < 64; q++) {
                uint4 a = ring[q & 3];
                ring[q & 3] = (q + 4 < 64) ? __ldcg(Aw2 + (q + 4) * 128)
                                           : __ldcg(AwN + (q - 60) * 128);
                const int kc = s * 64 + q;
#pragma unroll
                for (int g = 0; g < 4; g++)
                    mmabf(acc[g], a, Wsm2[(kc * 4 + g) * 32 + lane]);
            }
            __syncthreads();
            if (s == 0) {
#pragma unroll
                for (int g = 0; g < 4; g++) {
                    Gs[em0 * 36 + g * 8 + cc * 2]     = acc[g][0];
                    Gs[em0 * 36 + g * 8 + cc * 2 + 1] = acc[g][1];
                    Gs[em1 * 36 + g * 8 + cc * 2]     = acc[g][2];
                    Gs[em1 * 36 + g * 8 + cc * 2 + 1] = acc[g][3];
                }
            }
            __syncthreads();
            if (s == 1) {
#pragma unroll
                for (int hh = 0; hh < 2; hh++) {
                    int m = hh ? em1 : em0;
                    float gi0 = acc[0][hh*2]   + Gs[m*36 +      cc*2]     + b2i.x;
                    float gi1 = acc[0][hh*2+1] + Gs[m*36 +      cc*2 + 1] + b2i.y;
                    float gf0 = acc[1][hh*2]   + Gs[m*36 +  8 + cc*2]     + b2f.x;
                    float gf1 = acc[1][hh*2+1] + Gs[m*36 +  8 + cc*2 + 1] + b2f.y;
                    float gg0 = acc[2][hh*2]   + Gs[m*36 + 16 + cc*2]     + b2g.x;
                    float gg1 = acc[2][hh*2+1] + Gs[m*36 + 16 + cc*2 + 1] + b2g.y;
                    float go0 = acc[3][hh*2]   + Gs[m*36 + 24 + cc*2]     + b2o.x;
                    float go1 = acc[3][hh*2+1] + Gs[m*36 + 24 + cc*2 + 1] + b2o.y;
                    float cn0 = fsig(gf0) * c2v[hh].x + fsig(gi0) * ftanh_(gg0);
                    float cn1 = fsig(gf1) * c2v[hh].y + fsig(gi1) * ftanh_(gg1);
                    c2v[hh] = make_float2(cn0, cn1);
                    float h0 = fsig(go0) * ftanh_(cn0);
                    float h1 = fsig(go1) * ftanh_(cn1);
                    g_h2p[(t + 1) & 1][((((bx >> 1) * 4 + mt) * 32 + lane) * 4)
                                       + hh + 2 * (bx & 1)] = pk(h0, h1);
                    int mbL   = m * 2 + (t >> 6);
                    int kcL   = bx >> 1;
                    int mtL   = (t >> 4) & 3;
                    int laneL = (t & 7) * 4 + cc;
                    int regL  = ((t >> 3) & 1) + 2 * (bx & 1);
                    g_LOp[((((size_t)mbL * 64 + kcL) * 4 + mtL) * 32 + laneL) * 4 + regL]
                        = pk(h0 + h1res[hh].x, h1 + h1res[hh].y);
                }
            }
        }
    }
}

// =================== head GEMM 1: hid = relu(LO @ Wp1 + bp1) =================
__global__ __launch_bounds__(256) void k_mlp1b(const float* __restrict__ bp1)
{
    extern __shared__ uint4 sm[];
    const int tid = threadIdx.x, wid = tid >> 5, lane = tid & 31;
    const int mt = wid & 3, s = wid >> 2;
    const int rr = lane >> 2, cc = lane & 3;
    const int nb = blockIdx.x, mb = blockIdx.y;
    float acc[4][4] = {};
    const uint4* A4 = (const uint4*)g_LOp + (size_t)mb * 64 * 128;
    const uint4* B4 = (const uint4*)g_Wp1p + (size_t)nb * 64 * 128;

    auto loadst = [&](int it) {
        if (it < 16) {
            uint4* dst = sm + (it & 3) * 1024;
            const uint4* a = A4 + (size_t)it * 512;
            const uint4* b = B4 + (size_t)it * 512;
            cp16(&dst[tid],             &a[tid]);
            cp16(&dst[tid + 256],       &a[tid + 256]);
            cp16(&dst[512 + tid],       &b[tid]);
            cp16(&dst[512 + tid + 256], &b[tid + 256]);
        }
        cp_commit();
    };
    loadst(0); loadst(1); loadst(2);
    for (int it = 0; it < 16; it++) {
        cp_wait2(); __syncthreads();
        loadst(it + 3);
        const uint4* SA = sm + (it & 3) * 1024;
        const uint2* SB = (const uint2*)(SA + 512);
#pragma unroll
        for (int kcl = 0; kcl < 4; kcl++) {
            uint4 a = SA[(kcl * 4 + mt) * 32 + lane];
#pragma unroll
            for (int jn = 0; jn < 4; jn++) {
                uint2 b = SB[(kcl * 8 + s * 4 + jn) * 32 + lane];
                mmabf(acc[jn], a, b);
            }
        }
    }
#pragma unroll
    for (int jn = 0; jn < 4; jn++) {
        int c8  = s * 4 + jn;
        int col = nb * 64 + c8 * 8 + cc * 2;
        float b0 = bp1[col], b1 = bp1[col + 1];
        int kcH = nb * 4 + (c8 >> 1);
        int regH_base = 2 * (c8 & 1);
#pragma unroll
        for (int hh = 0; hh < 2; hh++) {
            float v0 = fmaxf(acc[jn][hh * 2 + 0] + b0, 0.f);
            float v1 = fmaxf(acc[jn][hh * 2 + 1] + b1, 0.f);
            g_HIDp[((((size_t)mb * 16 + kcH) * 4 + mt) * 32 + (rr * 4 + cc)) * 4
                   + hh + regH_base] = pk(v0, v1);
        }
    }
}

// =================== head GEMM 2: logits = hid @ Wp2 + bp2 ===================
__global__ __launch_bounds__(256) void k_logitsb(const float* __restrict__ bp2,
                                                 float* __restrict__ out)
{
    extern __shared__ uint4 sm[];
    const int tid = threadIdx.x, wid = tid >> 5, lane = tid & 31;
    const int mt = wid & 3, s = wid >> 2;
    const int rr = lane >> 2, cc = lane & 3;
    const int nb = blockIdx.x, mb = blockIdx.y;
    float acc[4][4] = {};
    const uint4* A4 = (const uint4*)g_HIDp + (size_t)mb * 16 * 128;
    const uint4* B4 = (const uint4*)g_Wp2p + (size_t)nb * 16 * 128;

    auto loadst = [&](int it) {
        if (it < 4) {
            uint4* dst = sm + (it & 3) * 1024;
            const uint4* a = A4 + (size_t)it * 512;
            const uint4* b = B4 + (size_t)it * 512;
            cp16(&dst[tid],             &a[tid]);
            cp16(&dst[tid + 256],       &a[tid + 256]);
            cp16(&dst[512 + tid],       &b[tid]);
            cp16(&dst[512 + tid + 256], &b[tid + 256]);
        }
        cp_commit();
    };
    loadst(0); loadst(1); loadst(2);
    for (int it = 0; it < 4; it++) {
        cp_wait2(); __syncthreads();
        loadst(it + 3);
        const uint4* SA = sm + (it & 3) * 1024;
        const uint2* SB = (const uint2*)(SA + 512);
#pragma unroll
        for (int kcl = 0; kcl < 4; kcl++) {
            uint4 a = SA[(kcl * 4 + mt) * 32 + lane];
#pragma unroll
            for (int jn = 0; jn < 4; jn++) {
                uint2 b = SB[(kcl * 8 + s * 4 + jn) * 32 + lane];
                mmabf(acc[jn], a, b);
            }
        }
    }
#pragma unroll
    for (int jn = 0; jn < 4; jn++) {
        int n = nb * 64 + (s * 4 + jn) * 8 + cc * 2;
        if (n < NANS) {
            float b0 = bp2[n], b1 = bp2[n + 1];
#pragma unroll
            for (int hh = 0; hh < 2; hh++) {
                int m = mb * 64 + mt * 16 + rr + hh * 8;
                float* o = out + (size_t)m * NANS + n;
                o[0] = acc[jn][hh * 2 + 0] + b0;
                o[1] = acc[jn][hh * 2 + 1] + b1;
            }
        }
    }
}

// ---------------- softmax ------------------------------------------------------
__global__ __launch_bounds__(256) void k_softmax(float* __restrict__ out)
{
    __shared__ float red[256];
    const int tid = threadIdx.x;
    float* p = out + (size_t)blockIdx.x * NANS;
    float v[4];
    float mx = -1e30f;
#pragma unroll
    for (int i = 0; i < 4; i++) {
        int n = tid + i * 256;
        v[i] = (n < NANS) ? p[n] : -1e30f;
        mx = fmaxf(mx, v[i]);
    }
    red[tid] = mx; __syncthreads();
    for (int s = 128; s > 0; s >>= 1) {
        if (tid < s) red[tid] = fmaxf(red[tid], red[tid + s]);
        __syncthreads();
    }
    mx = red[0]; __syncthreads();
    float sum = 0.f;
#pragma unroll
    for (int i = 0; i < 4; i++) {
        int n = tid + i * 256;
        if (n < NANS) { v[i] = expf(v[i] - mx); sum += v[i]; }
    }
    red[tid] = sum; __syncthreads();
    for (int s = 128; s > 0; s >>= 1) {
        if (tid < s) red[tid] += red[tid + s];
        __syncthreads();
    }
    float inv = 1.f / red[0];
#pragma unroll
    for (int i = 0; i < 4; i++) {
        int n = tid + i * 256;
        if (n < NANS) p[n] = v[i] * inv;
    }
}

// ---------------- launch ------------------------------------------------------
extern "C" void kernel_launch(void* const* d_in, const int* in_sizes, int n_in,
                              void* d_out, int out_size)
{
    const float* data1 = (const float*)d_in[0];
    const float* data2 = (const float*)d_in[1];
    const float* W_ih1 = (const float*)d_in[2];
    const float* W_hh1 = (const float*)d_in[3];
    const float* b1    = (const float*)d_in[4];
    const float* W_ih2 = (const float*)d_in[5];
    const float* W_hh2 = (const float*)d_in[6];
    const float* b2    = (const float*)d_in[7];
    const float* Wp1   = (const float*)d_in[8];
    const float* bp1   = (const float*)d_in[9];
    const float* Wp2   = (const float*)d_in[10];
    const float* bp2   = (const float*)d_in[11];
    float* out = (float*)d_out;

    static bool attr_done = false;
    if (!attr_done) {
        cudaFuncSetAttribute(k_xprojb,  cudaFuncAttributeMaxDynamicSharedMemorySize, 65536);
        cudaFuncSetAttribute(k_mlp1b,   cudaFuncAttributeMaxDynamicSharedMemorySize, 65536);
        cudaFuncSetAttribute(k_logitsb, cudaFuncAttributeMaxDynamicSharedMemorySize, 65536);
        cudaFuncSetAttribute(k_recur,   cudaFuncAttributeMaxDynamicSharedMemorySize, 215040);
        attr_done = true;
    }

    k_init_state<<<128, 256>>>();
    k_pack_all<<<dim3(1024, 6), 256>>>(W_hh1, W_ih2, W_hh2, data1, data2,
                                       W_ih1, Wp1, Wp2);
    k_xprojb<<<dim3(64, 128), 256, 65536>>>(b1);
    k_recur<<<128, 256, 215040>>>(b2);
    k_mlp1b<<<dim3(4, 128), 256, 65536>>>(bp1);
    k_logitsb<<<dim3(16, 128), 256, 65536>>>(bp2, out);
    k_softmax<<<BT, 256>>>(out);
}

// round 10
// speedup vs baseline: 1.8639x; 1.3374x over previous
#include <cuda_runtime.h>
#include <cuda_bf16.h>
#include <cstdint>
#include <math.h>

#define NB   64
#define NT   128
#define BT   8192
#define H    1024
#define DIN  2048
#define G4   4096
#define NH1  256
#define NANS 1000
#define NCTA 128u

// ---------------- device scratch ----------------
__device__ float g_X1[(size_t)BT * G4];          // [t][b][4H] (includes +b1)
__device__ unsigned g_bar;
// h in bf16 A-fragment layout: [kc(64)][mt(4)][lane(32)][reg(4)] u32
__device__ __align__(16) uint32_t g_h1p[2][32768];
__device__ __align__(16) uint32_t g_h2p[2][32768];
// step weights, B-fragment layout: [bx(128)][kc][g(4)][lane(32)] uint2
__device__ __align__(16) uint32_t g_W1p[128 * 64 * 4 * 32 * 2];     // 8 MB
__device__ __align__(16) uint32_t g_W2p[128 * 128 * 4 * 32 * 2];    // 16 MB
// xproj operands
__device__ __align__(16) uint32_t g_Ax[(size_t)128 * 128 * 4 * 32 * 4];  // 32 MB
__device__ __align__(16) uint32_t g_Wx[(size_t)64 * 128 * 8 * 32 * 2];   // 16 MB
// head: lstm_out bf16 A-frag [mb(128)][kc(64)][mt(4)][lane(32)][reg(4)]
__device__ __align__(16) uint32_t g_LOp[(size_t)128 * 64 * 4 * 32 * 4];  // 16 MB
// hid bf16 A-frag [mb(128)][kc(16)][mt][lane][reg]
__device__ __align__(16) uint32_t g_HIDp[(size_t)128 * 16 * 4 * 32 * 4]; // 4 MB
__device__ __align__(16) uint32_t g_Wp1p[4 * 64 * 8 * 32 * 2];
__device__ __align__(16) uint32_t g_Wp2p[16 * 16 * 8 * 32 * 2];

// fast activations
__device__ __forceinline__ float fsig(float x) {
    return __fdividef(1.f, 1.f + __expf(-x));
}
__device__ __forceinline__ float ftanh_(float x) {
    return fmaf(2.f, fsig(2.f * x), -1.f);
}
__device__ __forceinline__ uint32_t pk(float x, float y) {
    __nv_bfloat162 v = __floats2bfloat162_rn(x, y);
    return *reinterpret_cast<uint32_t*>(&v);
}
__device__ __forceinline__ void mmabf(float c[4], uint4 a, uint2 b) {
    asm volatile(
        "mma.sync.aligned.m16n8k16.row.col.f32.bf16.bf16.f32 "
        "{%0,%1,%2,%3},{%4,%5,%6,%7},{%8,%9},{%0,%1,%2,%3};"
        : "+f"(c[0]), "+f"(c[1]), "+f"(c[2]), "+f"(c[3])
        : "r"(a.x), "r"(a.y), "r"(a.z), "r"(a.w), "r"(b.x), "r"(b.y));
}
__device__ __forceinline__ void cp16(void* smem, const void* g) {
    uint32_t s = (uint32_t)__cvta_generic_to_shared(smem);
    asm volatile("cp.async.cg.shared.global [%0], [%1], 16;" :: "r"(s), "l"(g));
}
__device__ __forceinline__ void cp_commit() { asm volatile("cp.async.commit_group;"); }
__device__ __forceinline__ void cp_wait2()  { asm volatile("cp.async.wait_group 2;"); }
__device__ __forceinline__ void cp_wait0()  { asm volatile("cp.async.wait_group 0;"); }

// global barrier: release-arrive + acquire-poll
__device__ __forceinline__ void gbar(unsigned target) {
    __syncthreads();
    if (threadIdx.x == 0) {
        unsigned* bp = &g_bar;
        asm volatile("red.release.gpu.global.add.u32 [%0], %1;"
                     :: "l"(bp), "r"(1u) : "memory");
        unsigned v;
        do {
            asm volatile("ld.acquire.gpu.global.u32 %0, [%1];"
                         : "=r"(v) : "l"(bp) : "memory");
        } while (v < target);
    }
    __syncthreads();
}

// ---------------- init ----------------
__global__ void k_init_state() {
    int i = blockIdx.x * blockDim.x + threadIdx.x;
    if (i == 0) g_bar = 0u;
    if (i < 32768) { g_h1p[0][i] = 0u; g_h2p[0][i] = 0u; }
}

// ---------------- unified pack kernel (job = blockIdx.y) ---------------------
__global__ void k_pack_all(
    const float* __restrict__ W_hh1, const float* __restrict__ W_ih2,
    const float* __restrict__ W_hh2, const float* __restrict__ d1,
    const float* __restrict__ d2,   const float* __restrict__ W_ih1,
    const float* __restrict__ Wp1,  const float* __restrict__ Wp2)
{
    const int job = blockIdx.y;
    const int gid = blockIdx.x * blockDim.x + threadIdx.x;
    const int stride = gridDim.x * blockDim.x;

    if (job == 0) {
        uint2* out = (uint2*)g_W1p;
        for (int idx = gid; idx < 128 * 64 * 4 * 32; idx += stride) {
            int lane = idx & 31;
            int t1 = idx >> 5;  int g = t1 & 3;
            int t2 = t1 >> 2;   int kc = t2 & 63; int bx = t2 >> 6;
            int rr = lane >> 2, cc = lane & 3;
            const float* p = W_hh1 + (size_t)(g * H + bx * 8 + rr) * H + kc * 16 + cc * 2;
            uint2 v; v.x = pk(p[0], p[1]); v.y = pk(p[8], p[9]);
            out[idx] = v;
        }
    } else if (job == 1) {
        uint2* out = (uint2*)g_W2p;
        for (int idx = gid; idx < 128 * 128 * 4 * 32; idx += stride) {
            int lane = idx & 31;
            int t1 = idx >> 5;  int g = t1 & 3;
            int t2 = t1 >> 2;   int kc = t2 & 127; int bx = t2 >> 7;
            int rr = lane >> 2, cc = lane & 3;
            int row = g * H + bx * 8 + rr;
            const float* W = W_ih2; int k0 = kc * 16 + cc * 2;
            if (kc >= 64) { W = W_hh2; k0 -= 1024; }
            const float* p = W + (size_t)row * H + k0;
            uint2 v; v.x = pk(p[0], p[1]); v.y = pk(p[8], p[9]);
            out[idx] = v;
        }
    } else if (job == 2) {
        uint4* out = (uint4*)g_Ax;
        for (int idx = gid; idx < 128 * 128 * 4 * 32; idx += stride) {
            int lane = idx & 31;
            int t1 = idx >> 5;
            int mt = t1 & 3; t1 >>= 2;
            int kc = t1 & 127;
            int mb = t1 >> 7;
            int rr = lane >> 2, cc = lane & 3;
            int r0 = mb * 64 + mt * 16 + rr, r1 = r0 + 8;
            int k0 = kc * 16 + cc * 2;
            const float *s0, *s1;
            if (k0 < 1024) { s0 = d1 + (size_t)r0 * 1024 + k0;        s1 = d1 + (size_t)r1 * 1024 + k0; }
            else           { s0 = d2 + (size_t)r0 * 1024 + k0 - 1024; s1 = d2 + (size_t)r1 * 1024 + k0 - 1024; }
            uint4 v;
            v.x = pk(s0[0], s0[1]);
            v.y = pk(s1[0], s1[1]);
            v.z = pk(s0[8], s0[9]);
            v.w = pk(s1[8], s1[9]);
            out[idx] = v;
        }
    } else if (job == 3) {
        uint2* out = (uint2*)g_Wx;
        for (int idx = gid; idx < 64 * 128 * 8 * 32; idx += stride) {
            int lane = idx & 31;
            int t1 = idx >> 5;
            int c = t1 & 7; t1 >>= 3;
            int kc = t1 & 127;
            int nb = t1 >> 7;
            int rr = lane >> 2, cc = lane & 3;
            const float* p = W_ih1 + (size_t)(nb * 64 + c * 8 + rr) * DIN + kc * 16 + cc * 2;
            uint2 v; v.x = pk(p[0], p[1]); v.y = pk(p[8], p[9]);
            out[idx] = v;
        }
    } else if (job == 4) {
        uint2* out = (uint2*)g_Wp1p;
        for (int idx = gid; idx < 4 * 64 * 8 * 32; idx += stride) {
            int lane = idx & 31;
            int t1 = idx >> 5;
            int c = t1 & 7; t1 >>= 3;
            int kc = t1 & 63;
            int nb = t1 >> 6;
            int rr = lane >> 2, cc = lane & 3;
            int n  = nb * 64 + c * 8 + rr;
            int k0 = kc * 16 + cc * 2;
            uint2 v;
            v.x = pk(Wp1[(size_t)k0 * NH1 + n],       Wp1[(size_t)(k0 + 1) * NH1 + n]);
            v.y = pk(Wp1[(size_t)(k0 + 8) * NH1 + n], Wp1[(size_t)(k0 + 9) * NH1 + n]);
            out[idx] = v;
        }
    } else {
        uint2* out = (uint2*)g_Wp2p;
        for (int idx = gid; idx < 16 * 16 * 8 * 32; idx += stride) {
            int lane = idx & 31;
            int t1 = idx >> 5;
            int c = t1 & 7; t1 >>= 3;
            int kc = t1 & 15;
            int nb = t1 >> 4;
            int rr = lane >> 2, cc = lane & 3;
            int n  = nb * 64 + c * 8 + rr;
            int k0 = kc * 16 + cc * 2;
            float a0 = 0.f, a1 = 0.f, b0 = 0.f, b1 = 0.f;
            if (n < NANS) {
                a0 = Wp2[(size_t)k0 * NANS + n];       a1 = Wp2[(size_t)(k0 + 1) * NANS + n];
                b0 = Wp2[(size_t)(k0 + 8) * NANS + n]; b1 = Wp2[(size_t)(k0 + 9) * NANS + n];
            }
            uint2 v; v.x = pk(a0, a1); v.y = pk(b0, b1);
            out[idx] = v;
        }
    }
}

// =================== xproj: bf16 mma, pre-packed fragments ==================
__global__ __launch_bounds__(256) void k_xprojb(const float* __restrict__ bias)
{
    extern __shared__ uint4 sm[];
    const int tid = threadIdx.x, wid = tid >> 5, lane = tid & 31;
    const int mt = wid & 3, s = wid >> 2;
    const int rr = lane >> 2, cc = lane & 3;
    const int nb = blockIdx.x, mb = blockIdx.y;
    float acc[4][4] = {};
    const uint4* A4 = (const uint4*)g_Ax + (size_t)mb * 128 * 128;
    const uint4* B4 = (const uint4*)g_Wx + (size_t)nb * 128 * 128;

    auto loadst = [&](int it) {
        if (it < 32) {
            uint4* dst = sm + (it & 3) * 1024;
            const uint4* a = A4 + (size_t)it * 512;
            const uint4* b = B4 + (size_t)it * 512;
            cp16(&dst[tid],             &a[tid]);
            cp16(&dst[tid + 256],       &a[tid + 256]);
            cp16(&dst[512 + tid],       &b[tid]);
            cp16(&dst[512 + tid + 256], &b[tid + 256]);
        }
        cp_commit();
    };
    loadst(0); loadst(1); loadst(2);
    for (int it = 0; it < 32; it++) {
        cp_wait2(); __syncthreads();
        loadst(it + 3);
        const uint4* SA = sm + (it & 3) * 1024;
        const uint2* SB = (const uint2*)(SA + 512);
#pragma unroll
        for (int kcl = 0; kcl < 4; kcl++) {
            uint4 a = SA[(kcl * 4 + mt) * 32 + lane];
#pragma unroll
            for (int jn = 0; jn < 4; jn++) {
                uint2 b = SB[(kcl * 8 + s * 4 + jn) * 32 + lane];
                mmabf(acc[jn], a, b);
            }
        }
    }
#pragma unroll
    for (int jn = 0; jn < 4; jn++) {
        int col = nb * 64 + (s * 4 + jn) * 8 + cc * 2;
        float b0 = bias[col], b1 = bias[col + 1];
#pragma unroll
        for (int hh = 0; hh < 2; hh++) {
            int m = mb * 64 + mt * 16 + rr + hh * 8;
            int tt = m & 127, bb = m >> 7;
            float* o = g_X1 + ((size_t)tt * NB + bb) * G4 + col;
            o[0] = acc[jn][hh * 2 + 0] + b0;
            o[1] = acc[jn][hh * 2 + 1] + b1;
        }
    }
}

// =================== persistent recurrence kernel ===========================
// MERGED-PHASE: per step one combined GEMM computes L2(t) gates (K=2048) AND
// L1(t+1) gates (K=1024); h1_t A-fragments feed both (8 MMAs/frag). One reduce
// complex + one gbar per step. c-state in regs, X1 via cp.async, fast
// activations, depth-8 A ring (occupancy pinned by smem -> regs free).
// smem (uint4): Gs[0,576) Gs2[576,1152) W1[1152,5248) W2[5248,13440)
//               XS[13440,14016)   total 224256 B
__global__ __launch_bounds__(256) void k_recur(const float* __restrict__ b2)
{
    extern __shared__ uint4 sm[];
    const int tid = threadIdx.x, wid = tid >> 5, lane = tid & 31;
    const int mt = wid & 3, s = wid >> 2;
    const int rr = lane >> 2, cc = lane & 3;
    const int bx = blockIdx.x;
    float* Gs   = (float*)sm;                         // L2 gate partials
    float* Gs2  = (float*)(sm + 576);                 // L1-next gate partials
    const uint2* Wsm1 = (const uint2*)(sm + 1152);
    const uint2* Wsm2 = (const uint2*)(sm + 5248);
    float* XSf  = (float*)(sm + 13440);               // [64][36]
    const int j = bx * 8 + cc * 2;
    const int j0 = bx * 8;
    const int fragoff = mt * 32 + lane;

    // weights -> smem (one time)
    {
        const uint4* w1 = (const uint4*)g_W1p + (size_t)bx * 4096;
        for (int i = tid; i < 4096; i += 256) cp16(&sm[1152 + i], &w1[i]);
        const uint4* w2 = (const uint4*)g_W2p + (size_t)bx * 8192;
        for (int i = tid; i < 8192; i += 256) cp16(&sm[5248 + i], &w2[i]);
        cp_commit(); cp_wait0(); __syncthreads();
    }

    float2 b2i = make_float2(b2[j],         b2[j + 1]);
    float2 b2f = make_float2(b2[H + j],     b2[H + j + 1]);
    float2 b2g = make_float2(b2[2 * H + j], b2[2 * H + j + 1]);
    float2 b2o = make_float2(b2[3 * H + j], b2[3 * H + j + 1]);

    const int em0 = mt * 16 + rr, em1 = em0 + 8;
    float2 h1res[2];
    float2 c1v[2] = { make_float2(0.f, 0.f), make_float2(0.f, 0.f) };
    float2 c2v[2] = { make_float2(0.f, 0.f), make_float2(0.f, 0.f) };

    auto stageX = [&](int tt) {
        const float* Xt = g_X1 + (size_t)tt * NB * G4;
#pragma unroll
        for (int e = 0; e < 2; e++) {
            int i = tid + e * 256;
            int m = i >> 3, seg = i & 7;
            int g = seg >> 1, half = seg & 1;
            cp16(&XSf[m * 36 + g * 8 + half * 4],
                 Xt + (size_t)m * G4 + g * H + j0 + half * 4);
        }
        cp_commit();
    };

    // ---------------- prologue: L1(0) = cell(X1[0]) only (h1_{-1}=0) --------
    {
        stageX(0);
        cp_wait0(); __syncthreads();
        if (s == 1) {
#pragma unroll
            for (int hh = 0; hh < 2; hh++) {
                int m = hh ? em1 : em0;
                const float* xm = &XSf[m * 36];
                float gi0 = xm[     cc*2], gi1 = xm[     cc*2 + 1];
                float gg0 = xm[16 + cc*2], gg1 = xm[16 + cc*2 + 1];
                float go0 = xm[24 + cc*2], go1 = xm[24 + cc*2 + 1];
                float cn0 = fsig(gi0) * ftanh_(gg0);
                float cn1 = fsig(gi1) * ftanh_(gg1);
                c1v[hh] = make_float2(cn0, cn1);
                float h0 = fsig(go0) * ftanh_(cn0);
                float h1 = fsig(go1) * ftanh_(cn1);
                h1res[hh] = make_float2(h0, h1);
                g_h1p[1][((((bx >> 1) * 4 + mt) * 32 + lane) * 4)
                         + hh + 2 * (bx & 1)] = pk(h0, h1);
            }
        }
        gbar(NCTA);
    }

    // ---------------- main loop: phase(t) = L2(t) + L1(t+1) -----------------
    for (int t = 0; t < NT - 1; t++) {
        const uint4* Aw1 = (const uint4*)(g_h1p[(t + 1) & 1]) + (s * 32) * 128 + fragoff;
        const uint4* Aw2 = (const uint4*)(g_h2p[t & 1])       + (s * 32) * 128 + fragoff;
        float accL2[4][4] = {};
        float accL1[4][4] = {};

        stageX(t + 1);

        uint4 ring[8];
#pragma unroll
        for (int p = 0; p < 8; p++) ring[p] = __ldcg(Aw1 + p * 128);
        // h1_t half: feeds BOTH gate sets (8 MMAs per fragment)
#pragma unroll 8
        for (int i = 0; i < 32; i++) {
            uint4 a = ring[i & 7];
            int r = i + 8;
            ring[i & 7] = (r < 32) ? __ldcg(Aw1 + r * 128)
                                   : __ldcg(Aw2 + (r - 32) * 128);
            const int kc = s * 32 + i;
#pragma unroll
            for (int g = 0; g < 4; g++)
                mmabf(accL2[g], a, Wsm2[(kc * 4 + g) * 32 + lane]);
#pragma unroll
            for (int g = 0; g < 4; g++)
                mmabf(accL1[g], a, Wsm1[(kc * 4 + g) * 32 + lane]);
        }
        // h2_{t-1} half: L2 only
#pragma unroll 8
        for (int i = 0; i < 32; i++) {
            uint4 a = ring[i & 7];
            if (i + 8 < 32) ring[i & 7] = __ldcg(Aw2 + (i + 8) * 128);
            const int kc = 64 + s * 32 + i;
#pragma unroll
            for (int g = 0; g < 4; g++)
                mmabf(accL2[g], a, Wsm2[(kc * 4 + g) * 32 + lane]);
        }

        cp_wait0();
        __syncthreads();
        if (s == 0) {
#pragma unroll
            for (int g = 0; g < 4; g++) {
                Gs [em0 * 36 + g * 8 + cc * 2]     = accL2[g][0];
                Gs [em0 * 36 + g * 8 + cc * 2 + 1] = accL2[g][1];
                Gs [em1 * 36 + g * 8 + cc * 2]     = accL2[g][2];
                Gs [em1 * 36 + g * 8 + cc * 2 + 1] = accL2[g][3];
                Gs2[em0 * 36 + g * 8 + cc * 2]     = accL1[g][0];
                Gs2[em0 * 36 + g * 8 + cc * 2 + 1] = accL1[g][1];
                Gs2[em1 * 36 + g * 8 + cc * 2]     = accL1[g][2];
                Gs2[em1 * 36 + g * 8 + cc * 2 + 1] = accL1[g][3];
            }
        }
        __syncthreads();
        if (s == 1) {
            // ---- epilogue L2(t): uses h1res from L1(t) ----
#pragma unroll
            for (int hh = 0; hh < 2; hh++) {
                int m = hh ? em1 : em0;
                float gi0 = accL2[0][hh*2]   + Gs[m*36 +      cc*2]     + b2i.x;
                float gi1 = accL2[0][hh*2+1] + Gs[m*36 +      cc*2 + 1] + b2i.y;
                float gf0 = accL2[1][hh*2]   + Gs[m*36 +  8 + cc*2]     + b2f.x;
                float gf1 = accL2[1][hh*2+1] + Gs[m*36 +  8 + cc*2 + 1] + b2f.y;
                float gg0 = accL2[2][hh*2]   + Gs[m*36 + 16 + cc*2]     + b2g.x;
                float gg1 = accL2[2][hh*2+1] + Gs[m*36 + 16 + cc*2 + 1] + b2g.y;
                float go0 = accL2[3][hh*2]   + Gs[m*36 + 24 + cc*2]     + b2o.x;
                float go1 = accL2[3][hh*2+1] + Gs[m*36 + 24 + cc*2 + 1] + b2o.y;
                float cn0 = fsig(gf0) * c2v[hh].x + fsig(gi0) * ftanh_(gg0);
                float cn1 = fsig(gf1) * c2v[hh].y + fsig(gi1) * ftanh_(gg1);
                c2v[hh] = make_float2(cn0, cn1);
                float h0 = fsig(go0) * ftanh_(cn0);
                float h1 = fsig(go1) * ftanh_(cn1);
                g_h2p[(t + 1) & 1][((((bx >> 1) * 4 + mt) * 32 + lane) * 4)
                                   + hh + 2 * (bx & 1)] = pk(h0, h1);
                int mbL   = m * 2 + (t >> 6);
                int kcL   = bx >> 1;
                int mtL   = (t >> 4) & 3;
                int laneL = (t & 7) * 4 + cc;
                int regL  = ((t >> 3) & 1) + 2 * (bx & 1);
                g_LOp[((((size_t)mbL * 64 + kcL) * 4 + mtL) * 32 + laneL) * 4 + regL]
                    = pk(h0 + h1res[hh].x, h1 + h1res[hh].y);
            }
            // ---- epilogue L1(t+1): overwrites h1res, writes h1p[(t+2)&1] ----
#pragma unroll
            for (int hh = 0; hh < 2; hh++) {
                int m = hh ? em1 : em0;
                const float* xm = &XSf[m * 36];
                float gi0 = accL1[0][hh*2]   + Gs2[m*36 +      cc*2]     + xm[     cc*2];
                float gi1 = accL1[0][hh*2+1] + Gs2[m*36 +      cc*2 + 1] + xm[     cc*2 + 1];
                float gf0 = accL1[1][hh*2]   + Gs2[m*36 +  8 + cc*2]     + xm[ 8 + cc*2];
                float gf1 = accL1[1][hh*2+1] + Gs2[m*36 +  8 + cc*2 + 1] + xm[ 8 + cc*2 + 1];
                float gg0 = accL1[2][hh*2]   + Gs2[m*36 + 16 + cc*2]     + xm[16 + cc*2];
                float gg1 = accL1[2][hh*2+1] + Gs2[m*36 + 16 + cc*2 + 1] + xm[16 + cc*2 + 1];
                float go0 = accL1[3][hh*2]   + Gs2[m*36 + 24 + cc*2]     + xm[24 + cc*2];
                float go1 = accL1[3][hh*2+1] + Gs2[m*36 + 24 + cc*2 + 1] + xm[24 + cc*2 + 1];
                float cn0 = fsig(gf0) * c1v[hh].x + fsig(gi0) * ftanh_(gg0);
                float cn1 = fsig(gf1) * c1v[hh].y + fsig(gi1) * ftanh_(gg1);
                c1v[hh] = make_float2(cn0, cn1);
                float h0 = fsig(go0) * ftanh_(cn0);
                float h1 = fsig(go1) * ftanh_(cn1);
                h1res[hh] = make_float2(h0, h1);
                g_h1p[(t + 2) & 1][((((bx >> 1) * 4 + mt) * 32 + lane) * 4)
                                   + hh + 2 * (bx & 1)] = pk(h0, h1);
            }
        }
        gbar((unsigned)(t + 2) * NCTA);
    }

    // ---------------- tail: L2(127) only ------------------------------------
    {
        const int t = NT - 1;  // 127
        const uint4* Aw1 = (const uint4*)(g_h1p[(t + 1) & 1]) + (s * 32) * 128 + fragoff;
        const uint4* Aw2 = (const uint4*)(g_h2p[t & 1])       + (s * 32) * 128 + fragoff;
        float accL2[4][4] = {};
        uint4 ring[8];
#pragma unroll
        for (int p = 0; p < 8; p++) ring[p] = __ldcg(Aw1 + p * 128);
#pragma unroll 8
        for (int i = 0; i < 32; i++) {
            uint4 a = ring[i & 7];
            int r = i + 8;
            ring[i & 7] = (r < 32) ? __ldcg(Aw1 + r * 128)
                                   : __ldcg(Aw2 + (r - 32) * 128);
            const int kc = s * 32 + i;
#pragma unroll
            for (int g = 0; g < 4; g++)
                mmabf(accL2[g], a, Wsm2[(kc * 4 + g) * 32 + lane]);
        }
#pragma unroll 8
        for (int i = 0; i < 32; i++) {
            uint4 a = ring[i & 7];
            if (i + 8 < 32) ring[i & 7] = __ldcg(Aw2 + (i + 8) * 128);
            const int kc = 64 + s * 32 + i;
#pragma unroll
            for (int g = 0; g < 4; g++)
                mmabf(accL2[g], a, Wsm2[(kc * 4 + g) * 32 + lane]);
        }
        __syncthreads();
        if (s == 0) {
#pragma unroll
            for (int g = 0; g < 4; g++) {
                Gs[em0 * 36 + g * 8 + cc * 2]     = accL2[g][0];
                Gs[em0 * 36 + g * 8 + cc * 2 + 1] = accL2[g][1];
                Gs[em1 * 36 + g * 8 + cc * 2]     = accL2[g][2];
                Gs[em1 * 36 + g * 8 + cc * 2 + 1] = accL2[g][3];
            }
        }
        __syncthreads();
        if (s == 1) {
#pragma unroll
            for (int hh = 0; hh < 2; hh++) {
                int m = hh ? em1 : em0;
                float gi0 = accL2[0][hh*2]   + Gs[m*36 +      cc*2]     + b2i.x;
                float gi1 = accL2[0][hh*2+1] + Gs[m*36 +      cc*2 + 1] + b2i.y;
                float gf0 = accL2[1][hh*2]   + Gs[m*36 +  8 + cc*2]     + b2f.x;
                float gf1 = accL2[1][hh*2+1] + Gs[m*36 +  8 + cc*2 + 1] + b2f.y;
                float gg0 = accL2[2][hh*2]   + Gs[m*36 + 16 + cc*2]     + b2g.x;
                float gg1 = accL2[2][hh*2+1] + Gs[m*36 + 16 + cc*2 + 1] + b2g.y;
                float go0 = accL2[3][hh*2]   + Gs[m*36 + 24 + cc*2]     + b2o.x;
                float go1 = accL2[3][hh*2+1] + Gs[m*36 + 24 + cc*2 + 1] + b2o.y;
                float cn0 = fsig(gf0) * c2v[hh].x + fsig(gi0) * ftanh_(gg0);
                float cn1 = fsig(gf1) * c2v[hh].y + fsig(gi1) * ftanh_(gg1);
                float h0 = fsig(go0) * ftanh_(cn0);
                float h1 = fsig(go1) * ftanh_(cn1);
                int mbL   = m * 2 + (t >> 6);
                int kcL   = bx >> 1;
                int mtL   = (t >> 4) & 3;
                int laneL = (t & 7) * 4 + cc;
                int regL  = ((t >> 3) & 1) + 2 * (bx & 1);
                g_LOp[((((size_t)mbL * 64 + kcL) * 4 + mtL) * 32 + laneL) * 4 + regL]
                    = pk(h0 + h1res[hh].x, h1 + h1res[hh].y);
            }
        }
    }
}

// =================== head GEMM 1: hid = relu(LO @ Wp1 + bp1) =================
__global__ __launch_bounds__(256) void k_mlp1b(const float* __restrict__ bp1)
{
    extern __shared__ uint4 sm[];
    const int tid = threadIdx.x, wid = tid >> 5, lane = tid & 31;
    const int mt = wid & 3, s = wid >> 2;
    const int rr = lane >> 2, cc = lane & 3;
    const int nb = blockIdx.x, mb = blockIdx.y;
    float acc[4][4] = {};
    const uint4* A4 = (const uint4*)g_LOp + (size_t)mb * 64 * 128;
    const uint4* B4 = (const uint4*)g_Wp1p + (size_t)nb * 64 * 128;

    auto loadst = [&](int it) {
        if (it < 16) {
            uint4* dst = sm + (it & 3) * 1024;
            const uint4* a = A4 + (size_t)it * 512;
            const uint4* b = B4 + (size_t)it * 512;
            cp16(&dst[tid],             &a[tid]);
            cp16(&dst[tid + 256],       &a[tid + 256]);
            cp16(&dst[512 + tid],       &b[tid]);
            cp16(&dst[512 + tid + 256], &b[tid + 256]);
        }
        cp_commit();
    };
    loadst(0); loadst(1); loadst(2);
    for (int it = 0; it < 16; it++) {
        cp_wait2(); __syncthreads();
        loadst(it + 3);
        const uint4* SA = sm + (it & 3) * 1024;
        const uint2* SB = (const uint2*)(SA + 512);
#pragma unroll
        for (int kcl = 0; kcl < 4; kcl++) {
            uint4 a = SA[(kcl * 4 + mt) * 32 + lane];
#pragma unroll
            for (int jn = 0; jn < 4; jn++) {
                uint2 b = SB[(kcl * 8 + s * 4 + jn) * 32 + lane];
                mmabf(acc[jn], a, b);
            }
        }
    }
#pragma unroll
    for (int jn = 0; jn < 4; jn++) {
        int c8  = s * 4 + jn;
        int col = nb * 64 + c8 * 8 + cc * 2;
        float b0 = bp1[col], b1 = bp1[col + 1];
        int kcH = nb * 4 + (c8 >> 1);
        int regH_base = 2 * (c8 & 1);
#pragma unroll
        for (int hh = 0; hh < 2; hh++) {
            float v0 = fmaxf(acc[jn][hh * 2 + 0] + b0, 0.f);
            float v1 = fmaxf(acc[jn][hh * 2 + 1] + b1, 0.f);
            g_HIDp[((((size_t)mb * 16 + kcH) * 4 + mt) * 32 + (rr * 4 + cc)) * 4
                   + hh + regH_base] = pk(v0, v1);
        }
    }
}

// =================== head GEMM 2: logits = hid @ Wp2 + bp2 ===================
__global__ __launch_bounds__(256) void k_logitsb(const float* __restrict__ bp2,
                                                 float* __restrict__ out)
{
    extern __shared__ uint4 sm[];
    const int tid = threadIdx.x, wid = tid >> 5, lane = tid & 31;
    const int mt = wid & 3, s = wid >> 2;
    const int rr = lane >> 2, cc = lane & 3;
    const int nb = blockIdx.x, mb = blockIdx.y;
    float acc[4][4] = {};
    const uint4* A4 = (const uint4*)g_HIDp + (size_t)mb * 16 * 128;
    const uint4* B4 = (const uint4*)g_Wp2p + (size_t)nb * 16 * 128;

    auto loadst = [&](int it) {
        if (it < 4) {
            uint4* dst = sm + (it & 3) * 1024;
            const uint4* a = A4 + (size_t)it * 512;
            const uint4* b = B4 + (size_t)it * 512;
            cp16(&dst[tid],             &a[tid]);
            cp16(&dst[tid + 256],       &a[tid + 256]);
            cp16(&dst[512 + tid],       &b[tid]);
            cp16(&dst[512 + tid + 256], &b[tid + 256]);
        }
        cp_commit();
    };
    loadst(0); loadst(1); loadst(2);
    for (int it = 0; it < 4; it++) {
        cp_wait2(); __syncthreads();
        loadst(it + 3);
        const uint4* SA = sm + (it & 3) * 1024;
        const uint2* SB = (const uint2*)(SA + 512);
#pragma unroll
        for (int kcl = 0; kcl < 4; kcl++) {
            uint4 a = SA[(kcl * 4 + mt) * 32 + lane];
#pragma unroll
            for (int jn = 0; jn < 4; jn++) {
                uint2 b = SB[(kcl * 8 + s * 4 + jn) * 32 + lane];
                mmabf(acc[jn], a, b);
            }
        }
    }
#pragma unroll
    for (int jn = 0; jn < 4; jn++) {
        int n = nb * 64 + (s * 4 + jn) * 8 + cc * 2;
        if (n < NANS) {
            float b0 = bp2[n], b1 = bp2[n + 1];
#pragma unroll
            for (int hh = 0; hh < 2; hh++) {
                int m = mb * 64 + mt * 16 + rr + hh * 8;
                float* o = out + (size_t)m * NANS + n;
                o[0] = acc[jn][hh * 2 + 0] + b0;
                o[1] = acc[jn][hh * 2 + 1] + b1;
            }
        }
    }
}

// ---------------- softmax ------------------------------------------------------
__global__ __launch_bounds__(256) void k_softmax(float* __restrict__ out)
{
    __shared__ float red[256];
    const int tid = threadIdx.x;
    float* p = out + (size_t)blockIdx.x * NANS;
    float v[4];
    float mx = -1e30f;
#pragma unroll
    for (int i = 0; i < 4; i++) {
        int n = tid + i * 256;
        v[i] = (n < NANS) ? p[n] : -1e30f;
        mx = fmaxf(mx, v[i]);
    }
    red[tid] = mx; __syncthreads();
    for (int s = 128; s > 0; s >>= 1) {
        if (tid < s) red[tid] = fmaxf(red[tid], red[tid + s]);
        __syncthreads();
    }
    mx = red[0]; __syncthreads();
    float sum = 0.f;
#pragma unroll
    for (int i = 0; i < 4; i++) {
        int n = tid + i * 256;
        if (n < NANS) { v[i] = expf(v[i] - mx); sum += v[i]; }
    }
    red[tid] = sum; __syncthreads();
    for (int s = 128; s > 0; s >>= 1) {
        if (tid < s) red[tid] += red[tid + s];
        __syncthreads();
    }
    float inv = 1.f / red[0];
#pragma unroll
    for (int i = 0; i < 4; i++) {
        int n = tid + i * 256;
        if (n < NANS) p[n] = v[i] * inv;
    }
}

// ---------------- launch ------------------------------------------------------
extern "C" void kernel_launch(void* const* d_in, const int* in_sizes, int n_in,
                              void* d_out, int out_size)
{
    const float* data1 = (const float*)d_in[0];
    const float* data2 = (const float*)d_in[1];
    const float* W_ih1 = (const float*)d_in[2];
    const float* W_hh1 = (const float*)d_in[3];
    const float* b1    = (const float*)d_in[4];
    const float* W_ih2 = (const float*)d_in[5];
    const float* W_hh2 = (const float*)d_in[6];
    const float* b2    = (const float*)d_in[7];
    const float* Wp1   = (const float*)d_in[8];
    const float* bp1   = (const float*)d_in[9];
    const float* Wp2   = (const float*)d_in[10];
    const float* bp2   = (const float*)d_in[11];
    float* out = (float*)d_out;

    static bool attr_done = false;
    if (!attr_done) {
        cudaFuncSetAttribute(k_xprojb,  cudaFuncAttributeMaxDynamicSharedMemorySize, 65536);
        cudaFuncSetAttribute(k_mlp1b,   cudaFuncAttributeMaxDynamicSharedMemorySize, 65536);
        cudaFuncSetAttribute(k_logitsb, cudaFuncAttributeMaxDynamicSharedMemorySize, 65536);
        cudaFuncSetAttribute(k_recur,   cudaFuncAttributeMaxDynamicSharedMemorySize, 224256);
        attr_done = true;
    }

    k_init_state<<<128, 256>>>();
    k_pack_all<<<dim3(1024, 6), 256>>>(W_hh1, W_ih2, W_hh2, data1, data2,
                                       W_ih1, Wp1, Wp2);
    k_xprojb<<<dim3(64, 128), 256, 65536>>>(b1);
    k_recur<<<128, 256, 224256>>>(b2);
    k_mlp1b<<<dim3(4, 128), 256, 65536>>>(bp1);
    k_logitsb<<<dim3(16, 128), 256, 65536>>>(bp2, out);
    k_softmax<<<BT, 256>>>(out);
}

// round 11
// speedup vs baseline: 1.9648x; 1.0541x over previous
#include <cuda_runtime.h>
#include <cuda_bf16.h>
#include <cstdint>
#include <math.h>

#define NB   64
#define NT   128
#define BT   8192
#define H    1024
#define DIN  2048
#define G4   4096
#define NH1  256
#define NANS 1000
#define NCTA 128u

// ---------------- device scratch ----------------
__device__ float g_X1[(size_t)BT * G4];          // [t][b][4H] (includes +b1)
__device__ unsigned g_bar;
// h in bf16 A-fragment layout: [kc(64)][mt(4)][lane(32)][reg(4)] u32
__device__ __align__(16) uint32_t g_h1p[2][32768];
__device__ __align__(16) uint32_t g_h2p[2][32768];
// step weights, B-fragment layout: [bx(128)][kc][g(4)][lane(32)] uint2
__device__ __align__(16) uint32_t g_W1p[128 * 64 * 4 * 32 * 2];     // 8 MB
__device__ __align__(16) uint32_t g_W2p[128 * 128 * 4 * 32 * 2];    // 16 MB
// xproj operands
__device__ __align__(16) uint32_t g_Ax[(size_t)128 * 128 * 4 * 32 * 4];  // 32 MB
__device__ __align__(16) uint32_t g_Wx[(size_t)64 * 128 * 8 * 32 * 2];   // 16 MB
// head: lstm_out bf16 A-frag [mb(128)][kc(64)][mt(4)][lane(32)][reg(4)]
__device__ __align__(16) uint32_t g_LOp[(size_t)128 * 64 * 4 * 32 * 4];  // 16 MB
// hid bf16 A-frag [mb(128)][kc(16)][mt][lane][reg]
__device__ __align__(16) uint32_t g_HIDp[(size_t)128 * 16 * 4 * 32 * 4]; // 4 MB
__device__ __align__(16) uint32_t g_Wp1p[4 * 64 * 8 * 32 * 2];
__device__ __align__(16) uint32_t g_Wp2p[16 * 16 * 8 * 32 * 2];

// fast activations
__device__ __forceinline__ float fsig(float x) {
    return __fdividef(1.f, 1.f + __expf(-x));
}
__device__ __forceinline__ float ftanh_(float x) {
    return fmaf(2.f, fsig(2.f * x), -1.f);
}
__device__ __forceinline__ uint32_t pk(float x, float y) {
    __nv_bfloat162 v = __floats2bfloat162_rn(x, y);
    return *reinterpret_cast<uint32_t*>(&v);
}
__device__ __forceinline__ void mmabf(float c[4], uint4 a, uint2 b) {
    asm volatile(
        "mma.sync.aligned.m16n8k16.row.col.f32.bf16.bf16.f32 "
        "{%0,%1,%2,%3},{%4,%5,%6,%7},{%8,%9},{%0,%1,%2,%3};"
        : "+f"(c[0]), "+f"(c[1]), "+f"(c[2]), "+f"(c[3])
        : "r"(a.x), "r"(a.y), "r"(a.z), "r"(a.w), "r"(b.x), "r"(b.y));
}
__device__ __forceinline__ void cp16(void* smem, const void* g) {
    uint32_t s = (uint32_t)__cvta_generic_to_shared(smem);
    asm volatile("cp.async.cg.shared.global [%0], [%1], 16;" :: "r"(s), "l"(g));
}
__device__ __forceinline__ void cp_commit() { asm volatile("cp.async.commit_group;"); }
__device__ __forceinline__ void cp_wait2()  { asm volatile("cp.async.wait_group 2;"); }
__device__ __forceinline__ void cp_wait0()  { asm volatile("cp.async.wait_group 0;"); }

// global barrier: release-arrive + acquire-poll
__device__ __forceinline__ void gbar(unsigned target) {
    __syncthreads();
    if (threadIdx.x == 0) {
        unsigned* bp = &g_bar;
        asm volatile("red.release.gpu.global.add.u32 [%0], %1;"
                     :: "l"(bp), "r"(1u) : "memory");
        unsigned v;
        do {
            asm volatile("ld.acquire.gpu.global.u32 %0, [%1];"
                         : "=r"(v) : "l"(bp) : "memory");
        } while (v < target);
    }
    __syncthreads();
}

// ---------------- init ----------------
__global__ void k_init_state() {
    int i = blockIdx.x * blockDim.x + threadIdx.x;
    if (i == 0) g_bar = 0u;
    if (i < 32768) { g_h1p[0][i] = 0u; g_h2p[0][i] = 0u; }
}

// ---------------- unified pack kernel (job = blockIdx.y) ---------------------
__global__ void k_pack_all(
    const float* __restrict__ W_hh1, const float* __restrict__ W_ih2,
    const float* __restrict__ W_hh2, const float* __restrict__ d1,
    const float* __restrict__ d2,   const float* __restrict__ W_ih1,
    const float* __restrict__ Wp1,  const float* __restrict__ Wp2)
{
    const int job = blockIdx.y;
    const int gid = blockIdx.x * blockDim.x + threadIdx.x;
    const int stride = gridDim.x * blockDim.x;

    if (job == 0) {
        uint2* out = (uint2*)g_W1p;
        for (int idx = gid; idx < 128 * 64 * 4 * 32; idx += stride) {
            int lane = idx & 31;
            int t1 = idx >> 5;  int g = t1 & 3;
            int t2 = t1 >> 2;   int kc = t2 & 63; int bx = t2 >> 6;
            int rr = lane >> 2, cc = lane & 3;
            const float* p = W_hh1 + (size_t)(g * H + bx * 8 + rr) * H + kc * 16 + cc * 2;
            uint2 v; v.x = pk(p[0], p[1]); v.y = pk(p[8], p[9]);
            out[idx] = v;
        }
    } else if (job == 1) {
        uint2* out = (uint2*)g_W2p;
        for (int idx = gid; idx < 128 * 128 * 4 * 32; idx += stride) {
            int lane = idx & 31;
            int t1 = idx >> 5;  int g = t1 & 3;
            int t2 = t1 >> 2;   int kc = t2 & 127; int bx = t2 >> 7;
            int rr = lane >> 2, cc = lane & 3;
            int row = g * H + bx * 8 + rr;
            const float* W = W_ih2; int k0 = kc * 16 + cc * 2;
            if (kc >= 64) { W = W_hh2; k0 -= 1024; }
            const float* p = W + (size_t)row * H + k0;
            uint2 v; v.x = pk(p[0], p[1]); v.y = pk(p[8], p[9]);
            out[idx] = v;
        }
    } else if (job == 2) {
        uint4* out = (uint4*)g_Ax;
        for (int idx = gid; idx < 128 * 128 * 4 * 32; idx += stride) {
            int lane = idx & 31;
            int t1 = idx >> 5;
            int mt = t1 & 3; t1 >>= 2;
            int kc = t1 & 127;
            int mb = t1 >> 7;
            int rr = lane >> 2, cc = lane & 3;
            int r0 = mb * 64 + mt * 16 + rr, r1 = r0 + 8;
            int k0 = kc * 16 + cc * 2;
            const float *s0, *s1;
            if (k0 < 1024) { s0 = d1 + (size_t)r0 * 1024 + k0;        s1 = d1 + (size_t)r1 * 1024 + k0; }
            else           { s0 = d2 + (size_t)r0 * 1024 + k0 - 1024; s1 = d2 + (size_t)r1 * 1024 + k0 - 1024; }
            uint4 v;
            v.x = pk(s0[0], s0[1]);
            v.y = pk(s1[0], s1[1]);
            v.z = pk(s0[8], s0[9]);
            v.w = pk(s1[8], s1[9]);
            out[idx] = v;
        }
    } else if (job == 3) {
        uint2* out = (uint2*)g_Wx;
        for (int idx = gid; idx < 64 * 128 * 8 * 32; idx += stride) {
            int lane = idx & 31;
            int t1 = idx >> 5;
            int c = t1 & 7; t1 >>= 3;
            int kc = t1 & 127;
            int nb = t1 >> 7;
            int rr = lane >> 2, cc = lane & 3;
            const float* p = W_ih1 + (size_t)(nb * 64 + c * 8 + rr) * DIN + kc * 16 + cc * 2;
            uint2 v; v.x = pk(p[0], p[1]); v.y = pk(p[8], p[9]);
            out[idx] = v;
        }
    } else if (job == 4) {
        uint2* out = (uint2*)g_Wp1p;
        for (int idx = gid; idx < 4 * 64 * 8 * 32; idx += stride) {
            int lane = idx & 31;
            int t1 = idx >> 5;
            int c = t1 & 7; t1 >>= 3;
            int kc = t1 & 63;
            int nb = t1 >> 6;
            int rr = lane >> 2, cc = lane & 3;
            int n  = nb * 64 + c * 8 + rr;
            int k0 = kc * 16 + cc * 2;
            uint2 v;
            v.x = pk(Wp1[(size_t)k0 * NH1 + n],       Wp1[(size_t)(k0 + 1) * NH1 + n]);
            v.y = pk(Wp1[(size_t)(k0 + 8) * NH1 + n], Wp1[(size_t)(k0 + 9) * NH1 + n]);
            out[idx] = v;
        }
    } else {
        uint2* out = (uint2*)g_Wp2p;
        for (int idx = gid; idx < 16 * 16 * 8 * 32; idx += stride) {
            int lane = idx & 31;
            int t1 = idx >> 5;
            int c = t1 & 7; t1 >>= 3;
            int kc = t1 & 15;
            int nb = t1 >> 4;
            int rr = lane >> 2, cc = lane & 3;
            int n  = nb * 64 + c * 8 + rr;
            int k0 = kc * 16 + cc * 2;
            float a0 = 0.f, a1 = 0.f, b0 = 0.f, b1 = 0.f;
            if (n < NANS) {
                a0 = Wp2[(size_t)k0 * NANS + n];       a1 = Wp2[(size_t)(k0 + 1) * NANS + n];
                b0 = Wp2[(size_t)(k0 + 8) * NANS + n]; b1 = Wp2[(size_t)(k0 + 9) * NANS + n];
            }
            uint2 v; v.x = pk(a0, a1); v.y = pk(b0, b1);
            out[idx] = v;
        }
    }
}

// =================== xproj: bf16 mma, 128x128 CTA tile ======================
// L2-traffic-optimal: A reread x32, B reread x64 -> ~2.1 GB total (was 4 GB).
// Tile composed of 2x2 old 64-blocks; same packed fragment arrays.
// smem: 4 stages x 2048 uint4 (A 16KB + B 16KB per stage) = 128 KB.
__global__ __launch_bounds__(256) void k_xprojb(const float* __restrict__ bias)
{
    extern __shared__ uint4 sm[];
    const int tid = threadIdx.x, wid = tid >> 5, lane = tid & 31;
    const int mt = wid & 3, s = wid >> 2;
    const int rr = lane >> 2, cc = lane & 3;
    const int nb = blockIdx.x, mb = blockIdx.y;    // nb' 0..31, mb' 0..63
    float acc[2][8][4] = {};
    const uint4* A0 = (const uint4*)g_Ax + (size_t)(mb * 2    ) * 16384;
    const uint4* A1 = (const uint4*)g_Ax + (size_t)(mb * 2 + 1) * 16384;
    const uint4* B0 = (const uint4*)g_Wx + (size_t)(nb * 2    ) * 16384;
    const uint4* B1 = (const uint4*)g_Wx + (size_t)(nb * 2 + 1) * 16384;

    auto loadst = [&](int it) {
        if (it < 32) {
            uint4* dst = sm + (it & 3) * 2048;
            const int kc0 = it * 4;
#pragma unroll
            for (int e = 0; e < 8; e++) {
                int flat = e * 256 + tid;      // 0..2047
                int q = flat >> 7;             // chunk 0..15
                int i = flat & 127;
                const uint4* src;
                if (q < 8) {                   // A: q = kcl*2 + h
                    int h = q & 1, kcl = q >> 1;
                    src = (h ? A1 : A0) + (kc0 + kcl) * 128 + i;
                } else {                       // B: q-8 = kcl*2 + sh
                    int q2 = q - 8;
                    int sh = q2 & 1, kcl = q2 >> 1;
                    src = (sh ? B1 : B0) + (kc0 + kcl) * 128 + i;
                }
                cp16(&dst[flat], src);
            }
        }
        cp_commit();
    };
    loadst(0); loadst(1); loadst(2);
    for (int it = 0; it < 32; it++) {
        cp_wait2(); __syncthreads();
        loadst(it + 3);
        const uint4* SA = sm + (it & 3) * 2048;
        const uint2* SB = (const uint2*)(SA + 1024);
#pragma unroll
        for (int kcl = 0; kcl < 4; kcl++) {
            uint4 a0 = SA[(kcl * 2    ) * 128 + mt * 32 + lane];
            uint4 a1 = SA[(kcl * 2 + 1) * 128 + mt * 32 + lane];
#pragma unroll
            for (int c = 0; c < 8; c++) {
                uint2 b = SB[((kcl * 2 + s) * 8 + c) * 32 + lane];
                mmabf(acc[0][c], a0, b);
                mmabf(acc[1][c], a1, b);
            }
        }
    }
#pragma unroll
    for (int h = 0; h < 2; h++)
#pragma unroll
    for (int c = 0; c < 8; c++) {
        int col = nb * 128 + s * 64 + c * 8 + cc * 2;
        float b0 = bias[col], b1 = bias[col + 1];
#pragma unroll
        for (int hh = 0; hh < 2; hh++) {
            int m = mb * 128 + h * 64 + mt * 16 + rr + hh * 8;
            int tt = m & 127, bb = m >> 7;
            float* o = g_X1 + ((size_t)tt * NB + bb) * G4 + col;
            o[0] = acc[h][c][hh * 2 + 0] + b0;
            o[1] = acc[h][c][hh * 2 + 1] + b1;
        }
    }
}

// =================== persistent recurrence kernel (unchanged R10 core) ======
// smem (uint4): Gs[0,576) Gs2[576,1152) W1[1152,5248) W2[5248,13440)
//               XS[13440,14016)   total 224256 B
__global__ __launch_bounds__(256) void k_recur(const float* __restrict__ b2)
{
    extern __shared__ uint4 sm[];
    const int tid = threadIdx.x, wid = tid >> 5, lane = tid & 31;
    const int mt = wid & 3, s = wid >> 2;
    const int rr = lane >> 2, cc = lane & 3;
    const int bx = blockIdx.x;
    float* Gs   = (float*)sm;
    float* Gs2  = (float*)(sm + 576);
    const uint2* Wsm1 = (const uint2*)(sm + 1152);
    const uint2* Wsm2 = (const uint2*)(sm + 5248);
    float* XSf  = (float*)(sm + 13440);
    const int j = bx * 8 + cc * 2;
    const int j0 = bx * 8;
    const int fragoff = mt * 32 + lane;

    {
        const uint4* w1 = (const uint4*)g_W1p + (size_t)bx * 4096;
        for (int i = tid; i < 4096; i += 256) cp16(&sm[1152 + i], &w1[i]);
        const uint4* w2 = (const uint4*)g_W2p + (size_t)bx * 8192;
        for (int i = tid; i < 8192; i += 256) cp16(&sm[5248 + i], &w2[i]);
        cp_commit(); cp_wait0(); __syncthreads();
    }

    float2 b2i = make_float2(b2[j],         b2[j + 1]);
    float2 b2f = make_float2(b2[H + j],     b2[H + j + 1]);
    float2 b2g = make_float2(b2[2 * H + j], b2[2 * H + j + 1]);
    float2 b2o = make_float2(b2[3 * H + j], b2[3 * H + j + 1]);

    const int em0 = mt * 16 + rr, em1 = em0 + 8;
    float2 h1res[2];
    float2 c1v[2] = { make_float2(0.f, 0.f), make_float2(0.f, 0.f) };
    float2 c2v[2] = { make_float2(0.f, 0.f), make_float2(0.f, 0.f) };

    auto stageX = [&](int tt) {
        const float* Xt = g_X1 + (size_t)tt * NB * G4;
#pragma unroll
        for (int e = 0; e < 2; e++) {
            int i = tid + e * 256;
            int m = i >> 3, seg = i & 7;
            int g = seg >> 1, half = seg & 1;
            cp16(&XSf[m * 36 + g * 8 + half * 4],
                 Xt + (size_t)m * G4 + g * H + j0 + half * 4);
        }
        cp_commit();
    };

    // prologue: L1(0) = cell(X1[0]) only
    {
        stageX(0);
        cp_wait0(); __syncthreads();
        if (s == 1) {
#pragma unroll
            for (int hh = 0; hh < 2; hh++) {
                int m = hh ? em1 : em0;
                const float* xm = &XSf[m * 36];
                float gi0 = xm[     cc*2], gi1 = xm[     cc*2 + 1];
                float gg0 = xm[16 + cc*2], gg1 = xm[16 + cc*2 + 1];
                float go0 = xm[24 + cc*2], go1 = xm[24 + cc*2 + 1];
                float cn0 = fsig(gi0) * ftanh_(gg0);
                float cn1 = fsig(gi1) * ftanh_(gg1);
                c1v[hh] = make_float2(cn0, cn1);
                float h0 = fsig(go0) * ftanh_(cn0);
                float h1 = fsig(go1) * ftanh_(cn1);
                h1res[hh] = make_float2(h0, h1);
                g_h1p[1][((((bx >> 1) * 4 + mt) * 32 + lane) * 4)
                         + hh + 2 * (bx & 1)] = pk(h0, h1);
            }
        }
        gbar(NCTA);
    }

    // main loop: phase(t) = L2(t) + L1(t+1)
    for (int t = 0; t < NT - 1; t++) {
        const uint4* Aw1 = (const uint4*)(g_h1p[(t + 1) & 1]) + (s * 32) * 128 + fragoff;
        const uint4* Aw2 = (const uint4*)(g_h2p[t & 1])       + (s * 32) * 128 + fragoff;
        float accL2[4][4] = {};
        float accL1[4][4] = {};

        stageX(t + 1);

        uint4 ring[8];
#pragma unroll
        for (int p = 0; p < 8; p++) ring[p] = __ldcg(Aw1 + p * 128);
#pragma unroll 8
        for (int i = 0; i < 32; i++) {
            uint4 a = ring[i & 7];
            int r = i + 8;
            ring[i & 7] = (r < 32) ? __ldcg(Aw1 + r * 128)
                                   : __ldcg(Aw2 + (r - 32) * 128);
            const int kc = s * 32 + i;
#pragma unroll
            for (int g = 0; g < 4; g++)
                mmabf(accL2[g], a, Wsm2[(kc * 4 + g) * 32 + lane]);
#pragma unroll
            for (int g = 0; g < 4; g++)
                mmabf(accL1[g], a, Wsm1[(kc * 4 + g) * 32 + lane]);
        }
#pragma unroll 8
        for (int i = 0; i < 32; i++) {
            uint4 a = ring[i & 7];
            if (i + 8 < 32) ring[i & 7] = __ldcg(Aw2 + (i + 8) * 128);
            const int kc = 64 + s * 32 + i;
#pragma unroll
            for (int g = 0; g < 4; g++)
                mmabf(accL2[g], a, Wsm2[(kc * 4 + g) * 32 + lane]);
        }

        cp_wait0();
        __syncthreads();
        if (s == 0) {
#pragma unroll
            for (int g = 0; g < 4; g++) {
                Gs [em0 * 36 + g * 8 + cc * 2]     = accL2[g][0];
                Gs [em0 * 36 + g * 8 + cc * 2 + 1] = accL2[g][1];
                Gs [em1 * 36 + g * 8 + cc * 2]     = accL2[g][2];
                Gs [em1 * 36 + g * 8 + cc * 2 + 1] = accL2[g][3];
                Gs2[em0 * 36 + g * 8 + cc * 2]     = accL1[g][0];
                Gs2[em0 * 36 + g * 8 + cc * 2 + 1] = accL1[g][1];
                Gs2[em1 * 36 + g * 8 + cc * 2]     = accL1[g][2];
                Gs2[em1 * 36 + g * 8 + cc * 2 + 1] = accL1[g][3];
            }
        }
        __syncthreads();
        if (s == 1) {
#pragma unroll
            for (int hh = 0; hh < 2; hh++) {
                int m = hh ? em1 : em0;
                float gi0 = accL2[0][hh*2]   + Gs[m*36 +      cc*2]     + b2i.x;
                float gi1 = accL2[0][hh*2+1] + Gs[m*36 +      cc*2 + 1] + b2i.y;
                float gf0 = accL2[1][hh*2]   + Gs[m*36 +  8 + cc*2]     + b2f.x;
                float gf1 = accL2[1][hh*2+1] + Gs[m*36 +  8 + cc*2 + 1] + b2f.y;
                float gg0 = accL2[2][hh*2]   + Gs[m*36 + 16 + cc*2]     + b2g.x;
                float gg1 = accL2[2][hh*2+1] + Gs[m*36 + 16 + cc*2 + 1] + b2g.y;
                float go0 = accL2[3][hh*2]   + Gs[m*36 + 24 + cc*2]     + b2o.x;
                float go1 = accL2[3][hh*2+1] + Gs[m*36 + 24 + cc*2 + 1] + b2o.y;
                float cn0 = fsig(gf0) * c2v[hh].x + fsig(gi0) * ftanh_(gg0);
                float cn1 = fsig(gf1) * c2v[hh].y + fsig(gi1) * ftanh_(gg1);
                c2v[hh] = make_float2(cn0, cn1);
                float h0 = fsig(go0) * ftanh_(cn0);
                float h1 = fsig(go1) * ftanh_(cn1);
                g_h2p[(t + 1) & 1][((((bx >> 1) * 4 + mt) * 32 + lane) * 4)
                                   + hh + 2 * (bx & 1)] = pk(h0, h1);
                int mbL   = m * 2 + (t >> 6);
                int kcL   = bx >> 1;
                int mtL   = (t >> 4) & 3;
                int laneL = (t & 7) * 4 + cc;
                int regL  = ((t >> 3) & 1) + 2 * (bx & 1);
                g_LOp[((((size_t)mbL * 64 + kcL) * 4 + mtL) * 32 + laneL) * 4 + regL]
                    = pk(h0 + h1res[hh].x, h1 + h1res[hh].y);
            }
#pragma unroll
            for (int hh = 0; hh < 2; hh++) {
                int m = hh ? em1 : em0;
                const float* xm = &XSf[m * 36];
                float gi0 = accL1[0][hh*2]   + Gs2[m*36 +      cc*2]     + xm[     cc*2];
                float gi1 = accL1[0][hh*2+1] + Gs2[m*36 +      cc*2 + 1] + xm[     cc*2 + 1];
                float gf0 = accL1[1][hh*2]   + Gs2[m*36 +  8 + cc*2]     + xm[ 8 + cc*2];
                float gf1 = accL1[1][hh*2+1] + Gs2[m*36 +  8 + cc*2 + 1] + xm[ 8 + cc*2 + 1];
                float gg0 = accL1[2][hh*2]   + Gs2[m*36 + 16 + cc*2]     + xm[16 + cc*2];
                float gg1 = accL1[2][hh*2+1] + Gs2[m*36 + 16 + cc*2 + 1] + xm[16 + cc*2 + 1];
                float go0 = accL1[3][hh*2]   + Gs2[m*36 + 24 + cc*2]     + xm[24 + cc*2];
                float go1 = accL1[3][hh*2+1] + Gs2[m*36 + 24 + cc*2 + 1] + xm[24 + cc*2 + 1];
                float cn0 = fsig(gf0) * c1v[hh].x + fsig(gi0) * ftanh_(gg0);
                float cn1 = fsig(gf1) * c1v[hh].y + fsig(gi1) * ftanh_(gg1);
                c1v[hh] = make_float2(cn0, cn1);
                float h0 = fsig(go0) * ftanh_(cn0);
                float h1 = fsig(go1) * ftanh_(cn1);
                h1res[hh] = make_float2(h0, h1);
                g_h1p[(t + 2) & 1][((((bx >> 1) * 4 + mt) * 32 + lane) * 4)
                                   + hh + 2 * (bx & 1)] = pk(h0, h1);
            }
        }
        gbar((unsigned)(t + 2) * NCTA);
    }

    // tail: L2(127) only
    {
        const int t = NT - 1;
        const uint4* Aw1 = (const uint4*)(g_h1p[(t + 1) & 1]) + (s * 32) * 128 + fragoff;
        const uint4* Aw2 = (const uint4*)(g_h2p[t & 1])       + (s * 32) * 128 + fragoff;
        float accL2[4][4] = {};
        uint4 ring[8];
#pragma unroll
        for (int p = 0; p < 8; p++) ring[p] = __ldcg(Aw1 + p * 128);
#pragma unroll 8
        for (int i = 0; i < 32; i++) {
            uint4 a = ring[i & 7];
            int r = i + 8;
            ring[i & 7] = (r < 32) ? __ldcg(Aw1 + r * 128)
                                   : __ldcg(Aw2 + (r - 32) * 128);
            const int kc = s * 32 + i;
#pragma unroll
            for (int g = 0; g < 4; g++)
                mmabf(accL2[g], a, Wsm2[(kc * 4 + g) * 32 + lane]);
        }
#pragma unroll 8
        for (int i = 0; i < 32; i++) {
            uint4 a = ring[i & 7];
            if (i + 8 < 32) ring[i & 7] = __ldcg(Aw2 + (i + 8) * 128);
            const int kc = 64 + s * 32 + i;
#pragma unroll
            for (int g = 0; g < 4; g++)
                mmabf(accL2[g], a, Wsm2[(kc * 4 + g) * 32 + lane]);
        }
        __syncthreads();
        if (s == 0) {
#pragma unroll
            for (int g = 0; g < 4; g++) {
                Gs[em0 * 36 + g * 8 + cc * 2]     = accL2[g][0];
                Gs[em0 * 36 + g * 8 + cc * 2 + 1] = accL2[g][1];
                Gs[em1 * 36 + g * 8 + cc * 2]     = accL2[g][2];
                Gs[em1 * 36 + g * 8 + cc * 2 + 1] = accL2[g][3];
            }
        }
        __syncthreads();
        if (s == 1) {
#pragma unroll
            for (int hh = 0; hh < 2; hh++) {
                int m = hh ? em1 : em0;
                float gi0 = accL2[0][hh*2]   + Gs[m*36 +      cc*2]     + b2i.x;
                float gi1 = accL2[0][hh*2+1] + Gs[m*36 +      cc*2 + 1] + b2i.y;
                float gf0 = accL2[1][hh*2]   + Gs[m*36 +  8 + cc*2]     + b2f.x;
                float gf1 = accL2[1][hh*2+1] + Gs[m*36 +  8 + cc*2 + 1] + b2f.y;
                float gg0 = accL2[2][hh*2]   + Gs[m*36 + 16 + cc*2]     + b2g.x;
                float gg1 = accL2[2][hh*2+1] + Gs[m*36 + 16 + cc*2 + 1] + b2g.y;
                float go0 = accL2[3][hh*2]   + Gs[m*36 + 24 + cc*2]     + b2o.x;
                float go1 = accL2[3][hh*2+1] + Gs[m*36 + 24 + cc*2 + 1] + b2o.y;
                float cn0 = fsig(gf0) * c2v[hh].x + fsig(gi0) * ftanh_(gg0);
                float cn1 = fsig(gf1) * c2v[hh].y + fsig(gi1) * ftanh_(gg1);
                float h0 = fsig(go0) * ftanh_(cn0);
                float h1 = fsig(go1) * ftanh_(cn1);
                int mbL   = m * 2 + (t >> 6);
                int kcL   = bx >> 1;
                int mtL   = (t >> 4) & 3;
                int laneL = (t & 7) * 4 + cc;
                int regL  = ((t >> 3) & 1) + 2 * (bx & 1);
                g_LOp[((((size_t)mbL * 64 + kcL) * 4 + mtL) * 32 + laneL) * 4 + regL]
                    = pk(h0 + h1res[hh].x, h1 + h1res[hh].y);
            }
        }
    }
}

// =================== head GEMM 1: hid = relu(LO @ Wp1 + bp1) =================
__global__ __launch_bounds__(256) void k_mlp1b(const float* __restrict__ bp1)
{
    extern __shared__ uint4 sm[];
    const int tid = threadIdx.x, wid = tid >> 5, lane = tid & 31;
    const int mt = wid & 3, s = wid >> 2;
    const int rr = lane >> 2, cc = lane & 3;
    const int nb = blockIdx.x, mb = blockIdx.y;
    float acc[4][4] = {};
    const uint4* A4 = (const uint4*)g_LOp + (size_t)mb * 64 * 128;
    const uint4* B4 = (const uint4*)g_Wp1p + (size_t)nb * 64 * 128;

    auto loadst = [&](int it) {
        if (it < 16) {
            uint4* dst = sm + (it & 3) * 1024;
            const uint4* a = A4 + (size_t)it * 512;
            const uint4* b = B4 + (size_t)it * 512;
            cp16(&dst[tid],             &a[tid]);
            cp16(&dst[tid + 256],       &a[tid + 256]);
            cp16(&dst[512 + tid],       &b[tid]);
            cp16(&dst[512 + tid + 256], &b[tid + 256]);
        }
        cp_commit();
    };
    loadst(0); loadst(1); loadst(2);
    for (int it = 0; it < 16; it++) {
        cp_wait2(); __syncthreads();
        loadst(it + 3);
        const uint4* SA = sm + (it & 3) * 1024;
        const uint2* SB = (const uint2*)(SA + 512);
#pragma unroll
        for (int kcl = 0; kcl < 4; kcl++) {
            uint4 a = SA[(kcl * 4 + mt) * 32 + lane];
#pragma unroll
            for (int jn = 0; jn < 4; jn++) {
                uint2 b = SB[(kcl * 8 + s * 4 + jn) * 32 + lane];
                mmabf(acc[jn], a, b);
            }
        }
    }
#pragma unroll
    for (int jn = 0; jn < 4; jn++) {
        int c8  = s * 4 + jn;
        int col = nb * 64 + c8 * 8 + cc * 2;
        float b0 = bp1[col], b1 = bp1[col + 1];
        int kcH = nb * 4 + (c8 >> 1);
        int regH_base = 2 * (c8 & 1);
#pragma unroll
        for (int hh = 0; hh < 2; hh++) {
            float v0 = fmaxf(acc[jn][hh * 2 + 0] + b0, 0.f);
            float v1 = fmaxf(acc[jn][hh * 2 + 1] + b1, 0.f);
            g_HIDp[((((size_t)mb * 16 + kcH) * 4 + mt) * 32 + (rr * 4 + cc)) * 4
                   + hh + regH_base] = pk(v0, v1);
        }
    }
}

// =================== head GEMM 2: logits = hid @ Wp2 + bp2 ===================
__global__ __launch_bounds__(256) void k_logitsb(const float* __restrict__ bp2,
                                                 float* __restrict__ out)
{
    extern __shared__ uint4 sm[];
    const int tid = threadIdx.x, wid = tid >> 5, lane = tid & 31;
    const int mt = wid & 3, s = wid >> 2;
    const int rr = lane >> 2, cc = lane & 3;
    const int nb = blockIdx.x, mb = blockIdx.y;
    float acc[4][4] = {};
    const uint4* A4 = (const uint4*)g_HIDp + (size_t)mb * 16 * 128;
    const uint4* B4 = (const uint4*)g_Wp2p + (size_t)nb * 16 * 128;

    auto loadst = [&](int it) {
        if (it < 4) {
            uint4* dst = sm + (it & 3) * 1024;
            const uint4* a = A4 + (size_t)it * 512;
            const uint4* b = B4 + (size_t)it * 512;
            cp16(&dst[tid],             &a[tid]);
            cp16(&dst[tid + 256],       &a[tid + 256]);
            cp16(&dst[512 + tid],       &b[tid]);
            cp16(&dst[512 + tid + 256], &b[tid + 256]);
        }
        cp_commit();
    };
    loadst(0); loadst(1); loadst(2);
    for (int it = 0; it < 4; it++) {
        cp_wait2(); __syncthreads();
        loadst(it + 3);
        const uint4* SA = sm + (it & 3) * 1024;
        const uint2* SB = (const uint2*)(SA + 512);
#pragma unroll
        for (int kcl = 0; kcl < 4; kcl++) {
            uint4 a = SA[(kcl * 4 + mt) * 32 + lane];
#pragma unroll
            for (int jn = 0; jn < 4; jn++) {
                uint2 b = SB[(kcl * 8 + s * 4 + jn) * 32 + lane];
                mmabf(acc[jn], a, b);
            }
        }
    }
#pragma unroll
    for (int jn = 0; jn < 4; jn++) {
        int n = nb * 64 + (s * 4 + jn) * 8 + cc * 2;
        if (n < NANS) {
            float b0 = bp2[n], b1 = bp2[n + 1];
#pragma unroll
            for (int hh = 0; hh < 2; hh++) {
                int m = mb * 64 + mt * 16 + rr + hh * 8;
                float* o = out + (size_t)m * NANS + n;
                o[0] = acc[jn][hh * 2 + 0] + b0;
                o[1] = acc[jn][hh * 2 + 1] + b1;
            }
        }
    }
}

// ---------------- softmax ------------------------------------------------------
__global__ __launch_bounds__(256) void k_softmax(float* __restrict__ out)
{
    __shared__ float red[256];
    const int tid = threadIdx.x;
    float* p = out + (size_t)blockIdx.x * NANS;
    float v[4];
    float mx = -1e30f;
#pragma unroll
    for (int i = 0; i < 4; i++) {
        int n = tid + i * 256;
        v[i] = (n < NANS) ? p[n] : -1e30f;
        mx = fmaxf(mx, v[i]);
    }
    red[tid] = mx; __syncthreads();
    for (int s = 128; s > 0; s >>= 1) {
        if (tid < s) red[tid] = fmaxf(red[tid], red[tid + s]);
        __syncthreads();
    }
    mx = red[0]; __syncthreads();
    float sum = 0.f;
#pragma unroll
    for (int i = 0; i < 4; i++) {
        int n = tid + i * 256;
        if (n < NANS) { v[i] = expf(v[i] - mx); sum += v[i]; }
    }
    red[tid] = sum; __syncthreads();
    for (int s = 128; s > 0; s >>= 1) {
        if (tid < s) red[tid] += red[tid + s];
        __syncthreads();
    }
    float inv = 1.f / red[0];
#pragma unroll
    for (int i = 0; i < 4; i++) {
        int n = tid + i * 256;
        if (n < NANS) p[n] = v[i] * inv;
    }
}

// ---------------- launch ------------------------------------------------------
extern "C" void kernel_launch(void* const* d_in, const int* in_sizes, int n_in,
                              void* d_out, int out_size)
{
    const float* data1 = (const float*)d_in[0];
    const float* data2 = (const float*)d_in[1];
    const float* W_ih1 = (const float*)d_in[2];
    const float* W_hh1 = (const float*)d_in[3];
    const float* b1    = (const float*)d_in[4];
    const float* W_ih2 = (const float*)d_in[5];
    const float* W_hh2 = (const float*)d_in[6];
    const float* b2    = (const float*)d_in[7];
    const float* Wp1   = (const float*)d_in[8];
    const float* bp1   = (const float*)d_in[9];
    const float* Wp2   = (const float*)d_in[10];
    const float* bp2   = (const float*)d_in[11];
    float* out = (float*)d_out;

    static bool attr_done = false;
    if (!attr_done) {
        cudaFuncSetAttribute(k_xprojb,  cudaFuncAttributeMaxDynamicSharedMemorySize, 131072);
        cudaFuncSetAttribute(k_mlp1b,   cudaFuncAttributeMaxDynamicSharedMemorySize, 65536);
        cudaFuncSetAttribute(k_logitsb, cudaFuncAttributeMaxDynamicSharedMemorySize, 65536);
        cudaFuncSetAttribute(k_recur,   cudaFuncAttributeMaxDynamicSharedMemorySize, 224256);
        attr_done = true;
    }

    k_init_state<<<128, 256>>>();
    k_pack_all<<<dim3(1024, 6), 256>>>(W_hh1, W_ih2, W_hh2, data1, data2,
                                       W_ih1, Wp1, Wp2);
    k_xprojb<<<dim3(32, 64), 256, 131072>>>(b1);
    k_recur<<<128, 256, 224256>>>(b2);
    k_mlp1b<<<dim3(4, 128), 256, 65536>>>(bp1);
    k_logitsb<<<dim3(16, 128), 256, 65536>>>(bp2, out);
    k_softmax<<<BT, 256>>>(out);
}

// round 12
// speedup vs baseline: 2.0807x; 1.0590x over previous
#include <cuda_runtime.h>
#include <cuda_bf16.h>
#include <cstdint>
#include <math.h>

#define NB   64
#define NT   128
#define BT   8192
#define H    1024
#define DIN  2048
#define G4   4096
#define NH1  256
#define NANS 1000
#define NCTA 128u

// ---------------- device scratch ----------------
__device__ float g_X1[(size_t)BT * G4];          // [t][b][4H] (includes +b1)
__device__ unsigned g_bar;
// h in bf16 A-fragment layout: [kc(64)][mt(4)][lane(32)][reg(4)] u32
__device__ __align__(16) uint32_t g_h1p[2][32768];
__device__ __align__(16) uint32_t g_h2p[2][32768];
// step weights, B-fragment layout: [bx(128)][kc][g(4)][lane(32)] uint2
__device__ __align__(16) uint32_t g_W1p[128 * 64 * 4 * 32 * 2];     // 8 MB
__device__ __align__(16) uint32_t g_W2p[128 * 128 * 4 * 32 * 2];    // 16 MB
// xproj operands
__device__ __align__(16) uint32_t g_Ax[(size_t)128 * 128 * 4 * 32 * 4];  // 32 MB
__device__ __align__(16) uint32_t g_Wx[(size_t)64 * 128 * 8 * 32 * 2];   // 16 MB
// head: lstm_out bf16 A-frag [mb(128)][kc(64)][mt(4)][lane(32)][reg(4)]
__device__ __align__(16) uint32_t g_LOp[(size_t)128 * 64 * 4 * 32 * 4];  // 16 MB
// hid bf16 A-frag [mb(128)][kc(16)][mt][lane][reg]
__device__ __align__(16) uint32_t g_HIDp[(size_t)128 * 16 * 4 * 32 * 4]; // 4 MB
__device__ __align__(16) uint32_t g_Wp1p[4 * 64 * 8 * 32 * 2];
__device__ __align__(16) uint32_t g_Wp2p[16 * 16 * 8 * 32 * 2];

// fast activations
__device__ __forceinline__ float fsig(float x) {
    return __fdividef(1.f, 1.f + __expf(-x));
}
__device__ __forceinline__ float ftanh_(float x) {
    return fmaf(2.f, fsig(2.f * x), -1.f);
}
__device__ __forceinline__ uint32_t pk(float x, float y) {
    __nv_bfloat162 v = __floats2bfloat162_rn(x, y);
    return *reinterpret_cast<uint32_t*>(&v);
}
__device__ __forceinline__ void mmabf(float c[4], uint4 a, uint2 b) {
    asm volatile(
        "mma.sync.aligned.m16n8k16.row.col.f32.bf16.bf16.f32 "
        "{%0,%1,%2,%3},{%4,%5,%6,%7},{%8,%9},{%0,%1,%2,%3};"
        : "+f"(c[0]), "+f"(c[1]), "+f"(c[2]), "+f"(c[3])
        : "r"(a.x), "r"(a.y), "r"(a.z), "r"(a.w), "r"(b.x), "r"(b.y));
}
__device__ __forceinline__ void cp16(void* smem, const void* g) {
    uint32_t s = (uint32_t)__cvta_generic_to_shared(smem);
    asm volatile("cp.async.cg.shared.global [%0], [%1], 16;" :: "r"(s), "l"(g));
}
__device__ __forceinline__ void cp_commit() { asm volatile("cp.async.commit_group;"); }
__device__ __forceinline__ void cp_wait2()  { asm volatile("cp.async.wait_group 2;"); }
__device__ __forceinline__ void cp_wait0()  { asm volatile("cp.async.wait_group 0;"); }

// global barrier: release-arrive + acquire-poll
__device__ __forceinline__ void gbar(unsigned target) {
    __syncthreads();
    if (threadIdx.x == 0) {
        unsigned* bp = &g_bar;
        asm volatile("red.release.gpu.global.add.u32 [%0], %1;"
                     :: "l"(bp), "r"(1u) : "memory");
        unsigned v;
        do {
            asm volatile("ld.acquire.gpu.global.u32 %0, [%1];"
                         : "=r"(v) : "l"(bp) : "memory");
        } while (v < target);
    }
    __syncthreads();
}

// ---------------- init ----------------
__global__ void k_init_state() {
    int i = blockIdx.x * blockDim.x + threadIdx.x;
    if (i == 0) g_bar = 0u;
    if (i < 32768) { g_h1p[0][i] = 0u; g_h2p[0][i] = 0u; }
}

// ---------------- unified pack kernel (job = blockIdx.y) ---------------------
__global__ void k_pack_all(
    const float* __restrict__ W_hh1, const float* __restrict__ W_ih2,
    const float* __restrict__ W_hh2, const float* __restrict__ d1,
    const float* __restrict__ d2,   const float* __restrict__ W_ih1,
    const float* __restrict__ Wp1,  const float* __restrict__ Wp2)
{
    const int job = blockIdx.y;
    const int gid = blockIdx.x * blockDim.x + threadIdx.x;
    const int stride = gridDim.x * blockDim.x;

    if (job == 0) {
        uint2* out = (uint2*)g_W1p;
        for (int idx = gid; idx < 128 * 64 * 4 * 32; idx += stride) {
            int lane = idx & 31;
            int t1 = idx >> 5;  int g = t1 & 3;
            int t2 = t1 >> 2;   int kc = t2 & 63; int bx = t2 >> 6;
            int rr = lane >> 2, cc = lane & 3;
            const float* p = W_hh1 + (size_t)(g * H + bx * 8 + rr) * H + kc * 16 + cc * 2;
            uint2 v; v.x = pk(p[0], p[1]); v.y = pk(p[8], p[9]);
            out[idx] = v;
        }
    } else if (job == 1) {
        uint2* out = (uint2*)g_W2p;
        for (int idx = gid; idx < 128 * 128 * 4 * 32; idx += stride) {
            int lane = idx & 31;
            int t1 = idx >> 5;  int g = t1 & 3;
            int t2 = t1 >> 2;   int kc = t2 & 127; int bx = t2 >> 7;
            int rr = lane >> 2, cc = lane & 3;
            int row = g * H + bx * 8 + rr;
            const float* W = W_ih2; int k0 = kc * 16 + cc * 2;
            if (kc >= 64) { W = W_hh2; k0 -= 1024; }
            const float* p = W + (size_t)row * H + k0;
            uint2 v; v.x = pk(p[0], p[1]); v.y = pk(p[8], p[9]);
            out[idx] = v;
        }
    } else if (job == 2) {
        uint4* out = (uint4*)g_Ax;
        for (int idx = gid; idx < 128 * 128 * 4 * 32; idx += stride) {
            int lane = idx & 31;
            int t1 = idx >> 5;
            int mt = t1 & 3; t1 >>= 2;
            int kc = t1 & 127;
            int mb = t1 >> 7;
            int rr = lane >> 2, cc = lane & 3;
            int r0 = mb * 64 + mt * 16 + rr, r1 = r0 + 8;
            int k0 = kc * 16 + cc * 2;
            const float *s0, *s1;
            if (k0 < 1024) { s0 = d1 + (size_t)r0 * 1024 + k0;        s1 = d1 + (size_t)r1 * 1024 + k0; }
            else           { s0 = d2 + (size_t)r0 * 1024 + k0 - 1024; s1 = d2 + (size_t)r1 * 1024 + k0 - 1024; }
            uint4 v;
            v.x = pk(s0[0], s0[1]);
            v.y = pk(s1[0], s1[1]);
            v.z = pk(s0[8], s0[9]);
            v.w = pk(s1[8], s1[9]);
            out[idx] = v;
        }
    } else if (job == 3) {
        uint2* out = (uint2*)g_Wx;
        for (int idx = gid; idx < 64 * 128 * 8 * 32; idx += stride) {
            int lane = idx & 31;
            int t1 = idx >> 5;
            int c = t1 & 7; t1 >>= 3;
            int kc = t1 & 127;
            int nb = t1 >> 7;
            int rr = lane >> 2, cc = lane & 3;
            const float* p = W_ih1 + (size_t)(nb * 64 + c * 8 + rr) * DIN + kc * 16 + cc * 2;
            uint2 v; v.x = pk(p[0], p[1]); v.y = pk(p[8], p[9]);
            out[idx] = v;
        }
    } else if (job == 4) {
        uint2* out = (uint2*)g_Wp1p;
        for (int idx = gid; idx < 4 * 64 * 8 * 32; idx += stride) {
            int lane = idx & 31;
            int t1 = idx >> 5;
            int c = t1 & 7; t1 >>= 3;
            int kc = t1 & 63;
            int nb = t1 >> 6;
            int rr = lane >> 2, cc = lane & 3;
            int n  = nb * 64 + c * 8 + rr;
            int k0 = kc * 16 + cc * 2;
            uint2 v;
            v.x = pk(Wp1[(size_t)k0 * NH1 + n],       Wp1[(size_t)(k0 + 1) * NH1 + n]);
            v.y = pk(Wp1[(size_t)(k0 + 8) * NH1 + n], Wp1[(size_t)(k0 + 9) * NH1 + n]);
            out[idx] = v;
        }
    } else {
        uint2* out = (uint2*)g_Wp2p;
        for (int idx = gid; idx < 16 * 16 * 8 * 32; idx += stride) {
            int lane = idx & 31;
            int t1 = idx >> 5;
            int c = t1 & 7; t1 >>= 3;
            int kc = t1 & 15;
            int nb = t1 >> 4;
            int rr = lane >> 2, cc = lane & 3;
            int n  = nb * 64 + c * 8 + rr;
            int k0 = kc * 16 + cc * 2;
            float a0 = 0.f, a1 = 0.f, b0 = 0.f, b1 = 0.f;
            if (n < NANS) {
                a0 = Wp2[(size_t)k0 * NANS + n];       a1 = Wp2[(size_t)(k0 + 1) * NANS + n];
                b0 = Wp2[(size_t)(k0 + 8) * NANS + n]; b1 = Wp2[(size_t)(k0 + 9) * NANS + n];
            }
            uint2 v; v.x = pk(a0, a1); v.y = pk(b0, b1);
            out[idx] = v;
        }
    }
}

// =================== xproj: bf16 mma, 128x256 CTA tile ======================
// Traffic ~1.5 GB; each A-frag feeds 32 MMAs. smem: 4 stages x 3072 uint4
// (A 16KB + B 32KB per stage) = 192 KB. grid (nb=16, mb=64).
__global__ __launch_bounds__(256) void k_xprojb(const float* __restrict__ bias)
{
    extern __shared__ uint4 sm[];
    const int tid = threadIdx.x, wid = tid >> 5, lane = tid & 31;
    const int mt = wid & 3, s = wid >> 2;
    const int rr = lane >> 2, cc = lane & 3;
    const int nb = blockIdx.x, mb = blockIdx.y;
    float acc[2][16][4] = {};
    const uint4* Abase = (const uint4*)g_Ax + (size_t)(mb * 2) * 16384;
    const uint4* Bbase = (const uint4*)g_Wx + (size_t)(nb * 4) * 16384;

    auto loadst = [&](int it) {
        if (it < 32) {
            uint4* dst = sm + (it & 3) * 3072;
            const int kc0 = it * 4;
#pragma unroll
            for (int e = 0; e < 12; e++) {
                int flat = e * 256 + tid;          // 0..3071
                const uint4* src;
                if (flat < 1024) {                  // A: q = h*4+kcl
                    int q = flat >> 7, i = flat & 127;
                    int h = q >> 2, kcl = q & 3;
                    src = Abase + (size_t)h * 16384 + (kc0 + kcl) * 128 + i;
                } else {                            // B: q = cb*4+kcl
                    int f2 = flat - 1024;
                    int q = f2 >> 7, i = f2 & 127;
                    int cb = q >> 2, kcl = q & 3;
                    src = Bbase + (size_t)cb * 16384 + (kc0 + kcl) * 128 + i;
                }
                cp16(&dst[flat], src);
            }
        }
        cp_commit();
    };
    loadst(0); loadst(1); loadst(2);
    for (int it = 0; it < 32; it++) {
        cp_wait2(); __syncthreads();
        loadst(it + 3);
        const uint4* SA = sm + (it & 3) * 3072;
        const uint2* SB = (const uint2*)(SA + 1024);
#pragma unroll
        for (int kcl = 0; kcl < 4; kcl++) {
            uint4 a0 = SA[(kcl    ) * 128 + mt * 32 + lane];
            uint4 a1 = SA[(4 + kcl) * 128 + mt * 32 + lane];
#pragma unroll
            for (int cbl = 0; cbl < 2; cbl++) {
                int cb = s * 2 + cbl;
#pragma unroll
                for (int c = 0; c < 8; c++) {
                    uint2 b = SB[((cb * 4 + kcl) * 8 + c) * 32 + lane];
                    mmabf(acc[0][cbl * 8 + c], a0, b);
                    mmabf(acc[1][cbl * 8 + c], a1, b);
                }
            }
        }
    }
#pragma unroll
    for (int h = 0; h < 2; h++)
#pragma unroll
    for (int cg = 0; cg < 16; cg++) {
        int cb = s * 2 + (cg >> 3), c = cg & 7;
        int col = nb * 256 + cb * 64 + c * 8 + cc * 2;
        float b0 = bias[col], b1 = bias[col + 1];
#pragma unroll
        for (int hh = 0; hh < 2; hh++) {
            int m = mb * 128 + h * 64 + mt * 16 + rr + hh * 8;
            int tt = m & 127, bb = m >> 7;
            float* o = g_X1 + ((size_t)tt * NB + bb) * G4 + col;
            o[0] = acc[h][cg][hh * 2 + 0] + b0;
            o[1] = acc[h][cg][hh * 2 + 1] + b1;
        }
    }
}

// =================== persistent recurrence kernel ===========================
// Merged-phase + SPLIT EPILOGUE: s==0 runs L1(t+1) cell (owns c1), s==1 runs
// L2(t) cell (owns c2) concurrently. Each side publishes the accumulator half
// the other needs (s==0 accL2->Gs, s==1 accL1->Gs2). h1_t crosses groups via
// double-buffered smem HR[2].
// smem (uint4): Gs[0,576) Gs2[576,1152) W1[1152,5248) W2[5248,13440)
//               XS[13440,14016) HR floats at byte 224256 (2*64*10*4 = 5120)
__global__ __launch_bounds__(256) void k_recur(const float* __restrict__ b2)
{
    extern __shared__ uint4 sm[];
    const int tid = threadIdx.x, wid = tid >> 5, lane = tid & 31;
    const int mt = wid & 3, s = wid >> 2;
    const int rr = lane >> 2, cc = lane & 3;
    const int bx = blockIdx.x;
    float* Gs   = (float*)sm;
    float* Gs2  = (float*)(sm + 576);
    const uint2* Wsm1 = (const uint2*)(sm + 1152);
    const uint2* Wsm2 = (const uint2*)(sm + 5248);
    float* XSf  = (float*)(sm + 13440);
    float* HRf  = (float*)(sm + 14016);     // [2][64][10]
    const int j = bx * 8 + cc * 2;
    const int j0 = bx * 8;
    const int fragoff = mt * 32 + lane;

    {
        const uint4* w1 = (const uint4*)g_W1p + (size_t)bx * 4096;
        for (int i = tid; i < 4096; i += 256) cp16(&sm[1152 + i], &w1[i]);
        const uint4* w2 = (const uint4*)g_W2p + (size_t)bx * 8192;
        for (int i = tid; i < 8192; i += 256) cp16(&sm[5248 + i], &w2[i]);
        cp_commit(); cp_wait0(); __syncthreads();
    }

    float2 b2i = make_float2(b2[j],         b2[j + 1]);
    float2 b2f = make_float2(b2[H + j],     b2[H + j + 1]);
    float2 b2g = make_float2(b2[2 * H + j], b2[2 * H + j + 1]);
    float2 b2o = make_float2(b2[3 * H + j], b2[3 * H + j + 1]);

    const int em0 = mt * 16 + rr, em1 = em0 + 8;
    float2 c1v[2] = { make_float2(0.f, 0.f), make_float2(0.f, 0.f) };  // s==0 state
    float2 c2v[2] = { make_float2(0.f, 0.f), make_float2(0.f, 0.f) };  // s==1 state

    auto stageX = [&](int tt) {
        const float* Xt = g_X1 + (size_t)tt * NB * G4;
#pragma unroll
        for (int e = 0; e < 2; e++) {
            int i = tid + e * 256;
            int m = i >> 3, seg = i & 7;
            int g = seg >> 1, half = seg & 1;
            cp16(&XSf[m * 36 + g * 8 + half * 4],
                 Xt + (size_t)m * G4 + g * H + j0 + half * 4);
        }
        cp_commit();
    };

    // prologue: L1(0) = cell(X1[0]) by s==0; h1_0 -> h1p[1] + HR[0]
    {
        stageX(0);
        cp_wait0(); __syncthreads();
        if (s == 0) {
#pragma unroll
            for (int hh = 0; hh < 2; hh++) {
                int m = hh ? em1 : em0;
                const float* xm = &XSf[m * 36];
                float gi0 = xm[     cc*2], gi1 = xm[     cc*2 + 1];
                float gg0 = xm[16 + cc*2], gg1 = xm[16 + cc*2 + 1];
                float go0 = xm[24 + cc*2], go1 = xm[24 + cc*2 + 1];
                float cn0 = fsig(gi0) * ftanh_(gg0);
                float cn1 = fsig(gi1) * ftanh_(gg1);
                c1v[hh] = make_float2(cn0, cn1);
                float h0 = fsig(go0) * ftanh_(cn0);
                float h1 = fsig(go1) * ftanh_(cn1);
                HRf[m * 10 + cc * 2]     = h0;
                HRf[m * 10 + cc * 2 + 1] = h1;
                g_h1p[1][((((bx >> 1) * 4 + mt) * 32 + lane) * 4)
                         + hh + 2 * (bx & 1)] = pk(h0, h1);
            }
        }
        gbar(NCTA);
    }

    // main loop: phase(t) = L2(t) + L1(t+1)
    for (int t = 0; t < NT - 1; t++) {
        const uint4* Aw1 = (const uint4*)(g_h1p[(t + 1) & 1]) + (s * 32) * 128 + fragoff;
        const uint4* Aw2 = (const uint4*)(g_h2p[t & 1])       + (s * 32) * 128 + fragoff;
        float accL2[4][4] = {};
        float accL1[4][4] = {};

        stageX(t + 1);

        uint4 ring[8];
#pragma unroll
        for (int p = 0; p < 8; p++) ring[p] = __ldcg(Aw1 + p * 128);
#pragma unroll 8
        for (int i = 0; i < 32; i++) {
            uint4 a = ring[i & 7];
            int r = i + 8;
            ring[i & 7] = (r < 32) ? __ldcg(Aw1 + r * 128)
                                   : __ldcg(Aw2 + (r - 32) * 128);
            const int kc = s * 32 + i;
#pragma unroll
            for (int g = 0; g < 4; g++)
                mmabf(accL2[g], a, Wsm2[(kc * 4 + g) * 32 + lane]);
#pragma unroll
            for (int g = 0; g < 4; g++)
                mmabf(accL1[g], a, Wsm1[(kc * 4 + g) * 32 + lane]);
        }
#pragma unroll 8
        for (int i = 0; i < 32; i++) {
            uint4 a = ring[i & 7];
            if (i + 8 < 32) ring[i & 7] = __ldcg(Aw2 + (i + 8) * 128);
            const int kc = 64 + s * 32 + i;
#pragma unroll
            for (int g = 0; g < 4; g++)
                mmabf(accL2[g], a, Wsm2[(kc * 4 + g) * 32 + lane]);
        }

        cp_wait0();
        __syncthreads();
        if (s == 0) {           // publish accL2 for s==1
#pragma unroll
            for (int g = 0; g < 4; g++) {
                Gs [em0 * 36 + g * 8 + cc * 2]     = accL2[g][0];
                Gs [em0 * 36 + g * 8 + cc * 2 + 1] = accL2[g][1];
                Gs [em1 * 36 + g * 8 + cc * 2]     = accL2[g][2];
                Gs [em1 * 36 + g * 8 + cc * 2 + 1] = accL2[g][3];
            }
        } else {                // publish accL1 for s==0
#pragma unroll
            for (int g = 0; g < 4; g++) {
                Gs2[em0 * 36 + g * 8 + cc * 2]     = accL1[g][0];
                Gs2[em0 * 36 + g * 8 + cc * 2 + 1] = accL1[g][1];
                Gs2[em1 * 36 + g * 8 + cc * 2]     = accL1[g][2];
                Gs2[em1 * 36 + g * 8 + cc * 2 + 1] = accL1[g][3];
            }
        }
        __syncthreads();
        if (s == 1) {
            // ---- L2(t) epilogue (c2 state; h1_t from HR[t&1]) ----
            const float* hr = &HRf[(t & 1) * 640];
#pragma unroll
            for (int hh = 0; hh < 2; hh++) {
                int m = hh ? em1 : em0;
                float gi0 = accL2[0][hh*2]   + Gs[m*36 +      cc*2]     + b2i.x;
                float gi1 = accL2[0][hh*2+1] + Gs[m*36 +      cc*2 + 1] + b2i.y;
                float gf0 = accL2[1][hh*2]   + Gs[m*36 +  8 + cc*2]     + b2f.x;
                float gf1 = accL2[1][hh*2+1] + Gs[m*36 +  8 + cc*2 + 1] + b2f.y;
                float gg0 = accL2[2][hh*2]   + Gs[m*36 + 16 + cc*2]     + b2g.x;
                float gg1 = accL2[2][hh*2+1] + Gs[m*36 + 16 + cc*2 + 1] + b2g.y;
                float go0 = accL2[3][hh*2]   + Gs[m*36 + 24 + cc*2]     + b2o.x;
                float go1 = accL2[3][hh*2+1] + Gs[m*36 + 24 + cc*2 + 1] + b2o.y;
                float cn0 = fsig(gf0) * c2v[hh].x + fsig(gi0) * ftanh_(gg0);
                float cn1 = fsig(gf1) * c2v[hh].y + fsig(gi1) * ftanh_(gg1);
                c2v[hh] = make_float2(cn0, cn1);
                float h0 = fsig(go0) * ftanh_(cn0);
                float h1 = fsig(go1) * ftanh_(cn1);
                g_h2p[(t + 1) & 1][((((bx >> 1) * 4 + mt) * 32 + lane) * 4)
                                   + hh + 2 * (bx & 1)] = pk(h0, h1);
                float r0 = hr[m * 10 + cc * 2], r1 = hr[m * 10 + cc * 2 + 1];
                int mbL   = m * 2 + (t >> 6);
                int kcL   = bx >> 1;
                int mtL   = (t >> 4) & 3;
                int laneL = (t & 7) * 4 + cc;
                int regL  = ((t >> 3) & 1) + 2 * (bx & 1);
                g_LOp[((((size_t)mbL * 64 + kcL) * 4 + mtL) * 32 + laneL) * 4 + regL]
                    = pk(h0 + r0, h1 + r1);
            }
        } else {
            // ---- L1(t+1) epilogue (c1 state; X from XSf; write HR[(t+1)&1]) ----
            float* hr = &HRf[((t + 1) & 1) * 640];
#pragma unroll
            for (int hh = 0; hh < 2; hh++) {
                int m = hh ? em1 : em0;
                const float* xm = &XSf[m * 36];
                float gi0 = accL1[0][hh*2]   + Gs2[m*36 +      cc*2]     + xm[     cc*2];
                float gi1 = accL1[0][hh*2+1] + Gs2[m*36 +      cc*2 + 1] + xm[     cc*2 + 1];
                float gf0 = accL1[1][hh*2]   + Gs2[m*36 +  8 + cc*2]     + xm[ 8 + cc*2];
                float gf1 = accL1[1][hh*2+1] + Gs2[m*36 +  8 + cc*2 + 1] + xm[ 8 + cc*2 + 1];
                float gg0 = accL1[2][hh*2]   + Gs2[m*36 + 16 + cc*2]     + xm[16 + cc*2];
                float gg1 = accL1[2][hh*2+1] + Gs2[m*36 + 16 + cc*2 + 1] + xm[16 + cc*2 + 1];
                float go0 = accL1[3][hh*2]   + Gs2[m*36 + 24 + cc*2]     + xm[24 + cc*2];
                float go1 = accL1[3][hh*2+1] + Gs2[m*36 + 24 + cc*2 + 1] + xm[24 + cc*2 + 1];
                float cn0 = fsig(gf0) * c1v[hh].x + fsig(gi0) * ftanh_(gg0);
                float cn1 = fsig(gf1) * c1v[hh].y + fsig(gi1) * ftanh_(gg1);
                c1v[hh] = make_float2(cn0, cn1);
                float h0 = fsig(go0) * ftanh_(cn0);
                float h1 = fsig(go1) * ftanh_(cn1);
                hr[m * 10 + cc * 2]     = h0;
                hr[m * 10 + cc * 2 + 1] = h1;
                g_h1p[(t + 2) & 1][((((bx >> 1) * 4 + mt) * 32 + lane) * 4)
                                   + hh + 2 * (bx & 1)] = pk(h0, h1);
            }
        }
        gbar((unsigned)(t + 2) * NCTA);
    }

    // tail: L2(127) only
    {
        const int t = NT - 1;
        const uint4* Aw1 = (const uint4*)(g_h1p[(t + 1) & 1]) + (s * 32) * 128 + fragoff;
        const uint4* Aw2 = (const uint4*)(g_h2p[t & 1])       + (s * 32) * 128 + fragoff;
        float accL2[4][4] = {};
        uint4 ring[8];
#pragma unroll
        for (int p = 0; p < 8; p++) ring[p] = __ldcg(Aw1 + p * 128);
#pragma unroll 8
        for (int i = 0; i < 32; i++) {
            uint4 a = ring[i & 7];
            int r = i + 8;
            ring[i & 7] = (r < 32) ? __ldcg(Aw1 + r * 128)
                                   : __ldcg(Aw2 + (r - 32) * 128);
            const int kc = s * 32 + i;
#pragma unroll
            for (int g = 0; g < 4; g++)
                mmabf(accL2[g], a, Wsm2[(kc * 4 + g) * 32 + lane]);
        }
#pragma unroll 8
        for (int i = 0; i < 32; i++) {
            uint4 a = ring[i & 7];
            if (i + 8 < 32) ring[i & 7] = __ldcg(Aw2 + (i + 8) * 128);
            const int kc = 64 + s * 32 + i;
#pragma unroll
            for (int g = 0; g < 4; g++)
                mmabf(accL2[g], a, Wsm2[(kc * 4 + g) * 32 + lane]);
        }
        __syncthreads();
        if (s == 0) {
#pragma unroll
            for (int g = 0; g < 4; g++) {
                Gs[em0 * 36 + g * 8 + cc * 2]     = accL2[g][0];
                Gs[em0 * 36 + g * 8 + cc * 2 + 1] = accL2[g][1];
                Gs[em1 * 36 + g * 8 + cc * 2]     = accL2[g][2];
                Gs[em1 * 36 + g * 8 + cc * 2 + 1] = accL2[g][3];
            }
        }
        __syncthreads();
        if (s == 1) {
            const float* hr = &HRf[(t & 1) * 640];
#pragma unroll
            for (int hh = 0; hh < 2; hh++) {
                int m = hh ? em1 : em0;
                float gi0 = accL2[0][hh*2]   + Gs[m*36 +      cc*2]     + b2i.x;
                float gi1 = accL2[0][hh*2+1] + Gs[m*36 +      cc*2 + 1] + b2i.y;
                float gf0 = accL2[1][hh*2]   + Gs[m*36 +  8 + cc*2]     + b2f.x;
                float gf1 = accL2[1][hh*2+1] + Gs[m*36 +  8 + cc*2 + 1] + b2f.y;
                float gg0 = accL2[2][hh*2]   + Gs[m*36 + 16 + cc*2]     + b2g.x;
                float gg1 = accL2[2][hh*2+1] + Gs[m*36 + 16 + cc*2 + 1] + b2g.y;
                float go0 = accL2[3][hh*2]   + Gs[m*36 + 24 + cc*2]     + b2o.x;
                float go1 = accL2[3][hh*2+1] + Gs[m*36 + 24 + cc*2 + 1] + b2o.y;
                float cn0 = fsig(gf0) * c2v[hh].x + fsig(gi0) * ftanh_(gg0);
                float cn1 = fsig(gf1) * c2v[hh].y + fsig(gi1) * ftanh_(gg1);
                float h0 = fsig(go0) * ftanh_(cn0);
                float h1 = fsig(go1) * ftanh_(cn1);
                float r0 = hr[m * 10 + cc * 2], r1 = hr[m * 10 + cc * 2 + 1];
                int mbL   = m * 2 + (t >> 6);
                int kcL   = bx >> 1;
                int mtL   = (t >> 4) & 3;
                int laneL = (t & 7) * 4 + cc;
                int regL  = ((t >> 3) & 1) + 2 * (bx & 1);
                g_LOp[((((size_t)mbL * 64 + kcL) * 4 + mtL) * 32 + laneL) * 4 + regL]
                    = pk(h0 + r0, h1 + r1);
            }
        }
    }
}

// =================== head GEMM 1: hid = relu(LO @ Wp1 + bp1) =================
__global__ __launch_bounds__(256) void k_mlp1b(const float* __restrict__ bp1)
{
    extern __shared__ uint4 sm[];
    const int tid = threadIdx.x, wid = tid >> 5, lane = tid & 31;
    const int mt = wid & 3, s = wid >> 2;
    const int rr = lane >> 2, cc = lane & 3;
    const int nb = blockIdx.x, mb = blockIdx.y;
    float acc[4][4] = {};
    const uint4* A4 = (const uint4*)g_LOp + (size_t)mb * 64 * 128;
    const uint4* B4 = (const uint4*)g_Wp1p + (size_t)nb * 64 * 128;

    auto loadst = [&](int it) {
        if (it < 16) {
            uint4* dst = sm + (it & 3) * 1024;
            const uint4* a = A4 + (size_t)it * 512;
            const uint4* b = B4 + (size_t)it * 512;
            cp16(&dst[tid],             &a[tid]);
            cp16(&dst[tid + 256],       &a[tid + 256]);
            cp16(&dst[512 + tid],       &b[tid]);
            cp16(&dst[512 + tid + 256], &b[tid + 256]);
        }
        cp_commit();
    };
    loadst(0); loadst(1); loadst(2);
    for (int it = 0; it < 16; it++) {
        cp_wait2(); __syncthreads();
        loadst(it + 3);
        const uint4* SA = sm + (it & 3) * 1024;
        const uint2* SB = (const uint2*)(SA + 512);
#pragma unroll
        for (int kcl = 0; kcl < 4; kcl++) {
            uint4 a = SA[(kcl * 4 + mt) * 32 + lane];
#pragma unroll
            for (int jn = 0; jn < 4; jn++) {
                uint2 b = SB[(kcl * 8 + s * 4 + jn) * 32 + lane];
                mmabf(acc[jn], a, b);
            }
        }
    }
#pragma unroll
    for (int jn = 0; jn < 4; jn++) {
        int c8  = s * 4 + jn;
        int col = nb * 64 + c8 * 8 + cc * 2;
        float b0 = bp1[col], b1 = bp1[col + 1];
        int kcH = nb * 4 + (c8 >> 1);
        int regH_base = 2 * (c8 & 1);
#pragma unroll
        for (int hh = 0; hh < 2; hh++) {
            float v0 = fmaxf(acc[jn][hh * 2 + 0] + b0, 0.f);
            float v1 = fmaxf(acc[jn][hh * 2 + 1] + b1, 0.f);
            g_HIDp[((((size_t)mb * 16 + kcH) * 4 + mt) * 32 + (rr * 4 + cc)) * 4
                   + hh + regH_base] = pk(v0, v1);
        }
    }
}

// =================== head GEMM 2: logits = hid @ Wp2 + bp2 ===================
__global__ __launch_bounds__(256) void k_logitsb(const float* __restrict__ bp2,
                                                 float* __restrict__ out)
{
    extern __shared__ uint4 sm[];
    const int tid = threadIdx.x, wid = tid >> 5, lane = tid & 31;
    const int mt = wid & 3, s = wid >> 2;
    const int rr = lane >> 2, cc = lane & 3;
    const int nb = blockIdx.x, mb = blockIdx.y;
    float acc[4][4] = {};
    const uint4* A4 = (const uint4*)g_HIDp + (size_t)mb * 16 * 128;
    const uint4* B4 = (const uint4*)g_Wp2p + (size_t)nb * 16 * 128;

    auto loadst = [&](int it) {
        if (it < 4) {
            uint4* dst = sm + (it & 3) * 1024;
            const uint4* a = A4 + (size_t)it * 512;
            const uint4* b = B4 + (size_t)it * 512;
            cp16(&dst[tid],             &a[tid]);
            cp16(&dst[tid + 256],       &a[tid + 256]);
            cp16(&dst[512 + tid],       &b[tid]);
            cp16(&dst[512 + tid + 256], &b[tid + 256]);
        }
        cp_commit();
    };
    loadst(0); loadst(1); loadst(2);
    for (int it = 0; it < 4; it++) {
        cp_wait2(); __syncthreads();
        loadst(it + 3);
        const uint4* SA = sm + (it & 3) * 1024;
        const uint2* SB = (const uint2*)(SA + 512);
#pragma unroll
        for (int kcl = 0; kcl < 4; kcl++) {
            uint4 a = SA[(kcl * 4 + mt) * 32 + lane];
#pragma unroll
            for (int jn = 0; jn < 4; jn++) {
                uint2 b = SB[(kcl * 8 + s * 4 + jn) * 32 + lane];
                mmabf(acc[jn], a, b);
            }
        }
    }
#pragma unroll
    for (int jn = 0; jn < 4; jn++) {
        int n = nb * 64 + (s * 4 + jn) * 8 + cc * 2;
        if (n < NANS) {
            float b0 = bp2[n], b1 = bp2[n + 1];
#pragma unroll
            for (int hh = 0; hh < 2; hh++) {
                int m = mb * 64 + mt * 16 + rr + hh * 8;
                float* o = out + (size_t)m * NANS + n;
                o[0] = acc[jn][hh * 2 + 0] + b0;
                o[1] = acc[jn][hh * 2 + 1] + b1;
            }
        }
    }
}

// ---------------- softmax ------------------------------------------------------
__global__ __launch_bounds__(256) void k_softmax(float* __restrict__ out)
{
    __shared__ float red[256];
    const int tid = threadIdx.x;
    float* p = out + (size_t)blockIdx.x * NANS;
    float v[4];
    float mx = -1e30f;
#pragma unroll
    for (int i = 0; i < 4; i++) {
        int n = tid + i * 256;
        v[i] = (n < NANS) ? p[n] : -1e30f;
        mx = fmaxf(mx, v[i]);
    }
    red[tid] = mx; __syncthreads();
    for (int s = 128; s > 0; s >>= 1) {
        if (tid < s) red[tid] = fmaxf(red[tid], red[tid + s]);
        __syncthreads();
    }
    mx = red[0]; __syncthreads();
    float sum = 0.f;
#pragma unroll
    for (int i = 0; i < 4; i++) {
        int n = tid + i * 256;
        if (n < NANS) { v[i] = expf(v[i] - mx); sum += v[i]; }
    }
    red[tid] = sum; __syncthreads();
    for (int s = 128; s > 0; s >>= 1) {
        if (tid < s) red[tid] += red[tid + s];
        __syncthreads();
    }
    float inv = 1.f / red[0];
#pragma unroll
    for (int i = 0; i < 4; i++) {
        int n = tid + i * 256;
        if (n < NANS) p[n] = v[i] * inv;
    }
}

// ---------------- launch ------------------------------------------------------
extern "C" void kernel_launch(void* const* d_in, const int* in_sizes, int n_in,
                              void* d_out, int out_size)
{
    const float* data1 = (const float*)d_in[0];
    const float* data2 = (const float*)d_in[1];
    const float* W_ih1 = (const float*)d_in[2];
    const float* W_hh1 = (const float*)d_in[3];
    const float* b1    = (const float*)d_in[4];
    const float* W_ih2 = (const float*)d_in[5];
    const float* W_hh2 = (const float*)d_in[6];
    const float* b2    = (const float*)d_in[7];
    const float* Wp1   = (const float*)d_in[8];
    const float* bp1   = (const float*)d_in[9];
    const float* Wp2   = (const float*)d_in[10];
    const float* bp2   = (const float*)d_in[11];
    float* out = (float*)d_out;

    static bool attr_done = false;
    if (!attr_done) {
        cudaFuncSetAttribute(k_xprojb,  cudaFuncAttributeMaxDynamicSharedMemorySize, 196608);
        cudaFuncSetAttribute(k_mlp1b,   cudaFuncAttributeMaxDynamicSharedMemorySize, 65536);
        cudaFuncSetAttribute(k_logitsb, cudaFuncAttributeMaxDynamicSharedMemorySize, 65536);
        cudaFuncSetAttribute(k_recur,   cudaFuncAttributeMaxDynamicSharedMemorySize, 229376);
        attr_done = true;
    }

    k_init_state<<<128, 256>>>();
    k_pack_all<<<dim3(1024, 6), 256>>>(W_hh1, W_ih2, W_hh2, data1, data2,
                                       W_ih1, Wp1, Wp2);
    k_xprojb<<<dim3(16, 64), 256, 196608>>>(b1);
    k_recur<<<128, 256, 229376>>>(b2);
    k_mlp1b<<<dim3(4, 128), 256, 65536>>>(bp1);
    k_logitsb<<<dim3(16, 128), 256, 65536>>>(bp2, out);
    k_softmax<<<BT, 256>>>(out);
}